// round 5
// baseline (speedup 1.0000x reference)
#include <cuda_runtime.h>
#include <cstdint>

// ---------------------------------------------------------------------------
// Problem constants
// ---------------------------------------------------------------------------
#define NN 50000
#define EE 800000
#define IN_CH 128
#define HID 64
#define HEADS 4
#define HC (HEADS * HID)   // 256
#define OUT_CH 64

// ---------------------------------------------------------------------------
// Scratch (device globals; no allocation allowed anywhere)
// g_h is 51 MB -> stays L2-resident between the GEMM that writes it and the
// edge kernels that gather from it (this residency is worth ~600 us).
// ---------------------------------------------------------------------------
__device__ __align__(16) float g_h[(size_t)NN * HC];      // per-relation GEMM output
__device__ __align__(16) float g_out1[(size_t)NN * HC];   // layer1 accumulation
__device__ __align__(16) float g_out2[(size_t)NN * HID];  // layer2 accumulation
__device__ __align__(16) float g_als[(size_t)NN * HEADS];
__device__ __align__(16) float g_ald[(size_t)NN * HEADS];
__device__ __align__(16) float g_denom[(size_t)NN * HEADS];

// ---------------------------------------------------------------------------
// Helpers
// ---------------------------------------------------------------------------
__device__ __forceinline__ float lrelu(float x) { return fmaxf(x, 0.2f * x); }

__device__ __forceinline__ void red_add_v4(float* p, float4 v) {
    asm volatile("red.global.add.v4.f32 [%0], {%1, %2, %3, %4};"
                 :: "l"(p), "f"(v.x), "f"(v.y), "f"(v.z), "f"(v.w) : "memory");
}
__device__ __forceinline__ void red_add_v2(float* p, float2 v) {
    asm volatile("red.global.add.v2.f32 [%0], {%1, %2};"
                 :: "l"(p), "f"(v.x), "f"(v.y) : "memory");
}

// ---------------------------------------------------------------------------
// Register-prefetch pipelined SGEMM: C[M,N] = op(A)[M,K] @ B[K,N] (+ bias).
// ASEL: -1 = A from param, 1 = g_out1, 2 = g_out2. CSEL: -1 = param, 0 = g_h.
// ---------------------------------------------------------------------------
template<int BM, int BN, int BK, int TM, int TN, bool RELU_A, bool BIAS,
         int ASEL, int CSEL>
__global__ void __launch_bounds__((BM / TM) * (BN / TN))
sgemm_kernel(const float* __restrict__ Ap, const float* __restrict__ B,
             float* __restrict__ Cp, const float* __restrict__ bias,
             int M, int N, int K) {
    constexpr int NT = (BM / TM) * (BN / TN);
    constexpr int LA = BM * BK / (4 * NT);
    constexpr int LB = BK * BN / (4 * NT);
    constexpr int BMP = BM + 4;
    __shared__ float As[BK][BMP];
    __shared__ float Bs[BK][BN];

    const float* A = (ASEL == 1) ? (const float*)g_out1
                   : (ASEL == 2) ? (const float*)g_out2 : Ap;
    float* C = (CSEL == 0) ? (float*)g_h : Cp;

    const int tid = threadIdx.x;
    const int block_row = blockIdx.y * BM;
    const int block_col = blockIdx.x * BN;
    const int tcol = tid % (BN / TN);
    const int trow = tid / (BN / TN);

    float4 aR[LA], bR[LB];

    // prologue: load tile 0 into registers
#pragma unroll
    for (int j = 0; j < LA; j++) {
        int i = tid + j * NT;
        int r = i / (BK / 4), c4 = i % (BK / 4);
        int gr = block_row + r;
        float4 v = make_float4(0.f, 0.f, 0.f, 0.f);
        if (gr < M) v = *(const float4*)(A + (size_t)gr * K + c4 * 4);
        if (RELU_A) {
            v.x = fmaxf(v.x, 0.f); v.y = fmaxf(v.y, 0.f);
            v.z = fmaxf(v.z, 0.f); v.w = fmaxf(v.w, 0.f);
        }
        aR[j] = v;
    }
#pragma unroll
    for (int j = 0; j < LB; j++) {
        int i = tid + j * NT;
        int r = i / (BN / 4), c4 = i % (BN / 4);
        bR[j] = *(const float4*)(B + (size_t)r * N + block_col + c4 * 4);
    }

    float acc[TM][TN];
#pragma unroll
    for (int i = 0; i < TM; i++)
#pragma unroll
        for (int j = 0; j < TN; j++) acc[i][j] = 0.f;

    const int nk = K / BK;
    for (int t = 0; t < nk; t++) {
        // commit prefetched registers to shared
#pragma unroll
        for (int j = 0; j < LA; j++) {
            int i = tid + j * NT;
            int r = i / (BK / 4), c4 = i % (BK / 4);
            As[c4 * 4 + 0][r] = aR[j].x; As[c4 * 4 + 1][r] = aR[j].y;
            As[c4 * 4 + 2][r] = aR[j].z; As[c4 * 4 + 3][r] = aR[j].w;
        }
#pragma unroll
        for (int j = 0; j < LB; j++) {
            int i = tid + j * NT;
            int r = i / (BN / 4), c4 = i % (BN / 4);
            *(float4*)&Bs[r][c4 * 4] = bR[j];
        }
        __syncthreads();

        // prefetch next tile (LDGs overlap the FFMA block below)
        if (t + 1 < nk) {
            int k0 = (t + 1) * BK;
#pragma unroll
            for (int j = 0; j < LA; j++) {
                int i = tid + j * NT;
                int r = i / (BK / 4), c4 = i % (BK / 4);
                int gr = block_row + r;
                float4 v = make_float4(0.f, 0.f, 0.f, 0.f);
                if (gr < M) v = *(const float4*)(A + (size_t)gr * K + k0 + c4 * 4);
                if (RELU_A) {
                    v.x = fmaxf(v.x, 0.f); v.y = fmaxf(v.y, 0.f);
                    v.z = fmaxf(v.z, 0.f); v.w = fmaxf(v.w, 0.f);
                }
                aR[j] = v;
            }
#pragma unroll
            for (int j = 0; j < LB; j++) {
                int i = tid + j * NT;
                int r = i / (BN / 4), c4 = i % (BN / 4);
                bR[j] = *(const float4*)(B + (size_t)(k0 + r) * N + block_col + c4 * 4);
            }
        }

#pragma unroll
        for (int kk = 0; kk < BK; kk++) {
            float ar[TM], br[TN];
#pragma unroll
            for (int i = 0; i < TM; i += 4)
                *(float4*)&ar[i] = *(const float4*)&As[kk][trow * TM + i];
#pragma unroll
            for (int j = 0; j < TN; j += 4)
                *(float4*)&br[j] = *(const float4*)&Bs[kk][tcol * TN + j];
#pragma unroll
            for (int i = 0; i < TM; i++)
#pragma unroll
                for (int j = 0; j < TN; j++) acc[i][j] += ar[i] * br[j];
        }
        __syncthreads();
    }

#pragma unroll
    for (int i = 0; i < TM; i++) {
        int gr = block_row + trow * TM + i;
        if (gr >= M) continue;
#pragma unroll
        for (int j = 0; j < TN; j += 4) {
            int gc = block_col + tcol * TN + j;
            float4 v = make_float4(acc[i][j], acc[i][j + 1], acc[i][j + 2], acc[i][j + 3]);
            if (BIAS) {
                v.x += bias[gc]; v.y += bias[gc + 1];
                v.z += bias[gc + 2]; v.w += bias[gc + 3];
            }
            *(float4*)(C + (size_t)gr * N + gc) = v;
        }
    }
}

// ---------------------------------------------------------------------------
// Attention coefficients: als[n,h] = <g_h[n,h,:], a_s[h,:]>, same for ald.
// One warp per node; 8 lanes per head, 8 channels per lane.
// Also zeroes g_denom (replaces a memset node).
// ---------------------------------------------------------------------------
__global__ void attn_coef_kernel(const float* __restrict__ a_s,
                                 const float* __restrict__ a_d,
                                 int N) {
    int warp = (blockIdx.x * blockDim.x + threadIdx.x) >> 5;
    int lane = threadIdx.x & 31;
    if (warp >= N) return;
    int head = lane >> 3;
    int coff = head * HID + (lane & 7) * 8;
    const float4* hp = (const float4*)(g_h + (size_t)warp * HC + coff);
    const float4* sp = (const float4*)(a_s + coff);
    const float4* dp = (const float4*)(a_d + coff);
    float4 h0 = hp[0], h1 = hp[1];
    float4 s0 = sp[0], s1 = sp[1];
    float4 d0 = dp[0], d1 = dp[1];
    float ps = h0.x * s0.x + h0.y * s0.y + h0.z * s0.z + h0.w * s0.w
             + h1.x * s1.x + h1.y * s1.y + h1.z * s1.z + h1.w * s1.w;
    float pd = h0.x * d0.x + h0.y * d0.y + h0.z * d0.z + h0.w * d0.w
             + h1.x * d1.x + h1.y * d1.y + h1.z * d1.z + h1.w * d1.w;
#pragma unroll
    for (int off = 4; off; off >>= 1) {
        ps += __shfl_down_sync(0xffffffffu, ps, off);
        pd += __shfl_down_sync(0xffffffffu, pd, off);
    }
    if ((lane & 7) == 0) {
        g_als[warp * HEADS + head] = ps;
        g_ald[warp * HEADS + head] = pd;
        g_denom[warp * HEADS + head] = 0.f;
    }
}

// ---------------------------------------------------------------------------
// Pass A: softmax denominators. One thread per (virtual) edge.
// Edges e >= E are self-loops (node e - E).
// Shift-free softmax: logits are O(1) here, exp cannot overflow, and
// alpha = exp(l)/sum(exp(l)) is invariant to the max-shift in the reference.
// ---------------------------------------------------------------------------
__global__ void passA_kernel(const int* __restrict__ src, const int* __restrict__ dst,
                             int E, int Etot) {
    int e = blockIdx.x * blockDim.x + threadIdx.x;
    if (e >= Etot) return;
    int s, d;
    if (e < E) { s = src[e]; d = dst[e]; } else { s = d = e - E; }
    float4 as4 = *(const float4*)(g_als + (size_t)s * 4);
    float4 ad4 = *(const float4*)(g_ald + (size_t)d * 4);
    float4 ex;
    ex.x = __expf(lrelu(as4.x + ad4.x));
    ex.y = __expf(lrelu(as4.y + ad4.y));
    ex.z = __expf(lrelu(as4.z + ad4.z));
    ex.w = __expf(lrelu(as4.w + ad4.w));
    red_add_v4(g_denom + (size_t)d * 4, ex);
}

// ---------------------------------------------------------------------------
// Pass B layer1 (concat): one warp per edge; lane covers 8 of 256 channels.
// g_out1[dst, h, c] += alpha[h] * g_h[src, h, c]
// ---------------------------------------------------------------------------
__global__ void passB1_kernel(const int* __restrict__ src, const int* __restrict__ dst,
                              int E, int Etot) {
    int gt = blockIdx.x * blockDim.x + threadIdx.x;
    int e = gt >> 5, lane = gt & 31;
    if (e >= Etot) return;
    int s, d;
    if (e < E) { s = src[e]; d = dst[e]; } else { s = d = e - E; }
    int head = lane >> 3;
    float as_ = g_als[(size_t)s * 4 + head];
    float ad_ = g_ald[(size_t)d * 4 + head];
    float dn  = g_denom[(size_t)d * 4 + head];
    float alpha = __expf(lrelu(as_ + ad_)) / (dn + 1e-16f);
    const float4* hp = (const float4*)(g_h + (size_t)s * HC) + lane * 2;
    float4 v0 = hp[0], v1 = hp[1];
    v0.x *= alpha; v0.y *= alpha; v0.z *= alpha; v0.w *= alpha;
    v1.x *= alpha; v1.y *= alpha; v1.z *= alpha; v1.w *= alpha;
    float* op = g_out1 + (size_t)d * HC + lane * 8;
    red_add_v4(op, v0);
    red_add_v4(op + 4, v1);
}

// ---------------------------------------------------------------------------
// Pass B layer2 (mean over heads): one warp per edge; lane covers 2 of 64 ch.
// g_out2[dst, c] += 0.25 * sum_h alpha[h] * g_h[src, h, c]
// ---------------------------------------------------------------------------
__global__ void passB2_kernel(const int* __restrict__ src, const int* __restrict__ dst,
                              int E, int Etot) {
    int gt = blockIdx.x * blockDim.x + threadIdx.x;
    int e = gt >> 5, lane = gt & 31;
    if (e >= Etot) return;
    int s, d;
    if (e < E) { s = src[e]; d = dst[e]; } else { s = d = e - E; }
    float4 as4 = *(const float4*)(g_als + (size_t)s * 4);
    float4 ad4 = *(const float4*)(g_ald + (size_t)d * 4);
    float4 dn4 = *(const float4*)(g_denom + (size_t)d * 4);
    float al[4];
    al[0] = 0.25f * __expf(lrelu(as4.x + ad4.x)) / (dn4.x + 1e-16f);
    al[1] = 0.25f * __expf(lrelu(as4.y + ad4.y)) / (dn4.y + 1e-16f);
    al[2] = 0.25f * __expf(lrelu(as4.z + ad4.z)) / (dn4.z + 1e-16f);
    al[3] = 0.25f * __expf(lrelu(as4.w + ad4.w)) / (dn4.w + 1e-16f);
    const float* hrow = g_h + (size_t)s * HC;
    float2 acc = make_float2(0.f, 0.f);
#pragma unroll
    for (int hd = 0; hd < 4; hd++) {
        float2 v = *(const float2*)(hrow + hd * HID + lane * 2);
        acc.x += al[hd] * v.x;
        acc.y += al[hd] * v.y;
    }
    red_add_v2(g_out2 + (size_t)d * HID + lane * 2, acc);
}

// ---------------------------------------------------------------------------
// Init accumulation buffers with summed biases (3 relations contribute b each).
// SEL: 1 = g_out1 (C=HC), 2 = g_out2 (C=HID)
// ---------------------------------------------------------------------------
template<int SEL, int C>
__global__ void init_out_kernel(const float* __restrict__ b, int total) {
    int i = blockIdx.x * blockDim.x + threadIdx.x;
    if (i >= total) return;
    int c = i % C;
    float v = b[c] + b[C + c] + b[2 * C + c];
    if (SEL == 1) g_out1[i] = v; else g_out2[i] = v;
}

// ---------------------------------------------------------------------------
// Launcher: kernel launches ONLY (graph-capture safe)
// ---------------------------------------------------------------------------
extern "C" void kernel_launch(void* const* d_in, const int* in_sizes, int n_in,
                              void* d_out, int out_size) {
    const float* x   = (const float*)d_in[0];
    const int*   e0  = (const int*)d_in[1];
    const int*   e1  = (const int*)d_in[2];
    const int*   e2  = (const int*)d_in[3];
    const float* W1  = (const float*)d_in[4];
    const float* a1s = (const float*)d_in[5];
    const float* a1d = (const float*)d_in[6];
    const float* b1  = (const float*)d_in[7];
    const float* W2  = (const float*)d_in[8];
    const float* a2s = (const float*)d_in[9];
    const float* a2d = (const float*)d_in[10];
    const float* b2  = (const float*)d_in[11];
    const float* Wl  = (const float*)d_in[12];
    const float* bl  = (const float*)d_in[13];
    float* out = (float*)d_out;

    const int N = in_sizes[0] / IN_CH;
    const int E = in_sizes[1] / 2;

    const int* srcs[3] = {e0, e1, e2};
    const int  selfl[3] = {0, 1, 1};

    // ---------------- Layer 1 (concat) ----------------
    init_out_kernel<1, HC><<<(N * HC + 255) / 256, 256>>>(b1, N * HC);
    for (int r = 0; r < 3; r++) {
        const int* src = srcs[r];
        const int* dst = srcs[r] + E;
        {   // g_h = x @ W1[r]
            dim3 grid(HC / 128, (N + 127) / 128);
            sgemm_kernel<128, 128, 16, 8, 8, false, false, -1, 0><<<grid, 256>>>(
                x, W1 + (size_t)r * IN_CH * HC, nullptr, nullptr, N, HC, IN_CH);
        }
        attn_coef_kernel<<<(N + 7) / 8, 256>>>(a1s + r * HC, a1d + r * HC, N);
        int Etot = E + (selfl[r] ? N : 0);
        passA_kernel<<<(Etot + 255) / 256, 256>>>(src, dst, E, Etot);
        {
            long long th = (long long)Etot * 32;
            passB1_kernel<<<(unsigned)((th + 255) / 256), 256>>>(src, dst, E, Etot);
        }
    }

    // ---------------- Layer 2 (mean over heads) ----------------
    init_out_kernel<2, HID><<<(N * HID + 255) / 256, 256>>>(b2, N * HID);
    for (int r = 0; r < 3; r++) {
        const int* src = srcs[r];
        const int* dst = srcs[r] + E;
        {   // g_h = relu(g_out1) @ W2[r]
            dim3 grid(HC / 128, (N + 127) / 128);
            sgemm_kernel<128, 128, 16, 8, 8, true, false, 1, 0><<<grid, 256>>>(
                nullptr, W2 + (size_t)r * HC * HC, nullptr, nullptr, N, HC, HC);
        }
        attn_coef_kernel<<<(N + 7) / 8, 256>>>(a2s + r * HC, a2d + r * HC, N);
        int Etot = E + (selfl[r] ? N : 0);
        passA_kernel<<<(Etot + 255) / 256, 256>>>(src, dst, E, Etot);
        {
            long long th = (long long)Etot * 32;
            passB2_kernel<<<(unsigned)((th + 255) / 256), 256>>>(src, dst, E, Etot);
        }
    }

    // ---------------- Final linear: out = relu(g_out2) @ Wl + bl ----------------
    {
        dim3 grid(1, (N + 127) / 128);
        sgemm_kernel<128, 64, 16, 4, 8, true, true, 2, -1><<<grid, 256>>>(
            nullptr, Wl, out, bl, N, OUT_CH, OUT_CH);
    }
}

// round 6
// speedup vs baseline: 1.3327x; 1.3327x over previous
#include <cuda_runtime.h>
#include <cuda_bf16.h>
#include <cstdint>

// ---------------------------------------------------------------------------
// Problem constants
// ---------------------------------------------------------------------------
#define NN 50000
#define EE 800000
#define IN_CH 128
#define HID 64
#define HEADS 4
#define HC (HEADS * HID)   // 256
#define OUT_CH 64

// ---------------------------------------------------------------------------
// Scratch (device globals; no allocation allowed anywhere)
// ---------------------------------------------------------------------------
__device__ __align__(16) float g_h[(size_t)NN * HC];      // per-relation GEMM output
__device__ __align__(16) float g_out1[(size_t)NN * HC];   // layer1 accumulation
__device__ __align__(16) float g_out2[(size_t)NN * HID];  // layer2 accumulation
__device__ __align__(16) float g_als[(size_t)NN * HEADS];
__device__ __align__(16) float g_ald[(size_t)NN * HEADS];
__device__ __align__(16) float g_denom[(size_t)NN * HEADS];

// ---------------------------------------------------------------------------
// Helpers
// ---------------------------------------------------------------------------
__device__ __forceinline__ float lrelu(float x) { return fmaxf(x, 0.2f * x); }

__device__ __forceinline__ void red_add_v4(float* p, float4 v) {
    asm volatile("red.global.add.v4.f32 [%0], {%1, %2, %3, %4};"
                 :: "l"(p), "f"(v.x), "f"(v.y), "f"(v.z), "f"(v.w) : "memory");
}
__device__ __forceinline__ void red_add_v2(float* p, float2 v) {
    asm volatile("red.global.add.v2.f32 [%0], {%1, %2};"
                 :: "l"(p), "f"(v.x), "f"(v.y) : "memory");
}

// Split f32 into bf16 hi + lo (bits, for packing)
__device__ __forceinline__ void bf16_split(float v, unsigned short& h, unsigned short& l) {
    __nv_bfloat16 hb = __float2bfloat16_rn(v);
    float r = v - __bfloat162float(hb);
    __nv_bfloat16 lb = __float2bfloat16_rn(r);
    h = __bfloat16_as_ushort(hb);
    l = __bfloat16_as_ushort(lb);
}
__device__ __forceinline__ unsigned pk2(unsigned short a, unsigned short b) {
    return (unsigned)a | ((unsigned)b << 16);
}

#define MMA_BF16(d, a0, a1, a2, a3, b0, b1)                                    \
    asm volatile(                                                              \
        "mma.sync.aligned.m16n8k16.row.col.f32.bf16.bf16.f32 "                 \
        "{%0,%1,%2,%3}, {%4,%5,%6,%7}, {%8,%9}, {%0,%1,%2,%3};"                \
        : "+f"(d[0]), "+f"(d[1]), "+f"(d[2]), "+f"(d[3])                       \
        : "r"(a0), "r"(a1), "r"(a2), "r"(a3), "r"(b0), "r"(b1))

// ---------------------------------------------------------------------------
// bf16x3 split-precision tensor-core GEMM:
//   g_h[M, 256] = op(A)[M, K] @ B[K, 256]
// CTA tile 128x128, BK=32, 8 warps of 64x32. Fragments via plain LDS.32 from
// padded (BKP=40 -> conflict-free) k-contiguous smem planes.
// Error: drops lo*lo only -> ~1e-5 relative, far under the 1e-3 gate.
// ---------------------------------------------------------------------------
template<bool RELU_A, bool A_FROM_PARAM, int K>
__global__ void __launch_bounds__(256, 2)
mma_gemm_kernel(const float* __restrict__ Ap, const float* __restrict__ B, int M) {
    constexpr int BKP = 40;
    __shared__ unsigned short sAhi[128][BKP], sAlo[128][BKP];
    __shared__ unsigned short sBhi[128][BKP], sBlo[128][BKP];

    const float* A = A_FROM_PARAM ? Ap : (const float*)g_out1;
    float* C = g_h;

    const int tid = threadIdx.x;
    const int br = blockIdx.y * 128;
    const int bc = blockIdx.x * 128;
    const int lane = tid & 31, wid = tid >> 5;
    const int g = lane >> 2, tig = lane & 3;
    const int wm = (wid >> 2) * 64;   // warp row offset (0 or 64)
    const int wn = (wid & 3) * 32;    // warp col offset (0,32,64,96)

    float acc[4][4][4];
#pragma unroll
    for (int i = 0; i < 4; i++)
#pragma unroll
        for (int j = 0; j < 4; j++)
#pragma unroll
            for (int q = 0; q < 4; q++) acc[i][j][q] = 0.f;

    const int nB = tid & 127;          // B fill: this thread's n within tile
    const int kbB = (tid >> 7) * 4;    // and k base (0 or 4)

    for (int kt = 0; kt < K / 32; kt++) {
        const int k0 = kt * 32;
        if (kt) __syncthreads();

        // ---- fill A tile: 128x32 f32 -> hi/lo bf16 planes ----
#pragma unroll
        for (int it = 0; it < 4; it++) {
            int idx = tid + it * 256;          // 0..1023 float4 slots
            int r = idx >> 3;
            int c4 = (idx & 7) * 4;
            float4 v = make_float4(0.f, 0.f, 0.f, 0.f);
            if (br + r < M) v = *(const float4*)(A + (size_t)(br + r) * K + k0 + c4);
            if (RELU_A) {
                v.x = fmaxf(v.x, 0.f); v.y = fmaxf(v.y, 0.f);
                v.z = fmaxf(v.z, 0.f); v.w = fmaxf(v.w, 0.f);
            }
            unsigned short h0, h1, h2, h3, l0, l1, l2, l3;
            bf16_split(v.x, h0, l0); bf16_split(v.y, h1, l1);
            bf16_split(v.z, h2, l2); bf16_split(v.w, h3, l3);
            *(uint2*)&sAhi[r][c4] = make_uint2(pk2(h0, h1), pk2(h2, h3));
            *(uint2*)&sAlo[r][c4] = make_uint2(pk2(l0, l1), pk2(l2, l3));
        }
        // ---- fill B tile transposed: gmem [K,256] -> smem [n][k] hi/lo ----
#pragma unroll
        for (int it = 0; it < 4; it++) {
            int ks = kbB + it * 8;             // 4 consecutive k for this n
            float v0 = B[(size_t)(k0 + ks + 0) * HC + bc + nB];
            float v1 = B[(size_t)(k0 + ks + 1) * HC + bc + nB];
            float v2 = B[(size_t)(k0 + ks + 2) * HC + bc + nB];
            float v3 = B[(size_t)(k0 + ks + 3) * HC + bc + nB];
            unsigned short h0, h1, h2, h3, l0, l1, l2, l3;
            bf16_split(v0, h0, l0); bf16_split(v1, h1, l1);
            bf16_split(v2, h2, l2); bf16_split(v3, h3, l3);
            *(uint2*)&sBhi[nB][ks] = make_uint2(pk2(h0, h1), pk2(h2, h3));
            *(uint2*)&sBlo[nB][ks] = make_uint2(pk2(l0, l1), pk2(l2, l3));
        }
        __syncthreads();

        // ---- two k16 steps of mma ----
#pragma unroll
        for (int ks = 0; ks < 2; ks++) {
            const int ko = ks * 16;
            unsigned a[4][4], bh[4][2], bx[4][2];
            // A-hi fragments (4 m-tiles)
#pragma unroll
            for (int mt = 0; mt < 4; mt++) {
                int row = wm + mt * 16 + g;
                a[mt][0] = *(const unsigned*)&sAhi[row][ko + 2 * tig];
                a[mt][1] = *(const unsigned*)&sAhi[row + 8][ko + 2 * tig];
                a[mt][2] = *(const unsigned*)&sAhi[row][ko + 2 * tig + 8];
                a[mt][3] = *(const unsigned*)&sAhi[row + 8][ko + 2 * tig + 8];
            }
            // B-hi fragments (4 n-tiles)
#pragma unroll
            for (int nt = 0; nt < 4; nt++) {
                int col = wn + nt * 8 + g;
                bh[nt][0] = *(const unsigned*)&sBhi[col][ko + 2 * tig];
                bh[nt][1] = *(const unsigned*)&sBhi[col][ko + 2 * tig + 8];
            }
            // hi * hi
#pragma unroll
            for (int mt = 0; mt < 4; mt++)
#pragma unroll
                for (int nt = 0; nt < 4; nt++)
                    MMA_BF16(acc[mt][nt], a[mt][0], a[mt][1], a[mt][2], a[mt][3],
                             bh[nt][0], bh[nt][1]);
            // B-lo fragments, hi * lo
#pragma unroll
            for (int nt = 0; nt < 4; nt++) {
                int col = wn + nt * 8 + g;
                bx[nt][0] = *(const unsigned*)&sBlo[col][ko + 2 * tig];
                bx[nt][1] = *(const unsigned*)&sBlo[col][ko + 2 * tig + 8];
            }
#pragma unroll
            for (int mt = 0; mt < 4; mt++)
#pragma unroll
                for (int nt = 0; nt < 4; nt++)
                    MMA_BF16(acc[mt][nt], a[mt][0], a[mt][1], a[mt][2], a[mt][3],
                             bx[nt][0], bx[nt][1]);
            // A-lo fragments (reuse a regs), lo * hi
#pragma unroll
            for (int mt = 0; mt < 4; mt++) {
                int row = wm + mt * 16 + g;
                a[mt][0] = *(const unsigned*)&sAlo[row][ko + 2 * tig];
                a[mt][1] = *(const unsigned*)&sAlo[row + 8][ko + 2 * tig];
                a[mt][2] = *(const unsigned*)&sAlo[row][ko + 2 * tig + 8];
                a[mt][3] = *(const unsigned*)&sAlo[row + 8][ko + 2 * tig + 8];
            }
#pragma unroll
            for (int mt = 0; mt < 4; mt++)
#pragma unroll
                for (int nt = 0; nt < 4; nt++)
                    MMA_BF16(acc[mt][nt], a[mt][0], a[mt][1], a[mt][2], a[mt][3],
                             bh[nt][0], bh[nt][1]);
        }
    }

    // ---- epilogue: fp32 stores ----
#pragma unroll
    for (int mt = 0; mt < 4; mt++) {
#pragma unroll
        for (int nt = 0; nt < 4; nt++) {
            int row = br + wm + mt * 16 + g;
            int col = bc + wn + nt * 8 + 2 * tig;
            if (row < M)
                *(float2*)(C + (size_t)row * HC + col) =
                    make_float2(acc[mt][nt][0], acc[mt][nt][1]);
            if (row + 8 < M)
                *(float2*)(C + (size_t)(row + 8) * HC + col) =
                    make_float2(acc[mt][nt][2], acc[mt][nt][3]);
        }
    }
}

// ---------------------------------------------------------------------------
// SIMT SGEMM (final linear layer only): C[M,N] = relu(g_out2) @ B + bias
// ---------------------------------------------------------------------------
template<int BM, int BN, int BK, int TM, int TN>
__global__ void __launch_bounds__((BM / TM) * (BN / TN))
final_gemm_kernel(const float* __restrict__ B, float* __restrict__ C,
                  const float* __restrict__ bias, int M, int N, int K) {
    constexpr int NT = (BM / TM) * (BN / TN);
    __shared__ float As[BK][BM + 4];
    __shared__ float Bs[BK][BN];
    const float* A = (const float*)g_out2;
    const int tid = threadIdx.x;
    const int block_row = blockIdx.y * BM;
    const int block_col = blockIdx.x * BN;
    const int tcol = tid % (BN / TN);
    const int trow = tid / (BN / TN);

    float acc[TM][TN];
#pragma unroll
    for (int i = 0; i < TM; i++)
#pragma unroll
        for (int j = 0; j < TN; j++) acc[i][j] = 0.f;

    for (int k0 = 0; k0 < K; k0 += BK) {
#pragma unroll
        for (int i = tid; i < BM * BK / 4; i += NT) {
            int r = i / (BK / 4), c4 = i % (BK / 4);
            int gr = block_row + r;
            float4 v = make_float4(0.f, 0.f, 0.f, 0.f);
            if (gr < M) v = *(const float4*)(A + (size_t)gr * K + k0 + c4 * 4);
            v.x = fmaxf(v.x, 0.f); v.y = fmaxf(v.y, 0.f);
            v.z = fmaxf(v.z, 0.f); v.w = fmaxf(v.w, 0.f);
            As[c4 * 4 + 0][r] = v.x; As[c4 * 4 + 1][r] = v.y;
            As[c4 * 4 + 2][r] = v.z; As[c4 * 4 + 3][r] = v.w;
        }
#pragma unroll
        for (int i = tid; i < BK * BN / 4; i += NT) {
            int r = i / (BN / 4), c4 = i % (BN / 4);
            *(float4*)&Bs[r][c4 * 4] =
                *(const float4*)(B + (size_t)(k0 + r) * N + block_col + c4 * 4);
        }
        __syncthreads();
#pragma unroll
        for (int kk = 0; kk < BK; kk++) {
            float ar[TM], br[TN];
#pragma unroll
            for (int i = 0; i < TM; i++) ar[i] = As[kk][trow * TM + i];
#pragma unroll
            for (int j = 0; j < TN; j++) br[j] = Bs[kk][tcol * TN + j];
#pragma unroll
            for (int i = 0; i < TM; i++)
#pragma unroll
                for (int j = 0; j < TN; j++) acc[i][j] += ar[i] * br[j];
        }
        __syncthreads();
    }
#pragma unroll
    for (int i = 0; i < TM; i++) {
        int gr = block_row + trow * TM + i;
        if (gr >= M) continue;
#pragma unroll
        for (int j = 0; j < TN; j += 4) {
            int gc = block_col + tcol * TN + j;
            float4 v = make_float4(acc[i][j] + bias[gc], acc[i][j + 1] + bias[gc + 1],
                                   acc[i][j + 2] + bias[gc + 2], acc[i][j + 3] + bias[gc + 3]);
            *(float4*)(C + (size_t)gr * N + gc) = v;
        }
    }
}

// ---------------------------------------------------------------------------
// Attention coefficients (one warp per node), also zeroes g_denom.
// ---------------------------------------------------------------------------
__global__ void attn_coef_kernel(const float* __restrict__ a_s,
                                 const float* __restrict__ a_d, int N) {
    int warp = (blockIdx.x * blockDim.x + threadIdx.x) >> 5;
    int lane = threadIdx.x & 31;
    if (warp >= N) return;
    int head = lane >> 3;
    int coff = head * HID + (lane & 7) * 8;
    const float4* hp = (const float4*)(g_h + (size_t)warp * HC + coff);
    const float4* sp = (const float4*)(a_s + coff);
    const float4* dp = (const float4*)(a_d + coff);
    float4 h0 = hp[0], h1 = hp[1];
    float4 s0 = sp[0], s1 = sp[1];
    float4 d0 = dp[0], d1 = dp[1];
    float ps = h0.x * s0.x + h0.y * s0.y + h0.z * s0.z + h0.w * s0.w
             + h1.x * s1.x + h1.y * s1.y + h1.z * s1.z + h1.w * s1.w;
    float pd = h0.x * d0.x + h0.y * d0.y + h0.z * d0.z + h0.w * d0.w
             + h1.x * d1.x + h1.y * d1.y + h1.z * d1.z + h1.w * d1.w;
#pragma unroll
    for (int off = 4; off; off >>= 1) {
        ps += __shfl_down_sync(0xffffffffu, ps, off);
        pd += __shfl_down_sync(0xffffffffu, pd, off);
    }
    if ((lane & 7) == 0) {
        g_als[warp * HEADS + head] = ps;
        g_ald[warp * HEADS + head] = pd;
        g_denom[warp * HEADS + head] = 0.f;
    }
}

// ---------------------------------------------------------------------------
// Pass A: softmax denominators (shift-free; logits are O(1) so exp is safe and
// alpha is invariant to the reference's max-shift).
// ---------------------------------------------------------------------------
__global__ void passA_kernel(const int* __restrict__ src, const int* __restrict__ dst,
                             int E, int Etot) {
    int e = blockIdx.x * blockDim.x + threadIdx.x;
    if (e >= Etot) return;
    int s, d;
    if (e < E) { s = src[e]; d = dst[e]; } else { s = d = e - E; }
    float4 as4 = *(const float4*)(g_als + (size_t)s * 4);
    float4 ad4 = *(const float4*)(g_ald + (size_t)d * 4);
    float4 ex;
    ex.x = __expf(lrelu(as4.x + ad4.x));
    ex.y = __expf(lrelu(as4.y + ad4.y));
    ex.z = __expf(lrelu(as4.z + ad4.z));
    ex.w = __expf(lrelu(as4.w + ad4.w));
    red_add_v4(g_denom + (size_t)d * 4, ex);
}

// ---------------------------------------------------------------------------
// Pass B layer1 (concat): one warp per edge; lane covers 8 of 256 channels.
// ---------------------------------------------------------------------------
__global__ void passB1_kernel(const int* __restrict__ src, const int* __restrict__ dst,
                              int E, int Etot) {
    int gt = blockIdx.x * blockDim.x + threadIdx.x;
    int e = gt >> 5, lane = gt & 31;
    if (e >= Etot) return;
    int s, d;
    if (e < E) { s = src[e]; d = dst[e]; } else { s = d = e - E; }
    int head = lane >> 3;
    float as_ = g_als[(size_t)s * 4 + head];
    float ad_ = g_ald[(size_t)d * 4 + head];
    float dn  = g_denom[(size_t)d * 4 + head];
    float alpha = __expf(lrelu(as_ + ad_)) / (dn + 1e-16f);
    const float4* hp = (const float4*)(g_h + (size_t)s * HC) + lane * 2;
    float4 v0 = hp[0], v1 = hp[1];
    v0.x *= alpha; v0.y *= alpha; v0.z *= alpha; v0.w *= alpha;
    v1.x *= alpha; v1.y *= alpha; v1.z *= alpha; v1.w *= alpha;
    float* op = g_out1 + (size_t)d * HC + lane * 8;
    red_add_v4(op, v0);
    red_add_v4(op + 4, v1);
}

// ---------------------------------------------------------------------------
// Pass B layer2 (mean over heads): one warp per edge; lane covers 2 of 64 ch.
// ---------------------------------------------------------------------------
__global__ void passB2_kernel(const int* __restrict__ src, const int* __restrict__ dst,
                              int E, int Etot) {
    int gt = blockIdx.x * blockDim.x + threadIdx.x;
    int e = gt >> 5, lane = gt & 31;
    if (e >= Etot) return;
    int s, d;
    if (e < E) { s = src[e]; d = dst[e]; } else { s = d = e - E; }
    float4 as4 = *(const float4*)(g_als + (size_t)s * 4);
    float4 ad4 = *(const float4*)(g_ald + (size_t)d * 4);
    float4 dn4 = *(const float4*)(g_denom + (size_t)d * 4);
    float al[4];
    al[0] = 0.25f * __expf(lrelu(as4.x + ad4.x)) / (dn4.x + 1e-16f);
    al[1] = 0.25f * __expf(lrelu(as4.y + ad4.y)) / (dn4.y + 1e-16f);
    al[2] = 0.25f * __expf(lrelu(as4.z + ad4.z)) / (dn4.z + 1e-16f);
    al[3] = 0.25f * __expf(lrelu(as4.w + ad4.w)) / (dn4.w + 1e-16f);
    const float* hrow = g_h + (size_t)s * HC;
    float2 acc = make_float2(0.f, 0.f);
#pragma unroll
    for (int hd = 0; hd < 4; hd++) {
        float2 v = *(const float2*)(hrow + hd * HID + lane * 2);
        acc.x += al[hd] * v.x;
        acc.y += al[hd] * v.y;
    }
    red_add_v2(g_out2 + (size_t)d * HID + lane * 2, acc);
}

// ---------------------------------------------------------------------------
// Init accumulation buffers with summed biases.
// ---------------------------------------------------------------------------
template<int SEL, int C>
__global__ void init_out_kernel(const float* __restrict__ b, int total) {
    int i = blockIdx.x * blockDim.x + threadIdx.x;
    if (i >= total) return;
    int c = i % C;
    float v = b[c] + b[C + c] + b[2 * C + c];
    if (SEL == 1) g_out1[i] = v; else g_out2[i] = v;
}

// ---------------------------------------------------------------------------
// Launcher: kernel launches ONLY (graph-capture safe)
// ---------------------------------------------------------------------------
extern "C" void kernel_launch(void* const* d_in, const int* in_sizes, int n_in,
                              void* d_out, int out_size) {
    const float* x   = (const float*)d_in[0];
    const int*   e0  = (const int*)d_in[1];
    const int*   e1  = (const int*)d_in[2];
    const int*   e2  = (const int*)d_in[3];
    const float* W1  = (const float*)d_in[4];
    const float* a1s = (const float*)d_in[5];
    const float* a1d = (const float*)d_in[6];
    const float* b1  = (const float*)d_in[7];
    const float* W2  = (const float*)d_in[8];
    const float* a2s = (const float*)d_in[9];
    const float* a2d = (const float*)d_in[10];
    const float* b2  = (const float*)d_in[11];
    const float* Wl  = (const float*)d_in[12];
    const float* bl  = (const float*)d_in[13];
    float* out = (float*)d_out;

    const int N = in_sizes[0] / IN_CH;
    const int E = in_sizes[1] / 2;

    const int* srcs[3] = {e0, e1, e2};
    const int  selfl[3] = {0, 1, 1};
    const dim3 ggrid(2, (N + 127) / 128);

    // ---------------- Layer 1 (concat) ----------------
    init_out_kernel<1, HC><<<(N * HC + 255) / 256, 256>>>(b1, N * HC);
    for (int r = 0; r < 3; r++) {
        const int* src = srcs[r];
        const int* dst = srcs[r] + E;
        // g_h = x @ W1[r]  (tensor cores, bf16x3)
        mma_gemm_kernel<false, true, IN_CH><<<ggrid, 256>>>(
            x, W1 + (size_t)r * IN_CH * HC, N);
        attn_coef_kernel<<<(N + 7) / 8, 256>>>(a1s + r * HC, a1d + r * HC, N);
        int Etot = E + (selfl[r] ? N : 0);
        passA_kernel<<<(Etot + 255) / 256, 256>>>(src, dst, E, Etot);
        long long th = (long long)Etot * 32;
        passB1_kernel<<<(unsigned)((th + 255) / 256), 256>>>(src, dst, E, Etot);
    }

    // ---------------- Layer 2 (mean over heads) ----------------
    init_out_kernel<2, HID><<<(N * HID + 255) / 256, 256>>>(b2, N * HID);
    for (int r = 0; r < 3; r++) {
        const int* src = srcs[r];
        const int* dst = srcs[r] + E;
        // g_h = relu(g_out1) @ W2[r]  (tensor cores, bf16x3)
        mma_gemm_kernel<true, false, HC><<<ggrid, 256>>>(
            nullptr, W2 + (size_t)r * HC * HC, N);
        attn_coef_kernel<<<(N + 7) / 8, 256>>>(a2s + r * HC, a2d + r * HC, N);
        int Etot = E + (selfl[r] ? N : 0);
        passA_kernel<<<(Etot + 255) / 256, 256>>>(src, dst, E, Etot);
        long long th = (long long)Etot * 32;
        passB2_kernel<<<(unsigned)((th + 255) / 256), 256>>>(src, dst, E, Etot);
    }

    // ---------------- Final linear: out = relu(g_out2) @ Wl + bl ----------------
    {
        dim3 grid(1, (N + 127) / 128);
        final_gemm_kernel<128, 64, 16, 4, 8><<<grid, 256>>>(
            Wl, out, bl, N, OUT_CH, OUT_CH);
    }
}

// round 7
// speedup vs baseline: 2.1608x; 1.6214x over previous
#include <cuda_runtime.h>
#include <cuda_bf16.h>
#include <cstdint>

#define NN 50000
#define EE 800000
#define IN_CH 128
#define HID 64
#define HEADS 4
#define HC (HEADS * HID)   // 256
#define OUT_CH 64
#define NREL 3

// ---------------------------------------------------------------------------
// Scratch (device globals; no allocation allowed anywhere)
// ---------------------------------------------------------------------------
__device__ __align__(16) float g_h[(size_t)NN * HC];
__device__ __align__(16) float g_out1[(size_t)NN * HC];
__device__ __align__(16) float g_out2[(size_t)NN * HID];
__device__ __align__(16) float g_als[(size_t)NN * HEADS];
__device__ __align__(16) float g_ald[(size_t)NN * HEADS];
__device__ int g_cnt[NREL * NN];
__device__ int g_cnt2[NREL * NN];
__device__ int g_off[NREL * (NN + 1)];
__device__ int g_csr[(size_t)NREL * EE];

__device__ __forceinline__ float lrelu(float x) { return fmaxf(x, 0.2f * x); }

__device__ __forceinline__ void bf16_split(float v, unsigned short& h, unsigned short& l) {
    __nv_bfloat16 hb = __float2bfloat16_rn(v);
    float r = v - __bfloat162float(hb);
    __nv_bfloat16 lb = __float2bfloat16_rn(r);
    h = __bfloat16_as_ushort(hb);
    l = __bfloat16_as_ushort(lb);
}
__device__ __forceinline__ unsigned pk2(unsigned short a, unsigned short b) {
    return (unsigned)a | ((unsigned)b << 16);
}

#define MMA_BF16(d, a0, a1, a2, a3, b0, b1)                                    \
    asm volatile(                                                              \
        "mma.sync.aligned.m16n8k16.row.col.f32.bf16.bf16.f32 "                 \
        "{%0,%1,%2,%3}, {%4,%5,%6,%7}, {%8,%9}, {%0,%1,%2,%3};"                \
        : "+f"(d[0]), "+f"(d[1]), "+f"(d[2]), "+f"(d[3])                       \
        : "r"(a0), "r"(a1), "r"(a2), "r"(a3), "r"(b0), "r"(b1))

// ---------------------------------------------------------------------------
// bf16x3 split-precision tensor-core GEMM (validated in round 6):
//   g_h[M, 256] = op(A)[M, K] @ B[K, 256]
// ---------------------------------------------------------------------------
template<bool RELU_A, bool A_FROM_PARAM, int K>
__global__ void __launch_bounds__(256, 2)
mma_gemm_kernel(const float* __restrict__ Ap, const float* __restrict__ B, int M) {
    constexpr int BKP = 40;
    __shared__ unsigned short sAhi[128][BKP], sAlo[128][BKP];
    __shared__ unsigned short sBhi[128][BKP], sBlo[128][BKP];

    const float* A = A_FROM_PARAM ? Ap : (const float*)g_out1;
    float* C = g_h;

    const int tid = threadIdx.x;
    const int br = blockIdx.y * 128;
    const int bc = blockIdx.x * 128;
    const int lane = tid & 31, wid = tid >> 5;
    const int g = lane >> 2, tig = lane & 3;
    const int wm = (wid >> 2) * 64;
    const int wn = (wid & 3) * 32;

    float acc[4][4][4];
#pragma unroll
    for (int i = 0; i < 4; i++)
#pragma unroll
        for (int j = 0; j < 4; j++)
#pragma unroll
            for (int q = 0; q < 4; q++) acc[i][j][q] = 0.f;

    const int nB = tid & 127;
    const int kbB = (tid >> 7) * 4;

    for (int kt = 0; kt < K / 32; kt++) {
        const int k0 = kt * 32;
        if (kt) __syncthreads();

#pragma unroll
        for (int it = 0; it < 4; it++) {
            int idx = tid + it * 256;
            int r = idx >> 3;
            int c4 = (idx & 7) * 4;
            float4 v = make_float4(0.f, 0.f, 0.f, 0.f);
            if (br + r < M) v = *(const float4*)(A + (size_t)(br + r) * K + k0 + c4);
            if (RELU_A) {
                v.x = fmaxf(v.x, 0.f); v.y = fmaxf(v.y, 0.f);
                v.z = fmaxf(v.z, 0.f); v.w = fmaxf(v.w, 0.f);
            }
            unsigned short h0, h1, h2, h3, l0, l1, l2, l3;
            bf16_split(v.x, h0, l0); bf16_split(v.y, h1, l1);
            bf16_split(v.z, h2, l2); bf16_split(v.w, h3, l3);
            *(uint2*)&sAhi[r][c4] = make_uint2(pk2(h0, h1), pk2(h2, h3));
            *(uint2*)&sAlo[r][c4] = make_uint2(pk2(l0, l1), pk2(l2, l3));
        }
#pragma unroll
        for (int it = 0; it < 4; it++) {
            int ks = kbB + it * 8;
            float v0 = B[(size_t)(k0 + ks + 0) * HC + bc + nB];
            float v1 = B[(size_t)(k0 + ks + 1) * HC + bc + nB];
            float v2 = B[(size_t)(k0 + ks + 2) * HC + bc + nB];
            float v3 = B[(size_t)(k0 + ks + 3) * HC + bc + nB];
            unsigned short h0, h1, h2, h3, l0, l1, l2, l3;
            bf16_split(v0, h0, l0); bf16_split(v1, h1, l1);
            bf16_split(v2, h2, l2); bf16_split(v3, h3, l3);
            *(uint2*)&sBhi[nB][ks] = make_uint2(pk2(h0, h1), pk2(h2, h3));
            *(uint2*)&sBlo[nB][ks] = make_uint2(pk2(l0, l1), pk2(l2, l3));
        }
        __syncthreads();

#pragma unroll
        for (int ks = 0; ks < 2; ks++) {
            const int ko = ks * 16;
            unsigned a[4][4], bh[4][2], bx[4][2];
#pragma unroll
            for (int mt = 0; mt < 4; mt++) {
                int row = wm + mt * 16 + g;
                a[mt][0] = *(const unsigned*)&sAhi[row][ko + 2 * tig];
                a[mt][1] = *(const unsigned*)&sAhi[row + 8][ko + 2 * tig];
                a[mt][2] = *(const unsigned*)&sAhi[row][ko + 2 * tig + 8];
                a[mt][3] = *(const unsigned*)&sAhi[row + 8][ko + 2 * tig + 8];
            }
#pragma unroll
            for (int nt = 0; nt < 4; nt++) {
                int col = wn + nt * 8 + g;
                bh[nt][0] = *(const unsigned*)&sBhi[col][ko + 2 * tig];
                bh[nt][1] = *(const unsigned*)&sBhi[col][ko + 2 * tig + 8];
            }
#pragma unroll
            for (int mt = 0; mt < 4; mt++)
#pragma unroll
                for (int nt = 0; nt < 4; nt++)
                    MMA_BF16(acc[mt][nt], a[mt][0], a[mt][1], a[mt][2], a[mt][3],
                             bh[nt][0], bh[nt][1]);
#pragma unroll
            for (int nt = 0; nt < 4; nt++) {
                int col = wn + nt * 8 + g;
                bx[nt][0] = *(const unsigned*)&sBlo[col][ko + 2 * tig];
                bx[nt][1] = *(const unsigned*)&sBlo[col][ko + 2 * tig + 8];
            }
#pragma unroll
            for (int mt = 0; mt < 4; mt++)
#pragma unroll
                for (int nt = 0; nt < 4; nt++)
                    MMA_BF16(acc[mt][nt], a[mt][0], a[mt][1], a[mt][2], a[mt][3],
                             bx[nt][0], bx[nt][1]);
#pragma unroll
            for (int mt = 0; mt < 4; mt++) {
                int row = wm + mt * 16 + g;
                a[mt][0] = *(const unsigned*)&sAlo[row][ko + 2 * tig];
                a[mt][1] = *(const unsigned*)&sAlo[row + 8][ko + 2 * tig];
                a[mt][2] = *(const unsigned*)&sAlo[row][ko + 2 * tig + 8];
                a[mt][3] = *(const unsigned*)&sAlo[row + 8][ko + 2 * tig + 8];
            }
#pragma unroll
            for (int mt = 0; mt < 4; mt++)
#pragma unroll
                for (int nt = 0; nt < 4; nt++)
                    MMA_BF16(acc[mt][nt], a[mt][0], a[mt][1], a[mt][2], a[mt][3],
                             bh[nt][0], bh[nt][1]);
        }
    }

#pragma unroll
    for (int mt = 0; mt < 4; mt++) {
#pragma unroll
        for (int nt = 0; nt < 4; nt++) {
            int row = br + wm + mt * 16 + g;
            int col = bc + wn + nt * 8 + 2 * tig;
            if (row < M)
                *(float2*)(C + (size_t)row * HC + col) =
                    make_float2(acc[mt][nt][0], acc[mt][nt][1]);
            if (row + 8 < M)
                *(float2*)(C + (size_t)(row + 8) * HC + col) =
                    make_float2(acc[mt][nt][2], acc[mt][nt][3]);
        }
    }
}

// ---------------------------------------------------------------------------
// CSR-by-dst construction (rebuilt every call; stateless)
// ---------------------------------------------------------------------------
__global__ void csr_zero_kernel() {
    int i = blockIdx.x * blockDim.x + threadIdx.x;
    if (i < NREL * NN) { g_cnt[i] = 0; g_cnt2[i] = 0; }
}

__global__ void csr_hist_kernel(const int* __restrict__ e0, const int* __restrict__ e1,
                                const int* __restrict__ e2, int E) {
    int idx = blockIdx.x * blockDim.x + threadIdx.x;
    if (idx >= NREL * E) return;
    int r = idx / E, e = idx - r * E;
    const int* ep = (r == 0) ? e0 : (r == 1) ? e1 : e2;
    atomicAdd(&g_cnt[r * NN + ep[E + e]], 1);
}

__global__ void csr_scan_kernel(int N) {
    int r = blockIdx.x;
    int t = threadIdx.x;
    __shared__ int sums[1024];
    int chunk = (N + blockDim.x - 1) / blockDim.x;
    int begin = t * chunk;
    int end = min(begin + chunk, N);
    int s = 0;
    for (int i = begin; i < end; i++) s += g_cnt[r * NN + i];
    sums[t] = s;
    __syncthreads();
    for (int d = 1; d < 1024; d <<= 1) {
        int v = (t >= d) ? sums[t - d] : 0;
        __syncthreads();
        sums[t] += v;
        __syncthreads();
    }
    int run = (t == 0) ? 0 : sums[t - 1];
    for (int i = begin; i < end; i++) {
        g_off[r * (NN + 1) + i] = run;
        run += g_cnt[r * NN + i];
    }
    if (t == blockDim.x - 1) g_off[r * (NN + 1) + N] = run;
}

__global__ void csr_scatter_kernel(const int* __restrict__ e0, const int* __restrict__ e1,
                                   const int* __restrict__ e2, int E) {
    int idx = blockIdx.x * blockDim.x + threadIdx.x;
    if (idx >= NREL * E) return;
    int r = idx / E, e = idx - r * E;
    const int* ep = (r == 0) ? e0 : (r == 1) ? e1 : e2;
    int d = ep[E + e];
    int pos = g_off[r * (NN + 1) + d] + atomicAdd(&g_cnt2[r * NN + d], 1);
    g_csr[(size_t)r * EE + pos] = ep[e];
}

// ---------------------------------------------------------------------------
// Attention coefficients (one warp per node)
// ---------------------------------------------------------------------------
__global__ void attn_coef_kernel(const float* __restrict__ a_s,
                                 const float* __restrict__ a_d, int N) {
    int warp = (blockIdx.x * blockDim.x + threadIdx.x) >> 5;
    int lane = threadIdx.x & 31;
    if (warp >= N) return;
    int head = lane >> 3;
    int coff = head * HID + (lane & 7) * 8;
    const float4* hp = (const float4*)(g_h + (size_t)warp * HC + coff);
    const float4* sp = (const float4*)(a_s + coff);
    const float4* dp = (const float4*)(a_d + coff);
    float4 h0 = hp[0], h1 = hp[1];
    float4 s0 = sp[0], s1 = sp[1];
    float4 d0 = dp[0], d1 = dp[1];
    float ps = h0.x * s0.x + h0.y * s0.y + h0.z * s0.z + h0.w * s0.w
             + h1.x * s1.x + h1.y * s1.y + h1.z * s1.z + h1.w * s1.w;
    float pd = h0.x * d0.x + h0.y * d0.y + h0.z * d0.z + h0.w * d0.w
             + h1.x * d1.x + h1.y * d1.y + h1.z * d1.z + h1.w * d1.w;
#pragma unroll
    for (int off = 4; off; off >>= 1) {
        ps += __shfl_down_sync(0xffffffffu, ps, off);
        pd += __shfl_down_sync(0xffffffffu, pd, off);
    }
    if ((lane & 7) == 0) {
        g_als[warp * HEADS + head] = ps;
        g_ald[warp * HEADS + head] = pd;
    }
}

// ---------------------------------------------------------------------------
// Fused softmax + aggregation, layer 1 (concat). One warp per dst; NO atomics.
// Shift-free softmax (logits O(1); alpha invariant to the reference max-shift).
// ---------------------------------------------------------------------------
template<bool SELF_LOOP, bool FIRST>
__global__ void agg1_kernel(int rel, const float* __restrict__ b, int N) {
    int w = (blockIdx.x * blockDim.x + threadIdx.x) >> 5;
    int lane = threadIdx.x & 31;
    if (w >= N) return;
    const int* off = g_off + rel * (NN + 1);
    const int* csr = g_csr + (size_t)rel * EE;
    const int d = w;
    const int base = off[d];
    const int deg = off[d + 1] - base;

    float4 ad4 = *(const float4*)(g_ald + (size_t)d * 4);
    float dx = 0.f, dy = 0.f, dz = 0.f, dw = 0.f;
    for (int i = lane; i < deg; i += 32) {
        int s = csr[base + i];
        float4 as4 = *(const float4*)(g_als + (size_t)s * 4);
        dx += __expf(lrelu(as4.x + ad4.x));
        dy += __expf(lrelu(as4.y + ad4.y));
        dz += __expf(lrelu(as4.z + ad4.z));
        dw += __expf(lrelu(as4.w + ad4.w));
    }
#pragma unroll
    for (int o = 16; o; o >>= 1) {
        dx += __shfl_xor_sync(0xffffffffu, dx, o);
        dy += __shfl_xor_sync(0xffffffffu, dy, o);
        dz += __shfl_xor_sync(0xffffffffu, dz, o);
        dw += __shfl_xor_sync(0xffffffffu, dw, o);
    }
    float slx = 0.f, sly = 0.f, slz = 0.f, slw = 0.f;
    if (SELF_LOOP) {
        float4 as4 = *(const float4*)(g_als + (size_t)d * 4);
        slx = __expf(lrelu(as4.x + ad4.x));
        sly = __expf(lrelu(as4.y + ad4.y));
        slz = __expf(lrelu(as4.z + ad4.z));
        slw = __expf(lrelu(as4.w + ad4.w));
        dx += slx; dy += sly; dz += slz; dw += slw;
    }
    const int head = lane >> 3;
    float invh = (head == 0) ? 1.f / (dx + 1e-16f)
               : (head == 1) ? 1.f / (dy + 1e-16f)
               : (head == 2) ? 1.f / (dz + 1e-16f)
                             : 1.f / (dw + 1e-16f);
    float adh = (head == 0) ? ad4.x : (head == 1) ? ad4.y
              : (head == 2) ? ad4.z : ad4.w;

    float* op = g_out1 + (size_t)d * HC + lane * 8;
    float4 a0, a1;
    if (FIRST) {
        int c = lane * 8;
        a0.x = b[c + 0] + b[HC + c + 0] + b[2 * HC + c + 0];
        a0.y = b[c + 1] + b[HC + c + 1] + b[2 * HC + c + 1];
        a0.z = b[c + 2] + b[HC + c + 2] + b[2 * HC + c + 2];
        a0.w = b[c + 3] + b[HC + c + 3] + b[2 * HC + c + 3];
        a1.x = b[c + 4] + b[HC + c + 4] + b[2 * HC + c + 4];
        a1.y = b[c + 5] + b[HC + c + 5] + b[2 * HC + c + 5];
        a1.z = b[c + 6] + b[HC + c + 6] + b[2 * HC + c + 6];
        a1.w = b[c + 7] + b[HC + c + 7] + b[2 * HC + c + 7];
    } else {
        a0 = *(const float4*)op;
        a1 = *(const float4*)(op + 4);
    }
    for (int i = 0; i < deg; i++) {
        int s = csr[base + i];
        float ash = g_als[(size_t)s * 4 + head];
        float alpha = __expf(lrelu(ash + adh)) * invh;
        const float4* hp = (const float4*)(g_h + (size_t)s * HC) + lane * 2;
        float4 v0 = hp[0], v1 = hp[1];
        a0.x += alpha * v0.x; a0.y += alpha * v0.y;
        a0.z += alpha * v0.z; a0.w += alpha * v0.w;
        a1.x += alpha * v1.x; a1.y += alpha * v1.y;
        a1.z += alpha * v1.z; a1.w += alpha * v1.w;
    }
    if (SELF_LOOP) {
        float sl = (head == 0) ? slx : (head == 1) ? sly : (head == 2) ? slz : slw;
        float alpha = sl * invh;
        const float4* hp = (const float4*)(g_h + (size_t)d * HC) + lane * 2;
        float4 v0 = hp[0], v1 = hp[1];
        a0.x += alpha * v0.x; a0.y += alpha * v0.y;
        a0.z += alpha * v0.z; a0.w += alpha * v0.w;
        a1.x += alpha * v1.x; a1.y += alpha * v1.y;
        a1.z += alpha * v1.z; a1.w += alpha * v1.w;
    }
    *(float4*)op = a0;
    *(float4*)(op + 4) = a1;
}

// ---------------------------------------------------------------------------
// Fused softmax + aggregation, layer 2 (mean over heads). One warp per dst.
// ---------------------------------------------------------------------------
template<bool SELF_LOOP, bool FIRST>
__global__ void agg2_kernel(int rel, const float* __restrict__ b, int N) {
    int w = (blockIdx.x * blockDim.x + threadIdx.x) >> 5;
    int lane = threadIdx.x & 31;
    if (w >= N) return;
    const int* off = g_off + rel * (NN + 1);
    const int* csr = g_csr + (size_t)rel * EE;
    const int d = w;
    const int base = off[d];
    const int deg = off[d + 1] - base;

    float4 ad4 = *(const float4*)(g_ald + (size_t)d * 4);
    float dx = 0.f, dy = 0.f, dz = 0.f, dw = 0.f;
    for (int i = lane; i < deg; i += 32) {
        int s = csr[base + i];
        float4 as4 = *(const float4*)(g_als + (size_t)s * 4);
        dx += __expf(lrelu(as4.x + ad4.x));
        dy += __expf(lrelu(as4.y + ad4.y));
        dz += __expf(lrelu(as4.z + ad4.z));
        dw += __expf(lrelu(as4.w + ad4.w));
    }
#pragma unroll
    for (int o = 16; o; o >>= 1) {
        dx += __shfl_xor_sync(0xffffffffu, dx, o);
        dy += __shfl_xor_sync(0xffffffffu, dy, o);
        dz += __shfl_xor_sync(0xffffffffu, dz, o);
        dw += __shfl_xor_sync(0xffffffffu, dw, o);
    }
    float slx = 0.f, sly = 0.f, slz = 0.f, slw = 0.f;
    if (SELF_LOOP) {
        float4 as4 = *(const float4*)(g_als + (size_t)d * 4);
        slx = __expf(lrelu(as4.x + ad4.x));
        sly = __expf(lrelu(as4.y + ad4.y));
        slz = __expf(lrelu(as4.z + ad4.z));
        slw = __expf(lrelu(as4.w + ad4.w));
        dx += slx; dy += sly; dz += slz; dw += slw;
    }
    float i0 = 0.25f / (dx + 1e-16f), i1 = 0.25f / (dy + 1e-16f);
    float i2 = 0.25f / (dz + 1e-16f), i3 = 0.25f / (dw + 1e-16f);

    float* op = g_out2 + (size_t)d * HID + lane * 2;
    float2 acc;
    if (FIRST) {
        int c = lane * 2;
        acc.x = b[c] + b[HID + c] + b[2 * HID + c];
        acc.y = b[c + 1] + b[HID + c + 1] + b[2 * HID + c + 1];
    } else {
        acc = *(const float2*)op;
    }
    for (int i = 0; i < deg; i++) {
        int s = csr[base + i];
        float4 as4 = *(const float4*)(g_als + (size_t)s * 4);
        float a0 = __expf(lrelu(as4.x + ad4.x)) * i0;
        float a1 = __expf(lrelu(as4.y + ad4.y)) * i1;
        float a2 = __expf(lrelu(as4.z + ad4.z)) * i2;
        float a3 = __expf(lrelu(as4.w + ad4.w)) * i3;
        const float* hrow = g_h + (size_t)s * HC;
        float2 v0 = *(const float2*)(hrow + 0 * HID + lane * 2);
        float2 v1 = *(const float2*)(hrow + 1 * HID + lane * 2);
        float2 v2 = *(const float2*)(hrow + 2 * HID + lane * 2);
        float2 v3 = *(const float2*)(hrow + 3 * HID + lane * 2);
        acc.x += a0 * v0.x + a1 * v1.x + a2 * v2.x + a3 * v3.x;
        acc.y += a0 * v0.y + a1 * v1.y + a2 * v2.y + a3 * v3.y;
    }
    if (SELF_LOOP) {
        float a0 = slx * i0, a1 = sly * i1, a2 = slz * i2, a3 = slw * i3;
        const float* hrow = g_h + (size_t)d * HC;
        float2 v0 = *(const float2*)(hrow + 0 * HID + lane * 2);
        float2 v1 = *(const float2*)(hrow + 1 * HID + lane * 2);
        float2 v2 = *(const float2*)(hrow + 2 * HID + lane * 2);
        float2 v3 = *(const float2*)(hrow + 3 * HID + lane * 2);
        acc.x += a0 * v0.x + a1 * v1.x + a2 * v2.x + a3 * v3.x;
        acc.y += a0 * v0.y + a1 * v1.y + a2 * v2.y + a3 * v3.y;
    }
    *(float2*)op = acc;
}

// ---------------------------------------------------------------------------
// SIMT SGEMM (final linear layer): out = relu(g_out2) @ Wl + bl
// ---------------------------------------------------------------------------
template<int BM, int BN, int BK, int TM, int TN>
__global__ void __launch_bounds__((BM / TM) * (BN / TN))
final_gemm_kernel(const float* __restrict__ B, float* __restrict__ C,
                  const float* __restrict__ bias, int M, int N, int K) {
    constexpr int NT = (BM / TM) * (BN / TN);
    __shared__ float As[BK][BM + 4];
    __shared__ float Bs[BK][BN];
    const float* A = (const float*)g_out2;
    const int tid = threadIdx.x;
    const int block_row = blockIdx.y * BM;
    const int block_col = blockIdx.x * BN;
    const int tcol = tid % (BN / TN);
    const int trow = tid / (BN / TN);

    float acc[TM][TN];
#pragma unroll
    for (int i = 0; i < TM; i++)
#pragma unroll
        for (int j = 0; j < TN; j++) acc[i][j] = 0.f;

    for (int k0 = 0; k0 < K; k0 += BK) {
#pragma unroll
        for (int i = tid; i < BM * BK / 4; i += NT) {
            int r = i / (BK / 4), c4 = i % (BK / 4);
            int gr = block_row + r;
            float4 v = make_float4(0.f, 0.f, 0.f, 0.f);
            if (gr < M) v = *(const float4*)(A + (size_t)gr * K + k0 + c4 * 4);
            v.x = fmaxf(v.x, 0.f); v.y = fmaxf(v.y, 0.f);
            v.z = fmaxf(v.z, 0.f); v.w = fmaxf(v.w, 0.f);
            As[c4 * 4 + 0][r] = v.x; As[c4 * 4 + 1][r] = v.y;
            As[c4 * 4 + 2][r] = v.z; As[c4 * 4 + 3][r] = v.w;
        }
#pragma unroll
        for (int i = tid; i < BK * BN / 4; i += NT) {
            int r = i / (BN / 4), c4 = i % (BN / 4);
            *(float4*)&Bs[r][c4 * 4] =
                *(const float4*)(B + (size_t)(k0 + r) * N + block_col + c4 * 4);
        }
        __syncthreads();
#pragma unroll
        for (int kk = 0; kk < BK; kk++) {
            float ar[TM], br[TN];
#pragma unroll
            for (int i = 0; i < TM; i++) ar[i] = As[kk][trow * TM + i];
#pragma unroll
            for (int j = 0; j < TN; j++) br[j] = Bs[kk][tcol * TN + j];
#pragma unroll
            for (int i = 0; i < TM; i++)
#pragma unroll
                for (int j = 0; j < TN; j++) acc[i][j] += ar[i] * br[j];
        }
        __syncthreads();
    }
#pragma unroll
    for (int i = 0; i < TM; i++) {
        int gr = block_row + trow * TM + i;
        if (gr >= M) continue;
#pragma unroll
        for (int j = 0; j < TN; j += 4) {
            int gc = block_col + tcol * TN + j;
            float4 v = make_float4(acc[i][j] + bias[gc], acc[i][j + 1] + bias[gc + 1],
                                   acc[i][j + 2] + bias[gc + 2], acc[i][j + 3] + bias[gc + 3]);
            *(float4*)(C + (size_t)gr * N + gc) = v;
        }
    }
}

// ---------------------------------------------------------------------------
// Launcher: kernel launches ONLY (graph-capture safe)
// ---------------------------------------------------------------------------
extern "C" void kernel_launch(void* const* d_in, const int* in_sizes, int n_in,
                              void* d_out, int out_size) {
    const float* x   = (const float*)d_in[0];
    const int*   e0  = (const int*)d_in[1];
    const int*   e1  = (const int*)d_in[2];
    const int*   e2  = (const int*)d_in[3];
    const float* W1  = (const float*)d_in[4];
    const float* a1s = (const float*)d_in[5];
    const float* a1d = (const float*)d_in[6];
    const float* b1  = (const float*)d_in[7];
    const float* W2  = (const float*)d_in[8];
    const float* a2s = (const float*)d_in[9];
    const float* a2d = (const float*)d_in[10];
    const float* b2  = (const float*)d_in[11];
    const float* Wl  = (const float*)d_in[12];
    const float* bl  = (const float*)d_in[13];
    float* out = (float*)d_out;

    const int N = in_sizes[0] / IN_CH;
    const int E = in_sizes[1] / 2;

    // ---------------- CSR-by-dst build ----------------
    csr_zero_kernel<<<(NREL * NN + 255) / 256, 256>>>();
    csr_hist_kernel<<<(NREL * E + 255) / 256, 256>>>(e0, e1, e2, E);
    csr_scan_kernel<<<NREL, 1024>>>(N);
    csr_scatter_kernel<<<(NREL * E + 255) / 256, 256>>>(e0, e1, e2, E);

    const dim3 ggrid(2, (N + 127) / 128);
    const int agg_blocks = (N * 32 + 255) / 256;

    // ---------------- Layer 1 (concat) ----------------
    for (int r = 0; r < 3; r++) {
        mma_gemm_kernel<false, true, IN_CH><<<ggrid, 256>>>(
            x, W1 + (size_t)r * IN_CH * HC, N);
        attn_coef_kernel<<<(N + 7) / 8, 256>>>(a1s + r * HC, a1d + r * HC, N);
        if (r == 0)      agg1_kernel<false, true ><<<agg_blocks, 256>>>(0, b1, N);
        else if (r == 1) agg1_kernel<true,  false><<<agg_blocks, 256>>>(1, b1, N);
        else             agg1_kernel<true,  false><<<agg_blocks, 256>>>(2, b1, N);
    }

    // ---------------- Layer 2 (mean over heads) ----------------
    for (int r = 0; r < 3; r++) {
        mma_gemm_kernel<true, false, HC><<<ggrid, 256>>>(
            nullptr, W2 + (size_t)r * HC * HC, N);
        attn_coef_kernel<<<(N + 7) / 8, 256>>>(a2s + r * HC, a2d + r * HC, N);
        if (r == 0)      agg2_kernel<false, true ><<<agg_blocks, 256>>>(0, b2, N);
        else if (r == 1) agg2_kernel<true,  false><<<agg_blocks, 256>>>(1, b2, N);
        else             agg2_kernel<true,  false><<<agg_blocks, 256>>>(2, b2, N);
    }

    // ---------------- Final linear ----------------
    {
        dim3 grid(1, (N + 127) / 128);
        final_gemm_kernel<128, 64, 16, 4, 8><<<grid, 256>>>(
            Wl, out, bl, N, OUT_CH, OUT_CH);
    }
}

// round 8
// speedup vs baseline: 2.2885x; 1.0591x over previous
#include <cuda_runtime.h>
#include <cuda_bf16.h>
#include <cuda_fp16.h>
#include <cstdint>

#define NN 50000
#define EE 800000
#define IN_CH 128
#define HID 64
#define HEADS 4
#define HC (HEADS * HID)   // 256
#define OUT_CH 64
#define NREL 3

// ---------------------------------------------------------------------------
// Scratch (device globals; no allocation allowed anywhere)
// g_h is fp16: halves the dominant edge-gather traffic (rel_err ~3e-4 budget).
// ---------------------------------------------------------------------------
__device__ __align__(16) __half g_h[(size_t)NN * HC];
__device__ __align__(16) float g_out1[(size_t)NN * HC];
__device__ __align__(16) float g_out2[(size_t)NN * HID];
__device__ __align__(16) float g_als[(size_t)NN * HEADS];
__device__ __align__(16) float g_ald[(size_t)NN * HEADS];
__device__ int g_cnt[NREL * NN];
__device__ int g_cnt2[NREL * NN];   // scatter cursors (init'd by scan)
__device__ int g_off[NREL * (NN + 1)];
__device__ int g_csr[(size_t)NREL * EE];

__device__ __forceinline__ float lrelu(float x) { return fmaxf(x, 0.2f * x); }

__device__ __forceinline__ void bf16_split(float v, unsigned short& h, unsigned short& l) {
    __nv_bfloat16 hb = __float2bfloat16_rn(v);
    float r = v - __bfloat162float(hb);
    __nv_bfloat16 lb = __float2bfloat16_rn(r);
    h = __bfloat16_as_ushort(hb);
    l = __bfloat16_as_ushort(lb);
}
__device__ __forceinline__ unsigned pk2(unsigned short a, unsigned short b) {
    return (unsigned)a | ((unsigned)b << 16);
}

#define MMA_BF16(d, a0, a1, a2, a3, b0, b1)                                    \
    asm volatile(                                                              \
        "mma.sync.aligned.m16n8k16.row.col.f32.bf16.bf16.f32 "                 \
        "{%0,%1,%2,%3}, {%4,%5,%6,%7}, {%8,%9}, {%0,%1,%2,%3};"                \
        : "+f"(d[0]), "+f"(d[1]), "+f"(d[2]), "+f"(d[3])                       \
        : "r"(a0), "r"(a1), "r"(a2), "r"(a3), "r"(b0), "r"(b1))

// ---------------------------------------------------------------------------
// bf16x3 split-precision tensor-core GEMM (validated round 6):
//   g_h[M, 256] = fp16( op(A)[M, K] @ B[K, 256] )
// ---------------------------------------------------------------------------
template<bool RELU_A, bool A_FROM_PARAM, int K>
__global__ void __launch_bounds__(256, 2)
mma_gemm_kernel(const float* __restrict__ Ap, const float* __restrict__ B, int M) {
    constexpr int BKP = 40;
    __shared__ unsigned short sAhi[128][BKP], sAlo[128][BKP];
    __shared__ unsigned short sBhi[128][BKP], sBlo[128][BKP];

    const float* A = A_FROM_PARAM ? Ap : (const float*)g_out1;

    const int tid = threadIdx.x;
    const int br = blockIdx.y * 128;
    const int bc = blockIdx.x * 128;
    const int lane = tid & 31, wid = tid >> 5;
    const int g = lane >> 2, tig = lane & 3;
    const int wm = (wid >> 2) * 64;
    const int wn = (wid & 3) * 32;

    float acc[4][4][4];
#pragma unroll
    for (int i = 0; i < 4; i++)
#pragma unroll
        for (int j = 0; j < 4; j++)
#pragma unroll
            for (int q = 0; q < 4; q++) acc[i][j][q] = 0.f;

    const int nB = tid & 127;
    const int kbB = (tid >> 7) * 4;

    for (int kt = 0; kt < K / 32; kt++) {
        const int k0 = kt * 32;
        if (kt) __syncthreads();

#pragma unroll
        for (int it = 0; it < 4; it++) {
            int idx = tid + it * 256;
            int r = idx >> 3;
            int c4 = (idx & 7) * 4;
            float4 v = make_float4(0.f, 0.f, 0.f, 0.f);
            if (br + r < M) v = *(const float4*)(A + (size_t)(br + r) * K + k0 + c4);
            if (RELU_A) {
                v.x = fmaxf(v.x, 0.f); v.y = fmaxf(v.y, 0.f);
                v.z = fmaxf(v.z, 0.f); v.w = fmaxf(v.w, 0.f);
            }
            unsigned short h0, h1, h2, h3, l0, l1, l2, l3;
            bf16_split(v.x, h0, l0); bf16_split(v.y, h1, l1);
            bf16_split(v.z, h2, l2); bf16_split(v.w, h3, l3);
            *(uint2*)&sAhi[r][c4] = make_uint2(pk2(h0, h1), pk2(h2, h3));
            *(uint2*)&sAlo[r][c4] = make_uint2(pk2(l0, l1), pk2(l2, l3));
        }
#pragma unroll
        for (int it = 0; it < 4; it++) {
            int ks = kbB + it * 8;
            float v0 = B[(size_t)(k0 + ks + 0) * HC + bc + nB];
            float v1 = B[(size_t)(k0 + ks + 1) * HC + bc + nB];
            float v2 = B[(size_t)(k0 + ks + 2) * HC + bc + nB];
            float v3 = B[(size_t)(k0 + ks + 3) * HC + bc + nB];
            unsigned short h0, h1, h2, h3, l0, l1, l2, l3;
            bf16_split(v0, h0, l0); bf16_split(v1, h1, l1);
            bf16_split(v2, h2, l2); bf16_split(v3, h3, l3);
            *(uint2*)&sBhi[nB][ks] = make_uint2(pk2(h0, h1), pk2(h2, h3));
            *(uint2*)&sBlo[nB][ks] = make_uint2(pk2(l0, l1), pk2(l2, l3));
        }
        __syncthreads();

#pragma unroll
        for (int ks = 0; ks < 2; ks++) {
            const int ko = ks * 16;
            unsigned a[4][4], bh[4][2], bx[4][2];
#pragma unroll
            for (int mt = 0; mt < 4; mt++) {
                int row = wm + mt * 16 + g;
                a[mt][0] = *(const unsigned*)&sAhi[row][ko + 2 * tig];
                a[mt][1] = *(const unsigned*)&sAhi[row + 8][ko + 2 * tig];
                a[mt][2] = *(const unsigned*)&sAhi[row][ko + 2 * tig + 8];
                a[mt][3] = *(const unsigned*)&sAhi[row + 8][ko + 2 * tig + 8];
            }
#pragma unroll
            for (int nt = 0; nt < 4; nt++) {
                int col = wn + nt * 8 + g;
                bh[nt][0] = *(const unsigned*)&sBhi[col][ko + 2 * tig];
                bh[nt][1] = *(const unsigned*)&sBhi[col][ko + 2 * tig + 8];
            }
#pragma unroll
            for (int mt = 0; mt < 4; mt++)
#pragma unroll
                for (int nt = 0; nt < 4; nt++)
                    MMA_BF16(acc[mt][nt], a[mt][0], a[mt][1], a[mt][2], a[mt][3],
                             bh[nt][0], bh[nt][1]);
#pragma unroll
            for (int nt = 0; nt < 4; nt++) {
                int col = wn + nt * 8 + g;
                bx[nt][0] = *(const unsigned*)&sBlo[col][ko + 2 * tig];
                bx[nt][1] = *(const unsigned*)&sBlo[col][ko + 2 * tig + 8];
            }
#pragma unroll
            for (int mt = 0; mt < 4; mt++)
#pragma unroll
                for (int nt = 0; nt < 4; nt++)
                    MMA_BF16(acc[mt][nt], a[mt][0], a[mt][1], a[mt][2], a[mt][3],
                             bx[nt][0], bx[nt][1]);
#pragma unroll
            for (int mt = 0; mt < 4; mt++) {
                int row = wm + mt * 16 + g;
                a[mt][0] = *(const unsigned*)&sAlo[row][ko + 2 * tig];
                a[mt][1] = *(const unsigned*)&sAlo[row + 8][ko + 2 * tig];
                a[mt][2] = *(const unsigned*)&sAlo[row][ko + 2 * tig + 8];
                a[mt][3] = *(const unsigned*)&sAlo[row + 8][ko + 2 * tig + 8];
            }
#pragma unroll
            for (int mt = 0; mt < 4; mt++)
#pragma unroll
                for (int nt = 0; nt < 4; nt++)
                    MMA_BF16(acc[mt][nt], a[mt][0], a[mt][1], a[mt][2], a[mt][3],
                             bh[nt][0], bh[nt][1]);
        }
    }

    // epilogue: fp32 acc -> fp16 g_h
#pragma unroll
    for (int mt = 0; mt < 4; mt++) {
#pragma unroll
        for (int nt = 0; nt < 4; nt++) {
            int row = br + wm + mt * 16 + g;
            int col = bc + wn + nt * 8 + 2 * tig;
            if (row < M)
                *(__half2*)(g_h + (size_t)row * HC + col) =
                    __floats2half2_rn(acc[mt][nt][0], acc[mt][nt][1]);
            if (row + 8 < M)
                *(__half2*)(g_h + (size_t)(row + 8) * HC + col) =
                    __floats2half2_rn(acc[mt][nt][2], acc[mt][nt][3]);
        }
    }
}

// ---------------------------------------------------------------------------
// CSR-by-dst construction (rebuilt every call; stateless)
// ---------------------------------------------------------------------------
__global__ void csr_zero_kernel() {
    int i = blockIdx.x * blockDim.x + threadIdx.x;
    if (i < NREL * NN) g_cnt[i] = 0;
}

__global__ void csr_hist_kernel(const int* __restrict__ e0, const int* __restrict__ e1,
                                const int* __restrict__ e2, int E) {
    int idx = blockIdx.x * blockDim.x + threadIdx.x;
    if (idx >= NREL * E) return;
    int r = idx / E, e = idx - r * E;
    const int* ep = (r == 0) ? e0 : (r == 1) ? e1 : e2;
    atomicAdd(&g_cnt[r * NN + ep[E + e]], 1);
}

// one block per relation; exclusive scan; also seeds scatter cursors (g_cnt2)
__global__ void csr_scan_kernel(int N) {
    int r = blockIdx.x;
    int t = threadIdx.x;
    __shared__ int sums[1024];
    int chunk = (N + blockDim.x - 1) / blockDim.x;
    int begin = t * chunk;
    int end = min(begin + chunk, N);
    int s = 0;
    for (int i = begin; i < end; i++) s += g_cnt[r * NN + i];
    sums[t] = s;
    __syncthreads();
    for (int d = 1; d < 1024; d <<= 1) {
        int v = (t >= d) ? sums[t - d] : 0;
        __syncthreads();
        sums[t] += v;
        __syncthreads();
    }
    int run = (t == 0) ? 0 : sums[t - 1];
    for (int i = begin; i < end; i++) {
        g_off[r * (NN + 1) + i] = run;
        g_cnt2[r * NN + i] = run;
        run += g_cnt[r * NN + i];
    }
    if (t == blockDim.x - 1) g_off[r * (NN + 1) + N] = run;
}

__global__ void csr_scatter_kernel(const int* __restrict__ e0, const int* __restrict__ e1,
                                   const int* __restrict__ e2, int E) {
    int idx = blockIdx.x * blockDim.x + threadIdx.x;
    if (idx >= NREL * E) return;
    int r = idx / E, e = idx - r * E;
    const int* ep = (r == 0) ? e0 : (r == 1) ? e1 : e2;
    int d = ep[E + e];
    int pos = atomicAdd(&g_cnt2[r * NN + d], 1);
    g_csr[(size_t)r * EE + pos] = ep[e];
}

// ---------------------------------------------------------------------------
// Attention coefficients (one warp per node); reads fp16 g_h.
// ---------------------------------------------------------------------------
__global__ void attn_coef_kernel(const float* __restrict__ a_s,
                                 const float* __restrict__ a_d, int N) {
    int warp = (blockIdx.x * blockDim.x + threadIdx.x) >> 5;
    int lane = threadIdx.x & 31;
    if (warp >= N) return;
    int head = lane >> 3;
    int coff = head * HID + (lane & 7) * 8;
    uint4 hv = *(const uint4*)(g_h + (size_t)warp * HC + coff);
    float2 f0 = __half22float2(*(__half2*)&hv.x);
    float2 f1 = __half22float2(*(__half2*)&hv.y);
    float2 f2 = __half22float2(*(__half2*)&hv.z);
    float2 f3 = __half22float2(*(__half2*)&hv.w);
    const float4* sp = (const float4*)(a_s + coff);
    const float4* dp = (const float4*)(a_d + coff);
    float4 s0 = sp[0], s1 = sp[1];
    float4 d0 = dp[0], d1 = dp[1];
    float ps = f0.x * s0.x + f0.y * s0.y + f1.x * s0.z + f1.y * s0.w
             + f2.x * s1.x + f2.y * s1.y + f3.x * s1.z + f3.y * s1.w;
    float pd = f0.x * d0.x + f0.y * d0.y + f1.x * d0.z + f1.y * d0.w
             + f2.x * d1.x + f2.y * d1.y + f3.x * d1.z + f3.y * d1.w;
#pragma unroll
    for (int off = 4; off; off >>= 1) {
        ps += __shfl_down_sync(0xffffffffu, ps, off);
        pd += __shfl_down_sync(0xffffffffu, pd, off);
    }
    if ((lane & 7) == 0) {
        g_als[warp * HEADS + head] = ps;
        g_ald[warp * HEADS + head] = pd;
    }
}

// ---------------------------------------------------------------------------
// Fused softmax + aggregation, layer 1 (concat). One warp per dst; NO atomics.
// Shift-free softmax (logits O(1); alpha invariant to the reference max-shift).
// ---------------------------------------------------------------------------
template<bool SELF_LOOP, bool FIRST>
__global__ void agg1_kernel(int rel, const float* __restrict__ b, int N) {
    int w = (blockIdx.x * blockDim.x + threadIdx.x) >> 5;
    int lane = threadIdx.x & 31;
    if (w >= N) return;
    const int* off = g_off + rel * (NN + 1);
    const int* csr = g_csr + (size_t)rel * EE;
    const int d = w;
    const int base = off[d];
    const int deg = off[d + 1] - base;

    float4 ad4 = *(const float4*)(g_ald + (size_t)d * 4);
    float dx = 0.f, dy = 0.f, dz = 0.f, dw = 0.f;
    for (int i = lane; i < deg; i += 32) {
        int s = csr[base + i];
        float4 as4 = *(const float4*)(g_als + (size_t)s * 4);
        dx += __expf(lrelu(as4.x + ad4.x));
        dy += __expf(lrelu(as4.y + ad4.y));
        dz += __expf(lrelu(as4.z + ad4.z));
        dw += __expf(lrelu(as4.w + ad4.w));
    }
#pragma unroll
    for (int o = 16; o; o >>= 1) {
        dx += __shfl_xor_sync(0xffffffffu, dx, o);
        dy += __shfl_xor_sync(0xffffffffu, dy, o);
        dz += __shfl_xor_sync(0xffffffffu, dz, o);
        dw += __shfl_xor_sync(0xffffffffu, dw, o);
    }
    float slx = 0.f, sly = 0.f, slz = 0.f, slw = 0.f;
    if (SELF_LOOP) {
        float4 as4 = *(const float4*)(g_als + (size_t)d * 4);
        slx = __expf(lrelu(as4.x + ad4.x));
        sly = __expf(lrelu(as4.y + ad4.y));
        slz = __expf(lrelu(as4.z + ad4.z));
        slw = __expf(lrelu(as4.w + ad4.w));
        dx += slx; dy += sly; dz += slz; dw += slw;
    }
    const int head = lane >> 3;
    float invh = (head == 0) ? 1.f / (dx + 1e-16f)
               : (head == 1) ? 1.f / (dy + 1e-16f)
               : (head == 2) ? 1.f / (dz + 1e-16f)
                             : 1.f / (dw + 1e-16f);
    float adh = (head == 0) ? ad4.x : (head == 1) ? ad4.y
              : (head == 2) ? ad4.z : ad4.w;

    float* op = g_out1 + (size_t)d * HC + lane * 8;
    float4 a0, a1;
    if (FIRST) {
        int c = lane * 8;
        a0.x = b[c + 0] + b[HC + c + 0] + b[2 * HC + c + 0];
        a0.y = b[c + 1] + b[HC + c + 1] + b[2 * HC + c + 1];
        a0.z = b[c + 2] + b[HC + c + 2] + b[2 * HC + c + 2];
        a0.w = b[c + 3] + b[HC + c + 3] + b[2 * HC + c + 3];
        a1.x = b[c + 4] + b[HC + c + 4] + b[2 * HC + c + 4];
        a1.y = b[c + 5] + b[HC + c + 5] + b[2 * HC + c + 5];
        a1.z = b[c + 6] + b[HC + c + 6] + b[2 * HC + c + 6];
        a1.w = b[c + 7] + b[HC + c + 7] + b[2 * HC + c + 7];
    } else {
        a0 = *(const float4*)op;
        a1 = *(const float4*)(op + 4);
    }
    for (int i = 0; i < deg; i++) {
        int s = csr[base + i];
        float ash = g_als[(size_t)s * 4 + head];
        float alpha = __expf(lrelu(ash + adh)) * invh;
        uint4 hv = *((const uint4*)(g_h + (size_t)s * HC) + lane);
        float2 f0 = __half22float2(*(__half2*)&hv.x);
        float2 f1 = __half22float2(*(__half2*)&hv.y);
        float2 f2 = __half22float2(*(__half2*)&hv.z);
        float2 f3 = __half22float2(*(__half2*)&hv.w);
        a0.x += alpha * f0.x; a0.y += alpha * f0.y;
        a0.z += alpha * f1.x; a0.w += alpha * f1.y;
        a1.x += alpha * f2.x; a1.y += alpha * f2.y;
        a1.z += alpha * f3.x; a1.w += alpha * f3.y;
    }
    if (SELF_LOOP) {
        float sl = (head == 0) ? slx : (head == 1) ? sly : (head == 2) ? slz : slw;
        float alpha = sl * invh;
        uint4 hv = *((const uint4*)(g_h + (size_t)d * HC) + lane);
        float2 f0 = __half22float2(*(__half2*)&hv.x);
        float2 f1 = __half22float2(*(__half2*)&hv.y);
        float2 f2 = __half22float2(*(__half2*)&hv.z);
        float2 f3 = __half22float2(*(__half2*)&hv.w);
        a0.x += alpha * f0.x; a0.y += alpha * f0.y;
        a0.z += alpha * f1.x; a0.w += alpha * f1.y;
        a1.x += alpha * f2.x; a1.y += alpha * f2.y;
        a1.z += alpha * f3.x; a1.w += alpha * f3.y;
    }
    *(float4*)op = a0;
    *(float4*)(op + 4) = a1;
}

// ---------------------------------------------------------------------------
// Fused softmax + aggregation, layer 2 (mean over heads). One warp per dst.
// ---------------------------------------------------------------------------
template<bool SELF_LOOP, bool FIRST>
__global__ void agg2_kernel(int rel, const float* __restrict__ b, int N) {
    int w = (blockIdx.x * blockDim.x + threadIdx.x) >> 5;
    int lane = threadIdx.x & 31;
    if (w >= N) return;
    const int* off = g_off + rel * (NN + 1);
    const int* csr = g_csr + (size_t)rel * EE;
    const int d = w;
    const int base = off[d];
    const int deg = off[d + 1] - base;

    float4 ad4 = *(const float4*)(g_ald + (size_t)d * 4);
    float dx = 0.f, dy = 0.f, dz = 0.f, dw = 0.f;
    for (int i = lane; i < deg; i += 32) {
        int s = csr[base + i];
        float4 as4 = *(const float4*)(g_als + (size_t)s * 4);
        dx += __expf(lrelu(as4.x + ad4.x));
        dy += __expf(lrelu(as4.y + ad4.y));
        dz += __expf(lrelu(as4.z + ad4.z));
        dw += __expf(lrelu(as4.w + ad4.w));
    }
#pragma unroll
    for (int o = 16; o; o >>= 1) {
        dx += __shfl_xor_sync(0xffffffffu, dx, o);
        dy += __shfl_xor_sync(0xffffffffu, dy, o);
        dz += __shfl_xor_sync(0xffffffffu, dz, o);
        dw += __shfl_xor_sync(0xffffffffu, dw, o);
    }
    float slx = 0.f, sly = 0.f, slz = 0.f, slw = 0.f;
    if (SELF_LOOP) {
        float4 as4 = *(const float4*)(g_als + (size_t)d * 4);
        slx = __expf(lrelu(as4.x + ad4.x));
        sly = __expf(lrelu(as4.y + ad4.y));
        slz = __expf(lrelu(as4.z + ad4.z));
        slw = __expf(lrelu(as4.w + ad4.w));
        dx += slx; dy += sly; dz += slz; dw += slw;
    }
    float i0 = 0.25f / (dx + 1e-16f), i1 = 0.25f / (dy + 1e-16f);
    float i2 = 0.25f / (dz + 1e-16f), i3 = 0.25f / (dw + 1e-16f);

    float* op = g_out2 + (size_t)d * HID + lane * 2;
    float2 acc;
    if (FIRST) {
        int c = lane * 2;
        acc.x = b[c] + b[HID + c] + b[2 * HID + c];
        acc.y = b[c + 1] + b[HID + c + 1] + b[2 * HID + c + 1];
    } else {
        acc = *(const float2*)op;
    }
    for (int i = 0; i < deg; i++) {
        int s = csr[base + i];
        float4 as4 = *(const float4*)(g_als + (size_t)s * 4);
        float a0 = __expf(lrelu(as4.x + ad4.x)) * i0;
        float a1 = __expf(lrelu(as4.y + ad4.y)) * i1;
        float a2 = __expf(lrelu(as4.z + ad4.z)) * i2;
        float a3 = __expf(lrelu(as4.w + ad4.w)) * i3;
        const __half* hrow = g_h + (size_t)s * HC;
        float2 f0 = __half22float2(*(const __half2*)(hrow + 0 * HID + lane * 2));
        float2 f1 = __half22float2(*(const __half2*)(hrow + 1 * HID + lane * 2));
        float2 f2 = __half22float2(*(const __half2*)(hrow + 2 * HID + lane * 2));
        float2 f3 = __half22float2(*(const __half2*)(hrow + 3 * HID + lane * 2));
        acc.x += a0 * f0.x + a1 * f1.x + a2 * f2.x + a3 * f3.x;
        acc.y += a0 * f0.y + a1 * f1.y + a2 * f2.y + a3 * f3.y;
    }
    if (SELF_LOOP) {
        float a0 = slx * i0, a1 = sly * i1, a2 = slz * i2, a3 = slw * i3;
        const __half* hrow = g_h + (size_t)d * HC;
        float2 f0 = __half22float2(*(const __half2*)(hrow + 0 * HID + lane * 2));
        float2 f1 = __half22float2(*(const __half2*)(hrow + 1 * HID + lane * 2));
        float2 f2 = __half22float2(*(const __half2*)(hrow + 2 * HID + lane * 2));
        float2 f3 = __half22float2(*(const __half2*)(hrow + 3 * HID + lane * 2));
        acc.x += a0 * f0.x + a1 * f1.x + a2 * f2.x + a3 * f3.x;
        acc.y += a0 * f0.y + a1 * f1.y + a2 * f2.y + a3 * f3.y;
    }
    *(float2*)op = acc;
}

// ---------------------------------------------------------------------------
// SIMT SGEMM (final linear layer): out = relu(g_out2) @ Wl + bl
// ---------------------------------------------------------------------------
template<int BM, int BN, int BK, int TM, int TN>
__global__ void __launch_bounds__((BM / TM) * (BN / TN))
final_gemm_kernel(const float* __restrict__ B, float* __restrict__ C,
                  const float* __restrict__ bias, int M, int N, int K) {
    constexpr int NT = (BM / TM) * (BN / TN);
    __shared__ float As[BK][BM + 4];
    __shared__ float Bs[BK][BN];
    const float* A = (const float*)g_out2;
    const int tid = threadIdx.x;
    const int block_row = blockIdx.y * BM;
    const int block_col = blockIdx.x * BN;
    const int tcol = tid % (BN / TN);
    const int trow = tid / (BN / TN);

    float acc[TM][TN];
#pragma unroll
    for (int i = 0; i < TM; i++)
#pragma unroll
        for (int j = 0; j < TN; j++) acc[i][j] = 0.f;

    for (int k0 = 0; k0 < K; k0 += BK) {
#pragma unroll
        for (int i = tid; i < BM * BK / 4; i += NT) {
            int r = i / (BK / 4), c4 = i % (BK / 4);
            int gr = block_row + r;
            float4 v = make_float4(0.f, 0.f, 0.f, 0.f);
            if (gr < M) v = *(const float4*)(A + (size_t)gr * K + k0 + c4 * 4);
            v.x = fmaxf(v.x, 0.f); v.y = fmaxf(v.y, 0.f);
            v.z = fmaxf(v.z, 0.f); v.w = fmaxf(v.w, 0.f);
            As[c4 * 4 + 0][r] = v.x; As[c4 * 4 + 1][r] = v.y;
            As[c4 * 4 + 2][r] = v.z; As[c4 * 4 + 3][r] = v.w;
        }
#pragma unroll
        for (int i = tid; i < BK * BN / 4; i += NT) {
            int r = i / (BN / 4), c4 = i % (BN / 4);
            *(float4*)&Bs[r][c4 * 4] =
                *(const float4*)(B + (size_t)(k0 + r) * N + block_col + c4 * 4);
        }
        __syncthreads();
#pragma unroll
        for (int kk = 0; kk < BK; kk++) {
            float ar[TM], br[TN];
#pragma unroll
            for (int i = 0; i < TM; i++) ar[i] = As[kk][trow * TM + i];
#pragma unroll
            for (int j = 0; j < TN; j++) br[j] = Bs[kk][tcol * TN + j];
#pragma unroll
            for (int i = 0; i < TM; i++)
#pragma unroll
                for (int j = 0; j < TN; j++) acc[i][j] += ar[i] * br[j];
        }
        __syncthreads();
    }
#pragma unroll
    for (int i = 0; i < TM; i++) {
        int gr = block_row + trow * TM + i;
        if (gr >= M) continue;
#pragma unroll
        for (int j = 0; j < TN; j += 4) {
            int gc = block_col + tcol * TN + j;
            float4 v = make_float4(acc[i][j] + bias[gc], acc[i][j + 1] + bias[gc + 1],
                                   acc[i][j + 2] + bias[gc + 2], acc[i][j + 3] + bias[gc + 3]);
            *(float4*)(C + (size_t)gr * N + gc) = v;
        }
    }
}

// ---------------------------------------------------------------------------
// Launcher: kernel launches ONLY (graph-capture safe)
// ---------------------------------------------------------------------------
extern "C" void kernel_launch(void* const* d_in, const int* in_sizes, int n_in,
                              void* d_out, int out_size) {
    const float* x   = (const float*)d_in[0];
    const int*   e0  = (const int*)d_in[1];
    const int*   e1  = (const int*)d_in[2];
    const int*   e2  = (const int*)d_in[3];
    const float* W1  = (const float*)d_in[4];
    const float* a1s = (const float*)d_in[5];
    const float* a1d = (const float*)d_in[6];
    const float* b1  = (const float*)d_in[7];
    const float* W2  = (const float*)d_in[8];
    const float* a2s = (const float*)d_in[9];
    const float* a2d = (const float*)d_in[10];
    const float* b2  = (const float*)d_in[11];
    const float* Wl  = (const float*)d_in[12];
    const float* bl  = (const float*)d_in[13];
    float* out = (float*)d_out;

    const int N = in_sizes[0] / IN_CH;
    const int E = in_sizes[1] / 2;

    // ---------------- CSR-by-dst build ----------------
    csr_zero_kernel<<<(NREL * NN + 255) / 256, 256>>>();
    csr_hist_kernel<<<(NREL * E + 255) / 256, 256>>>(e0, e1, e2, E);
    csr_scan_kernel<<<NREL, 1024>>>(N);
    csr_scatter_kernel<<<(NREL * E + 255) / 256, 256>>>(e0, e1, e2, E);

    const dim3 ggrid(2, (N + 127) / 128);
    const int agg_blocks = (N * 32 + 255) / 256;

    // ---------------- Layer 1 (concat) ----------------
    for (int r = 0; r < 3; r++) {
        mma_gemm_kernel<false, true, IN_CH><<<ggrid, 256>>>(
            x, W1 + (size_t)r * IN_CH * HC, N);
        attn_coef_kernel<<<(N + 7) / 8, 256>>>(a1s + r * HC, a1d + r * HC, N);
        if (r == 0)      agg1_kernel<false, true ><<<agg_blocks, 256>>>(0, b1, N);
        else if (r == 1) agg1_kernel<true,  false><<<agg_blocks, 256>>>(1, b1, N);
        else             agg1_kernel<true,  false><<<agg_blocks, 256>>>(2, b1, N);
    }

    // ---------------- Layer 2 (mean over heads) ----------------
    for (int r = 0; r < 3; r++) {
        mma_gemm_kernel<true, false, HC><<<ggrid, 256>>>(
            nullptr, W2 + (size_t)r * HC * HC, N);
        attn_coef_kernel<<<(N + 7) / 8, 256>>>(a2s + r * HC, a2d + r * HC, N);
        if (r == 0)      agg2_kernel<false, true ><<<agg_blocks, 256>>>(0, b2, N);
        else if (r == 1) agg2_kernel<true,  false><<<agg_blocks, 256>>>(1, b2, N);
        else             agg2_kernel<true,  false><<<agg_blocks, 256>>>(2, b2, N);
    }

    // ---------------- Final linear ----------------
    {
        dim3 grid(1, (N + 127) / 128);
        final_gemm_kernel<128, 64, 16, 4, 8><<<grid, 256>>>(
            Wl, out, bl, N, OUT_CH, OUT_CH);
    }
}

// round 9
// speedup vs baseline: 2.4403x; 1.0663x over previous
#include <cuda_runtime.h>
#include <cuda_bf16.h>
#include <cuda_fp16.h>
#include <cstdint>

#define NN 50000
#define EE 800000
#define IN_CH 128
#define HID 64
#define HEADS 4
#define HC (HEADS * HID)   // 256
#define OUT_CH 64
#define NREL 3

// ---------------------------------------------------------------------------
// Scratch (device globals; no allocation allowed anywhere)
// ---------------------------------------------------------------------------
__device__ __align__(16) __half g_h[(size_t)NN * HC];
__device__ __align__(16) float g_out1[(size_t)NN * HC];
__device__ __align__(16) float g_out2[(size_t)NN * HID];
__device__ __align__(16) float g_als[(size_t)NN * HEADS];
__device__ __align__(16) float g_ald[(size_t)NN * HEADS];
__device__ int g_cnt[NREL * NN];
__device__ int g_cnt2[NREL * NN];   // scatter cursors (seeded by scan)
__device__ int g_off[NREL * (NN + 1)];
__device__ int g_csr[(size_t)NREL * EE];

__device__ __forceinline__ float lrelu(float x) { return fmaxf(x, 0.2f * x); }

__device__ __forceinline__ void bf16_split(float v, unsigned short& h, unsigned short& l) {
    __nv_bfloat16 hb = __float2bfloat16_rn(v);
    float r = v - __bfloat162float(hb);
    __nv_bfloat16 lb = __float2bfloat16_rn(r);
    h = __bfloat16_as_ushort(hb);
    l = __bfloat16_as_ushort(lb);
}
__device__ __forceinline__ unsigned pk2(unsigned short a, unsigned short b) {
    return (unsigned)a | ((unsigned)b << 16);
}

#define MMA_BF16(d, a0, a1, a2, a3, b0, b1)                                    \
    asm volatile(                                                              \
        "mma.sync.aligned.m16n8k16.row.col.f32.bf16.bf16.f32 "                 \
        "{%0,%1,%2,%3}, {%4,%5,%6,%7}, {%8,%9}, {%0,%1,%2,%3};"                \
        : "+f"(d[0]), "+f"(d[1]), "+f"(d[2]), "+f"(d[3])                       \
        : "r"(a0), "r"(a1), "r"(a2), "r"(a3), "r"(b0), "r"(b1))

// ---------------------------------------------------------------------------
// bf16x3 split-precision tensor-core GEMM with FUSED attention-coefficient
// epilogue:
//   g_h[M, 256] = fp16( op(A)[M, K] @ B[K, 256] )
//   g_als[m,h] += <C[m, h*64:(h+1)*64], a_s[h]>   (atomic partial per CTA)
//   g_ald likewise. Requires g_als/g_ald zeroed before launch.
// Each 32-col warp block lies within one head (wn in {0,32,64,96}, bc in
// {0,128}), so the head index is uniform per (warp, CTA).
// ---------------------------------------------------------------------------
template<bool RELU_A, bool A_FROM_PARAM, int K>
__global__ void __launch_bounds__(256, 2)
mma_gemm_kernel(const float* __restrict__ Ap, const float* __restrict__ B,
                const float* __restrict__ a_s, const float* __restrict__ a_d,
                int M) {
    constexpr int BKP = 40;
    __shared__ unsigned short sAhi[128][BKP], sAlo[128][BKP];
    __shared__ unsigned short sBhi[128][BKP], sBlo[128][BKP];

    const float* A = A_FROM_PARAM ? Ap : (const float*)g_out1;

    const int tid = threadIdx.x;
    const int br = blockIdx.y * 128;
    const int bc = blockIdx.x * 128;
    const int lane = tid & 31, wid = tid >> 5;
    const int g = lane >> 2, tig = lane & 3;
    const int wm = (wid >> 2) * 64;
    const int wn = (wid & 3) * 32;

    float acc[4][4][4];
#pragma unroll
    for (int i = 0; i < 4; i++)
#pragma unroll
        for (int j = 0; j < 4; j++)
#pragma unroll
            for (int q = 0; q < 4; q++) acc[i][j][q] = 0.f;

    const int nB = tid & 127;
    const int kbB = (tid >> 7) * 4;

    for (int kt = 0; kt < K / 32; kt++) {
        const int k0 = kt * 32;
        if (kt) __syncthreads();

#pragma unroll
        for (int it = 0; it < 4; it++) {
            int idx = tid + it * 256;
            int r = idx >> 3;
            int c4 = (idx & 7) * 4;
            float4 v = make_float4(0.f, 0.f, 0.f, 0.f);
            if (br + r < M) v = *(const float4*)(A + (size_t)(br + r) * K + k0 + c4);
            if (RELU_A) {
                v.x = fmaxf(v.x, 0.f); v.y = fmaxf(v.y, 0.f);
                v.z = fmaxf(v.z, 0.f); v.w = fmaxf(v.w, 0.f);
            }
            unsigned short h0, h1, h2, h3, l0, l1, l2, l3;
            bf16_split(v.x, h0, l0); bf16_split(v.y, h1, l1);
            bf16_split(v.z, h2, l2); bf16_split(v.w, h3, l3);
            *(uint2*)&sAhi[r][c4] = make_uint2(pk2(h0, h1), pk2(h2, h3));
            *(uint2*)&sAlo[r][c4] = make_uint2(pk2(l0, l1), pk2(l2, l3));
        }
#pragma unroll
        for (int it = 0; it < 4; it++) {
            int ks = kbB + it * 8;
            float v0 = B[(size_t)(k0 + ks + 0) * HC + bc + nB];
            float v1 = B[(size_t)(k0 + ks + 1) * HC + bc + nB];
            float v2 = B[(size_t)(k0 + ks + 2) * HC + bc + nB];
            float v3 = B[(size_t)(k0 + ks + 3) * HC + bc + nB];
            unsigned short h0, h1, h2, h3, l0, l1, l2, l3;
            bf16_split(v0, h0, l0); bf16_split(v1, h1, l1);
            bf16_split(v2, h2, l2); bf16_split(v3, h3, l3);
            *(uint2*)&sBhi[nB][ks] = make_uint2(pk2(h0, h1), pk2(h2, h3));
            *(uint2*)&sBlo[nB][ks] = make_uint2(pk2(l0, l1), pk2(l2, l3));
        }
        __syncthreads();

#pragma unroll
        for (int ks = 0; ks < 2; ks++) {
            const int ko = ks * 16;
            unsigned a[4][4], bh[4][2], bx[4][2];
#pragma unroll
            for (int mt = 0; mt < 4; mt++) {
                int row = wm + mt * 16 + g;
                a[mt][0] = *(const unsigned*)&sAhi[row][ko + 2 * tig];
                a[mt][1] = *(const unsigned*)&sAhi[row + 8][ko + 2 * tig];
                a[mt][2] = *(const unsigned*)&sAhi[row][ko + 2 * tig + 8];
                a[mt][3] = *(const unsigned*)&sAhi[row + 8][ko + 2 * tig + 8];
            }
#pragma unroll
            for (int nt = 0; nt < 4; nt++) {
                int col = wn + nt * 8 + g;
                bh[nt][0] = *(const unsigned*)&sBhi[col][ko + 2 * tig];
                bh[nt][1] = *(const unsigned*)&sBhi[col][ko + 2 * tig + 8];
            }
#pragma unroll
            for (int mt = 0; mt < 4; mt++)
#pragma unroll
                for (int nt = 0; nt < 4; nt++)
                    MMA_BF16(acc[mt][nt], a[mt][0], a[mt][1], a[mt][2], a[mt][3],
                             bh[nt][0], bh[nt][1]);
#pragma unroll
            for (int nt = 0; nt < 4; nt++) {
                int col = wn + nt * 8 + g;
                bx[nt][0] = *(const unsigned*)&sBlo[col][ko + 2 * tig];
                bx[nt][1] = *(const unsigned*)&sBlo[col][ko + 2 * tig + 8];
            }
#pragma unroll
            for (int mt = 0; mt < 4; mt++)
#pragma unroll
                for (int nt = 0; nt < 4; nt++)
                    MMA_BF16(acc[mt][nt], a[mt][0], a[mt][1], a[mt][2], a[mt][3],
                             bx[nt][0], bx[nt][1]);
#pragma unroll
            for (int mt = 0; mt < 4; mt++) {
                int row = wm + mt * 16 + g;
                a[mt][0] = *(const unsigned*)&sAlo[row][ko + 2 * tig];
                a[mt][1] = *(const unsigned*)&sAlo[row + 8][ko + 2 * tig];
                a[mt][2] = *(const unsigned*)&sAlo[row][ko + 2 * tig + 8];
                a[mt][3] = *(const unsigned*)&sAlo[row + 8][ko + 2 * tig + 8];
            }
#pragma unroll
            for (int mt = 0; mt < 4; mt++)
#pragma unroll
                for (int nt = 0; nt < 4; nt++)
                    MMA_BF16(acc[mt][nt], a[mt][0], a[mt][1], a[mt][2], a[mt][3],
                             bh[nt][0], bh[nt][1]);
        }
    }

    // ---- epilogue 1: fp32 acc -> fp16 g_h ----
#pragma unroll
    for (int mt = 0; mt < 4; mt++) {
#pragma unroll
        for (int nt = 0; nt < 4; nt++) {
            int row = br + wm + mt * 16 + g;
            int col = bc + wn + nt * 8 + 2 * tig;
            if (row < M)
                *(__half2*)(g_h + (size_t)row * HC + col) =
                    __floats2half2_rn(acc[mt][nt][0], acc[mt][nt][1]);
            if (row + 8 < M)
                *(__half2*)(g_h + (size_t)(row + 8) * HC + col) =
                    __floats2half2_rn(acc[mt][nt][2], acc[mt][nt][3]);
        }
    }

    // ---- epilogue 2: fused attention-coefficient partial dots ----
    const int head = (bc + wn) >> 6;   // uniform per warp
#pragma unroll
    for (int mt = 0; mt < 4; mt++) {
        float ps0 = 0.f, pd0 = 0.f, ps1 = 0.f, pd1 = 0.f;
#pragma unroll
        for (int nt = 0; nt < 4; nt++) {
            int col = bc + wn + nt * 8 + 2 * tig;
            float w0s = a_s[col], w1s = a_s[col + 1];
            float w0d = a_d[col], w1d = a_d[col + 1];
            ps0 += acc[mt][nt][0] * w0s + acc[mt][nt][1] * w1s;
            pd0 += acc[mt][nt][0] * w0d + acc[mt][nt][1] * w1d;
            ps1 += acc[mt][nt][2] * w0s + acc[mt][nt][3] * w1s;
            pd1 += acc[mt][nt][2] * w0d + acc[mt][nt][3] * w1d;
        }
        // reduce over the 4 lanes (tig) sharing a row
        ps0 += __shfl_down_sync(0xffffffffu, ps0, 2);
        ps0 += __shfl_down_sync(0xffffffffu, ps0, 1);
        pd0 += __shfl_down_sync(0xffffffffu, pd0, 2);
        pd0 += __shfl_down_sync(0xffffffffu, pd0, 1);
        ps1 += __shfl_down_sync(0xffffffffu, ps1, 2);
        ps1 += __shfl_down_sync(0xffffffffu, ps1, 1);
        pd1 += __shfl_down_sync(0xffffffffu, pd1, 2);
        pd1 += __shfl_down_sync(0xffffffffu, pd1, 1);
        if (tig == 0) {
            int row = br + wm + mt * 16 + g;
            if (row < M) {
                atomicAdd(&g_als[row * 4 + head], ps0);
                atomicAdd(&g_ald[row * 4 + head], pd0);
            }
            if (row + 8 < M) {
                atomicAdd(&g_als[(row + 8) * 4 + head], ps1);
                atomicAdd(&g_ald[(row + 8) * 4 + head], pd1);
            }
        }
    }
}

// ---------------------------------------------------------------------------
// Zero attn-coefficient buffers (before each fused GEMM)
// ---------------------------------------------------------------------------
__global__ void zero_attn_kernel(int total) {
    int i = blockIdx.x * blockDim.x + threadIdx.x;
    if (i < total) { g_als[i] = 0.f; g_ald[i] = 0.f; }
}

// ---------------------------------------------------------------------------
// CSR-by-dst construction (rebuilt every call; stateless)
// ---------------------------------------------------------------------------
__global__ void csr_zero_kernel() {
    int i = blockIdx.x * blockDim.x + threadIdx.x;
    if (i < NREL * NN) g_cnt[i] = 0;
}

__global__ void csr_hist_kernel(const int* __restrict__ e0, const int* __restrict__ e1,
                                const int* __restrict__ e2, int E) {
    int idx = blockIdx.x * blockDim.x + threadIdx.x;
    if (idx >= NREL * E) return;
    int r = idx / E, e = idx - r * E;
    const int* ep = (r == 0) ? e0 : (r == 1) ? e1 : e2;
    atomicAdd(&g_cnt[r * NN + ep[E + e]], 1);
}

__global__ void csr_scan_kernel(int N) {
    int r = blockIdx.x;
    int t = threadIdx.x;
    __shared__ int sums[1024];
    int chunk = (N + blockDim.x - 1) / blockDim.x;
    int begin = t * chunk;
    int end = min(begin + chunk, N);
    int s = 0;
    for (int i = begin; i < end; i++) s += g_cnt[r * NN + i];
    sums[t] = s;
    __syncthreads();
    for (int d = 1; d < 1024; d <<= 1) {
        int v = (t >= d) ? sums[t - d] : 0;
        __syncthreads();
        sums[t] += v;
        __syncthreads();
    }
    int run = (t == 0) ? 0 : sums[t - 1];
    for (int i = begin; i < end; i++) {
        g_off[r * (NN + 1) + i] = run;
        g_cnt2[r * NN + i] = run;
        run += g_cnt[r * NN + i];
    }
    if (t == blockDim.x - 1) g_off[r * (NN + 1) + N] = run;
}

__global__ void csr_scatter_kernel(const int* __restrict__ e0, const int* __restrict__ e1,
                                   const int* __restrict__ e2, int E) {
    int idx = blockIdx.x * blockDim.x + threadIdx.x;
    if (idx >= NREL * E) return;
    int r = idx / E, e = idx - r * E;
    const int* ep = (r == 0) ? e0 : (r == 1) ? e1 : e2;
    int d = ep[E + e];
    int pos = atomicAdd(&g_cnt2[r * NN + d], 1);
    g_csr[(size_t)r * EE + pos] = ep[e];
}

// ---------------------------------------------------------------------------
// SINGLE-PASS fused softmax + aggregation, layer 1 (concat).
// One warp per dst; no atomics, no separate denominator pass:
//   out = prev + (Σ_i e_i * h_i) / (Σ_i e_i)   per head.
// Each lane accumulates its head's D redundantly (free) and 8 channels.
// Shift-free softmax (logits O(1); alpha invariant to reference max-shift).
// ---------------------------------------------------------------------------
template<bool SELF_LOOP, bool FIRST>
__global__ void agg1_kernel(int rel, const float* __restrict__ b, int N) {
    int w = (blockIdx.x * blockDim.x + threadIdx.x) >> 5;
    int lane = threadIdx.x & 31;
    if (w >= N) return;
    const int* off = g_off + rel * (NN + 1);
    const int* csr = g_csr + (size_t)rel * EE;
    const int d = w;
    const int base = off[d];
    const int deg = off[d + 1] - base;
    const int head = lane >> 3;

    float adh = g_ald[(size_t)d * 4 + head];
    float D = 0.f;
    float4 n0 = make_float4(0.f, 0.f, 0.f, 0.f);
    float4 n1 = make_float4(0.f, 0.f, 0.f, 0.f);

    for (int i = 0; i < deg; i++) {
        int s = csr[base + i];
        float e = __expf(lrelu(g_als[(size_t)s * 4 + head] + adh));
        D += e;
        uint4 hv = *((const uint4*)(g_h + (size_t)s * HC) + lane);
        float2 f0 = __half22float2(*(__half2*)&hv.x);
        float2 f1 = __half22float2(*(__half2*)&hv.y);
        float2 f2 = __half22float2(*(__half2*)&hv.z);
        float2 f3 = __half22float2(*(__half2*)&hv.w);
        n0.x += e * f0.x; n0.y += e * f0.y;
        n0.z += e * f1.x; n0.w += e * f1.y;
        n1.x += e * f2.x; n1.y += e * f2.y;
        n1.z += e * f3.x; n1.w += e * f3.y;
    }
    if (SELF_LOOP) {
        float e = __expf(lrelu(g_als[(size_t)d * 4 + head] + adh));
        D += e;
        uint4 hv = *((const uint4*)(g_h + (size_t)d * HC) + lane);
        float2 f0 = __half22float2(*(__half2*)&hv.x);
        float2 f1 = __half22float2(*(__half2*)&hv.y);
        float2 f2 = __half22float2(*(__half2*)&hv.z);
        float2 f3 = __half22float2(*(__half2*)&hv.w);
        n0.x += e * f0.x; n0.y += e * f0.y;
        n0.z += e * f1.x; n0.w += e * f1.y;
        n1.x += e * f2.x; n1.y += e * f2.y;
        n1.z += e * f3.x; n1.w += e * f3.y;
    }
    float inv = 1.f / (D + 1e-16f);

    float* op = g_out1 + (size_t)d * HC + lane * 8;
    float4 a0, a1;
    if (FIRST) {
        int c = lane * 8;
        a0.x = b[c + 0] + b[HC + c + 0] + b[2 * HC + c + 0];
        a0.y = b[c + 1] + b[HC + c + 1] + b[2 * HC + c + 1];
        a0.z = b[c + 2] + b[HC + c + 2] + b[2 * HC + c + 2];
        a0.w = b[c + 3] + b[HC + c + 3] + b[2 * HC + c + 3];
        a1.x = b[c + 4] + b[HC + c + 4] + b[2 * HC + c + 4];
        a1.y = b[c + 5] + b[HC + c + 5] + b[2 * HC + c + 5];
        a1.z = b[c + 6] + b[HC + c + 6] + b[2 * HC + c + 6];
        a1.w = b[c + 7] + b[HC + c + 7] + b[2 * HC + c + 7];
    } else {
        a0 = *(const float4*)op;
        a1 = *(const float4*)(op + 4);
    }
    a0.x += inv * n0.x; a0.y += inv * n0.y;
    a0.z += inv * n0.z; a0.w += inv * n0.w;
    a1.x += inv * n1.x; a1.y += inv * n1.y;
    a1.z += inv * n1.z; a1.w += inv * n1.w;
    *(float4*)op = a0;
    *(float4*)(op + 4) = a1;
}

// ---------------------------------------------------------------------------
// SINGLE-PASS fused softmax + aggregation, layer 2 (mean over heads).
// One warp per dst; per-head numerators kept separately, one divide at end.
// ---------------------------------------------------------------------------
template<bool SELF_LOOP, bool FIRST>
__global__ void agg2_kernel(int rel, const float* __restrict__ b, int N) {
    int w = (blockIdx.x * blockDim.x + threadIdx.x) >> 5;
    int lane = threadIdx.x & 31;
    if (w >= N) return;
    const int* off = g_off + rel * (NN + 1);
    const int* csr = g_csr + (size_t)rel * EE;
    const int d = w;
    const int base = off[d];
    const int deg = off[d + 1] - base;

    float4 ad4 = *(const float4*)(g_ald + (size_t)d * 4);
    float Dx = 0.f, Dy = 0.f, Dz = 0.f, Dw = 0.f;
    float2 m0 = make_float2(0.f, 0.f), m1 = make_float2(0.f, 0.f);
    float2 m2 = make_float2(0.f, 0.f), m3 = make_float2(0.f, 0.f);

    for (int i = 0; i < deg; i++) {
        int s = csr[base + i];
        float4 as4 = *(const float4*)(g_als + (size_t)s * 4);
        float e0 = __expf(lrelu(as4.x + ad4.x));
        float e1 = __expf(lrelu(as4.y + ad4.y));
        float e2 = __expf(lrelu(as4.z + ad4.z));
        float e3 = __expf(lrelu(as4.w + ad4.w));
        Dx += e0; Dy += e1; Dz += e2; Dw += e3;
        const __half* hrow = g_h + (size_t)s * HC;
        float2 f0 = __half22float2(*(const __half2*)(hrow + 0 * HID + lane * 2));
        float2 f1 = __half22float2(*(const __half2*)(hrow + 1 * HID + lane * 2));
        float2 f2 = __half22float2(*(const __half2*)(hrow + 2 * HID + lane * 2));
        float2 f3 = __half22float2(*(const __half2*)(hrow + 3 * HID + lane * 2));
        m0.x += e0 * f0.x; m0.y += e0 * f0.y;
        m1.x += e1 * f1.x; m1.y += e1 * f1.y;
        m2.x += e2 * f2.x; m2.y += e2 * f2.y;
        m3.x += e3 * f3.x; m3.y += e3 * f3.y;
    }
    if (SELF_LOOP) {
        float4 as4 = *(const float4*)(g_als + (size_t)d * 4);
        float e0 = __expf(lrelu(as4.x + ad4.x));
        float e1 = __expf(lrelu(as4.y + ad4.y));
        float e2 = __expf(lrelu(as4.z + ad4.z));
        float e3 = __expf(lrelu(as4.w + ad4.w));
        Dx += e0; Dy += e1; Dz += e2; Dw += e3;
        const __half* hrow = g_h + (size_t)d * HC;
        float2 f0 = __half22float2(*(const __half2*)(hrow + 0 * HID + lane * 2));
        float2 f1 = __half22float2(*(const __half2*)(hrow + 1 * HID + lane * 2));
        float2 f2 = __half22float2(*(const __half2*)(hrow + 2 * HID + lane * 2));
        float2 f3 = __half22float2(*(const __half2*)(hrow + 3 * HID + lane * 2));
        m0.x += e0 * f0.x; m0.y += e0 * f0.y;
        m1.x += e1 * f1.x; m1.y += e1 * f1.y;
        m2.x += e2 * f2.x; m2.y += e2 * f2.y;
        m3.x += e3 * f3.x; m3.y += e3 * f3.y;
    }
    float i0 = 0.25f / (Dx + 1e-16f), i1 = 0.25f / (Dy + 1e-16f);
    float i2 = 0.25f / (Dz + 1e-16f), i3 = 0.25f / (Dw + 1e-16f);

    float* op = g_out2 + (size_t)d * HID + lane * 2;
    float2 acc;
    if (FIRST) {
        int c = lane * 2;
        acc.x = b[c] + b[HID + c] + b[2 * HID + c];
        acc.y = b[c + 1] + b[HID + c + 1] + b[2 * HID + c + 1];
    } else {
        acc = *(const float2*)op;
    }
    acc.x += i0 * m0.x + i1 * m1.x + i2 * m2.x + i3 * m3.x;
    acc.y += i0 * m0.y + i1 * m1.y + i2 * m2.y + i3 * m3.y;
    *(float2*)op = acc;
}

// ---------------------------------------------------------------------------
// SIMT SGEMM (final linear layer): out = relu(g_out2) @ Wl + bl
// ---------------------------------------------------------------------------
template<int BM, int BN, int BK, int TM, int TN>
__global__ void __launch_bounds__((BM / TM) * (BN / TN))
final_gemm_kernel(const float* __restrict__ B, float* __restrict__ C,
                  const float* __restrict__ bias, int M, int N, int K) {
    constexpr int NT = (BM / TM) * (BN / TN);
    __shared__ float As[BK][BM + 4];
    __shared__ float Bs[BK][BN];
    const float* A = (const float*)g_out2;
    const int tid = threadIdx.x;
    const int block_row = blockIdx.y * BM;
    const int block_col = blockIdx.x * BN;
    const int tcol = tid % (BN / TN);
    const int trow = tid / (BN / TN);

    float acc[TM][TN];
#pragma unroll
    for (int i = 0; i < TM; i++)
#pragma unroll
        for (int j = 0; j < TN; j++) acc[i][j] = 0.f;

    for (int k0 = 0; k0 < K; k0 += BK) {
#pragma unroll
        for (int i = tid; i < BM * BK / 4; i += NT) {
            int r = i / (BK / 4), c4 = i % (BK / 4);
            int gr = block_row + r;
            float4 v = make_float4(0.f, 0.f, 0.f, 0.f);
            if (gr < M) v = *(const float4*)(A + (size_t)gr * K + k0 + c4 * 4);
            v.x = fmaxf(v.x, 0.f); v.y = fmaxf(v.y, 0.f);
            v.z = fmaxf(v.z, 0.f); v.w = fmaxf(v.w, 0.f);
            As[c4 * 4 + 0][r] = v.x; As[c4 * 4 + 1][r] = v.y;
            As[c4 * 4 + 2][r] = v.z; As[c4 * 4 + 3][r] = v.w;
        }
#pragma unroll
        for (int i = tid; i < BK * BN / 4; i += NT) {
            int r = i / (BN / 4), c4 = i % (BN / 4);
            *(float4*)&Bs[r][c4 * 4] =
                *(const float4*)(B + (size_t)(k0 + r) * N + block_col + c4 * 4);
        }
        __syncthreads();
#pragma unroll
        for (int kk = 0; kk < BK; kk++) {
            float ar[TM], br[TN];
#pragma unroll
            for (int i = 0; i < TM; i++) ar[i] = As[kk][trow * TM + i];
#pragma unroll
            for (int j = 0; j < TN; j++) br[j] = Bs[kk][tcol * TN + j];
#pragma unroll
            for (int i = 0; i < TM; i++)
#pragma unroll
                for (int j = 0; j < TN; j++) acc[i][j] += ar[i] * br[j];
        }
        __syncthreads();
    }
#pragma unroll
    for (int i = 0; i < TM; i++) {
        int gr = block_row + trow * TM + i;
        if (gr >= M) continue;
#pragma unroll
        for (int j = 0; j < TN; j += 4) {
            int gc = block_col + tcol * TN + j;
            float4 v = make_float4(acc[i][j] + bias[gc], acc[i][j + 1] + bias[gc + 1],
                                   acc[i][j + 2] + bias[gc + 2], acc[i][j + 3] + bias[gc + 3]);
            *(float4*)(C + (size_t)gr * N + gc) = v;
        }
    }
}

// ---------------------------------------------------------------------------
// Launcher: kernel launches ONLY (graph-capture safe)
// ---------------------------------------------------------------------------
extern "C" void kernel_launch(void* const* d_in, const int* in_sizes, int n_in,
                              void* d_out, int out_size) {
    const float* x   = (const float*)d_in[0];
    const int*   e0  = (const int*)d_in[1];
    const int*   e1  = (const int*)d_in[2];
    const int*   e2  = (const int*)d_in[3];
    const float* W1  = (const float*)d_in[4];
    const float* a1s = (const float*)d_in[5];
    const float* a1d = (const float*)d_in[6];
    const float* b1  = (const float*)d_in[7];
    const float* W2  = (const float*)d_in[8];
    const float* a2s = (const float*)d_in[9];
    const float* a2d = (const float*)d_in[10];
    const float* b2  = (const float*)d_in[11];
    const float* Wl  = (const float*)d_in[12];
    const float* bl  = (const float*)d_in[13];
    float* out = (float*)d_out;

    const int N = in_sizes[0] / IN_CH;
    const int E = in_sizes[1] / 2;

    // ---------------- CSR-by-dst build ----------------
    csr_zero_kernel<<<(NREL * NN + 255) / 256, 256>>>();
    csr_hist_kernel<<<(NREL * E + 255) / 256, 256>>>(e0, e1, e2, E);
    csr_scan_kernel<<<NREL, 1024>>>(N);
    csr_scatter_kernel<<<(NREL * E + 255) / 256, 256>>>(e0, e1, e2, E);

    const dim3 ggrid(2, (N + 127) / 128);
    const int agg_blocks = (N * 32 + 255) / 256;
    const int zero_blocks = (N * HEADS + 255) / 256;

    // ---------------- Layer 1 (concat) ----------------
    for (int r = 0; r < 3; r++) {
        zero_attn_kernel<<<zero_blocks, 256>>>(N * HEADS);
        mma_gemm_kernel<false, true, IN_CH><<<ggrid, 256>>>(
            x, W1 + (size_t)r * IN_CH * HC, a1s + r * HC, a1d + r * HC, N);
        if (r == 0)      agg1_kernel<false, true ><<<agg_blocks, 256>>>(0, b1, N);
        else if (r == 1) agg1_kernel<true,  false><<<agg_blocks, 256>>>(1, b1, N);
        else             agg1_kernel<true,  false><<<agg_blocks, 256>>>(2, b1, N);
    }

    // ---------------- Layer 2 (mean over heads) ----------------
    for (int r = 0; r < 3; r++) {
        zero_attn_kernel<<<zero_blocks, 256>>>(N * HEADS);
        mma_gemm_kernel<true, false, HC><<<ggrid, 256>>>(
            nullptr, W2 + (size_t)r * HC * HC, a2s + r * HC, a2d + r * HC, N);
        if (r == 0)      agg2_kernel<false, true ><<<agg_blocks, 256>>>(0, b2, N);
        else if (r == 1) agg2_kernel<true,  false><<<agg_blocks, 256>>>(1, b2, N);
        else             agg2_kernel<true,  false><<<agg_blocks, 256>>>(2, b2, N);
    }

    // ---------------- Final linear ----------------
    {
        dim3 grid(1, (N + 127) / 128);
        final_gemm_kernel<128, 64, 16, 4, 8><<<grid, 256>>>(
            Wl, out, bl, N, OUT_CH, OUT_CH);
    }
}

// round 10
// speedup vs baseline: 2.5615x; 1.0497x over previous
#include <cuda_runtime.h>
#include <cuda_bf16.h>
#include <cuda_fp16.h>
#include <cstdint>

#define NN 50000
#define EE 800000
#define IN_CH 128
#define HID 64
#define HEADS 4
#define HC (HEADS * HID)   // 256
#define WIDE (3 * HC)      // 768
#define OUT_CH 64
#define NREL 3

// ---------------------------------------------------------------------------
// Scratch (device globals; no allocation allowed anywhere)
// g_h holds ALL 3 relation planes in fp16: 77 MB -> fits L2 (the fp32 version
// at 153 MB did not; that was round-3's failure mode).
// ---------------------------------------------------------------------------
__device__ __align__(16) __half g_h[(size_t)NN * WIDE];
__device__ __align__(16) float g_out1[(size_t)NN * HC];
__device__ __align__(16) float g_out2[(size_t)NN * HID];
__device__ __align__(16) float g_als[(size_t)NREL * NN * HEADS];
__device__ __align__(16) float g_ald[(size_t)NREL * NN * HEADS];
__device__ int g_cnt[NREL * NN];
__device__ int g_cnt2[NREL * NN];   // scatter cursors (seeded by scan)
__device__ int g_off[NREL * (NN + 1)];
__device__ int g_csr[(size_t)NREL * EE];

__device__ __forceinline__ float lrelu(float x) { return fmaxf(x, 0.2f * x); }

__device__ __forceinline__ void bf16_split(float v, unsigned short& h, unsigned short& l) {
    __nv_bfloat16 hb = __float2bfloat16_rn(v);
    float r = v - __bfloat162float(hb);
    __nv_bfloat16 lb = __float2bfloat16_rn(r);
    h = __bfloat16_as_ushort(hb);
    l = __bfloat16_as_ushort(lb);
}
__device__ __forceinline__ unsigned pk2(unsigned short a, unsigned short b) {
    return (unsigned)a | ((unsigned)b << 16);
}

#define MMA_BF16(d, a0, a1, a2, a3, b0, b1)                                    \
    asm volatile(                                                              \
        "mma.sync.aligned.m16n8k16.row.col.f32.bf16.bf16.f32 "                 \
        "{%0,%1,%2,%3}, {%4,%5,%6,%7}, {%8,%9}, {%0,%1,%2,%3};"                \
        : "+f"(d[0]), "+f"(d[1]), "+f"(d[2]), "+f"(d[3])                       \
        : "r"(a0), "r"(a1), "r"(a2), "r"(a3), "r"(b0), "r"(b1))

// ---------------------------------------------------------------------------
// WIDE bf16x3 split-precision tensor-core GEMM, all 3 relations at once:
//   g_h[M, 768] = fp16( op(A)[M, K] @ W[rel][K, 256] ),  rel = block_col/256
// Fused attention-coefficient epilogue (fp32, pre-rounding):
//   g_als[rel][m][h] += <C_block, a_s[rel][h]> partials (atomic).
// Requires g_als/g_ald zeroed before launch.
// ---------------------------------------------------------------------------
template<bool RELU_A, bool A_FROM_PARAM, int K>
__global__ void __launch_bounds__(256, 2)
mma_gemm_wide_kernel(const float* __restrict__ Ap, const float* __restrict__ W,
                     const float* __restrict__ as_all, const float* __restrict__ ad_all,
                     int M) {
    constexpr int BKP = 40;
    __shared__ unsigned short sAhi[128][BKP], sAlo[128][BKP];
    __shared__ unsigned short sBhi[128][BKP], sBlo[128][BKP];

    const float* A = A_FROM_PARAM ? Ap : (const float*)g_out1;

    const int tid = threadIdx.x;
    const int br = blockIdx.y * 128;
    const int bc = blockIdx.x * 128;          // 0..640, step 128
    const int rel = bc >> 8;                  // 0..2
    const int cb = bc & 255;                  // 0 or 128 within the relation
    const float* B = W + (size_t)rel * K * HC + cb;
    const int lane = tid & 31, wid = tid >> 5;
    const int g = lane >> 2, tig = lane & 3;
    const int wm = (wid >> 2) * 64;
    const int wn = (wid & 3) * 32;

    float acc[4][4][4];
#pragma unroll
    for (int i = 0; i < 4; i++)
#pragma unroll
        for (int j = 0; j < 4; j++)
#pragma unroll
            for (int q = 0; q < 4; q++) acc[i][j][q] = 0.f;

    const int nB = tid & 127;
    const int kbB = (tid >> 7) * 4;

    for (int kt = 0; kt < K / 32; kt++) {
        const int k0 = kt * 32;
        if (kt) __syncthreads();

#pragma unroll
        for (int it = 0; it < 4; it++) {
            int idx = tid + it * 256;
            int r = idx >> 3;
            int c4 = (idx & 7) * 4;
            float4 v = make_float4(0.f, 0.f, 0.f, 0.f);
            if (br + r < M) v = *(const float4*)(A + (size_t)(br + r) * K + k0 + c4);
            if (RELU_A) {
                v.x = fmaxf(v.x, 0.f); v.y = fmaxf(v.y, 0.f);
                v.z = fmaxf(v.z, 0.f); v.w = fmaxf(v.w, 0.f);
            }
            unsigned short h0, h1, h2, h3, l0, l1, l2, l3;
            bf16_split(v.x, h0, l0); bf16_split(v.y, h1, l1);
            bf16_split(v.z, h2, l2); bf16_split(v.w, h3, l3);
            *(uint2*)&sAhi[r][c4] = make_uint2(pk2(h0, h1), pk2(h2, h3));
            *(uint2*)&sAlo[r][c4] = make_uint2(pk2(l0, l1), pk2(l2, l3));
        }
#pragma unroll
        for (int it = 0; it < 4; it++) {
            int ks = kbB + it * 8;
            float v0 = B[(size_t)(k0 + ks + 0) * HC + nB];
            float v1 = B[(size_t)(k0 + ks + 1) * HC + nB];
            float v2 = B[(size_t)(k0 + ks + 2) * HC + nB];
            float v3 = B[(size_t)(k0 + ks + 3) * HC + nB];
            unsigned short h0, h1, h2, h3, l0, l1, l2, l3;
            bf16_split(v0, h0, l0); bf16_split(v1, h1, l1);
            bf16_split(v2, h2, l2); bf16_split(v3, h3, l3);
            *(uint2*)&sBhi[nB][ks] = make_uint2(pk2(h0, h1), pk2(h2, h3));
            *(uint2*)&sBlo[nB][ks] = make_uint2(pk2(l0, l1), pk2(l2, l3));
        }
        __syncthreads();

#pragma unroll
        for (int ks = 0; ks < 2; ks++) {
            const int ko = ks * 16;
            unsigned a[4][4], bh[4][2], bx[4][2];
#pragma unroll
            for (int mt = 0; mt < 4; mt++) {
                int row = wm + mt * 16 + g;
                a[mt][0] = *(const unsigned*)&sAhi[row][ko + 2 * tig];
                a[mt][1] = *(const unsigned*)&sAhi[row + 8][ko + 2 * tig];
                a[mt][2] = *(const unsigned*)&sAhi[row][ko + 2 * tig + 8];
                a[mt][3] = *(const unsigned*)&sAhi[row + 8][ko + 2 * tig + 8];
            }
#pragma unroll
            for (int nt = 0; nt < 4; nt++) {
                int col = wn + nt * 8 + g;
                bh[nt][0] = *(const unsigned*)&sBhi[col][ko + 2 * tig];
                bh[nt][1] = *(const unsigned*)&sBhi[col][ko + 2 * tig + 8];
            }
#pragma unroll
            for (int mt = 0; mt < 4; mt++)
#pragma unroll
                for (int nt = 0; nt < 4; nt++)
                    MMA_BF16(acc[mt][nt], a[mt][0], a[mt][1], a[mt][2], a[mt][3],
                             bh[nt][0], bh[nt][1]);
#pragma unroll
            for (int nt = 0; nt < 4; nt++) {
                int col = wn + nt * 8 + g;
                bx[nt][0] = *(const unsigned*)&sBlo[col][ko + 2 * tig];
                bx[nt][1] = *(const unsigned*)&sBlo[col][ko + 2 * tig + 8];
            }
#pragma unroll
            for (int mt = 0; mt < 4; mt++)
#pragma unroll
                for (int nt = 0; nt < 4; nt++)
                    MMA_BF16(acc[mt][nt], a[mt][0], a[mt][1], a[mt][2], a[mt][3],
                             bx[nt][0], bx[nt][1]);
#pragma unroll
            for (int mt = 0; mt < 4; mt++) {
                int row = wm + mt * 16 + g;
                a[mt][0] = *(const unsigned*)&sAlo[row][ko + 2 * tig];
                a[mt][1] = *(const unsigned*)&sAlo[row + 8][ko + 2 * tig];
                a[mt][2] = *(const unsigned*)&sAlo[row][ko + 2 * tig + 8];
                a[mt][3] = *(const unsigned*)&sAlo[row + 8][ko + 2 * tig + 8];
            }
#pragma unroll
            for (int mt = 0; mt < 4; mt++)
#pragma unroll
                for (int nt = 0; nt < 4; nt++)
                    MMA_BF16(acc[mt][nt], a[mt][0], a[mt][1], a[mt][2], a[mt][3],
                             bh[nt][0], bh[nt][1]);
        }
    }

    // ---- epilogue 1: fp32 acc -> fp16 g_h (wide layout) ----
#pragma unroll
    for (int mt = 0; mt < 4; mt++) {
#pragma unroll
        for (int nt = 0; nt < 4; nt++) {
            int row = br + wm + mt * 16 + g;
            int col = bc + wn + nt * 8 + 2 * tig;
            if (row < M)
                *(__half2*)(g_h + (size_t)row * WIDE + col) =
                    __floats2half2_rn(acc[mt][nt][0], acc[mt][nt][1]);
            if (row + 8 < M)
                *(__half2*)(g_h + (size_t)(row + 8) * WIDE + col) =
                    __floats2half2_rn(acc[mt][nt][2], acc[mt][nt][3]);
        }
    }

    // ---- epilogue 2: fused attention-coefficient partial dots ----
    const int head = (cb + wn) >> 6;                        // uniform per warp
    const float* a_s = as_all + rel * HC;
    const float* a_d = ad_all + rel * HC;
    float* als = g_als + (size_t)rel * NN * HEADS;
    float* ald = g_ald + (size_t)rel * NN * HEADS;
#pragma unroll
    for (int mt = 0; mt < 4; mt++) {
        float ps0 = 0.f, pd0 = 0.f, ps1 = 0.f, pd1 = 0.f;
#pragma unroll
        for (int nt = 0; nt < 4; nt++) {
            int col = cb + wn + nt * 8 + 2 * tig;
            float w0s = a_s[col], w1s = a_s[col + 1];
            float w0d = a_d[col], w1d = a_d[col + 1];
            ps0 += acc[mt][nt][0] * w0s + acc[mt][nt][1] * w1s;
            pd0 += acc[mt][nt][0] * w0d + acc[mt][nt][1] * w1d;
            ps1 += acc[mt][nt][2] * w0s + acc[mt][nt][3] * w1s;
            pd1 += acc[mt][nt][2] * w0d + acc[mt][nt][3] * w1d;
        }
        ps0 += __shfl_down_sync(0xffffffffu, ps0, 2);
        ps0 += __shfl_down_sync(0xffffffffu, ps0, 1);
        pd0 += __shfl_down_sync(0xffffffffu, pd0, 2);
        pd0 += __shfl_down_sync(0xffffffffu, pd0, 1);
        ps1 += __shfl_down_sync(0xffffffffu, ps1, 2);
        ps1 += __shfl_down_sync(0xffffffffu, ps1, 1);
        pd1 += __shfl_down_sync(0xffffffffu, pd1, 2);
        pd1 += __shfl_down_sync(0xffffffffu, pd1, 1);
        if (tig == 0) {
            int row = br + wm + mt * 16 + g;
            if (row < M) {
                atomicAdd(&als[row * 4 + head], ps0);
                atomicAdd(&ald[row * 4 + head], pd0);
            }
            if (row + 8 < M) {
                atomicAdd(&als[(row + 8) * 4 + head], ps1);
                atomicAdd(&ald[(row + 8) * 4 + head], pd1);
            }
        }
    }
}

// ---------------------------------------------------------------------------
// Zero attn-coefficient buffers (all relations; before each wide GEMM)
// ---------------------------------------------------------------------------
__global__ void zero_attn_kernel(int total) {
    int i = blockIdx.x * blockDim.x + threadIdx.x;
    if (i < total) { g_als[i] = 0.f; g_ald[i] = 0.f; }
}

// ---------------------------------------------------------------------------
// CSR-by-dst construction (rebuilt every call; stateless)
// ---------------------------------------------------------------------------
__global__ void csr_zero_kernel() {
    int i = blockIdx.x * blockDim.x + threadIdx.x;
    if (i < NREL * NN) g_cnt[i] = 0;
}

__global__ void csr_hist_kernel(const int* __restrict__ e0, const int* __restrict__ e1,
                                const int* __restrict__ e2, int E) {
    int idx = blockIdx.x * blockDim.x + threadIdx.x;
    if (idx >= NREL * E) return;
    int r = idx / E, e = idx - r * E;
    const int* ep = (r == 0) ? e0 : (r == 1) ? e1 : e2;
    atomicAdd(&g_cnt[r * NN + ep[E + e]], 1);
}

__global__ void csr_scan_kernel(int N) {
    int r = blockIdx.x;
    int t = threadIdx.x;
    __shared__ int sums[1024];
    int chunk = (N + blockDim.x - 1) / blockDim.x;
    int begin = t * chunk;
    int end = min(begin + chunk, N);
    int s = 0;
    for (int i = begin; i < end; i++) s += g_cnt[r * NN + i];
    sums[t] = s;
    __syncthreads();
    for (int d = 1; d < 1024; d <<= 1) {
        int v = (t >= d) ? sums[t - d] : 0;
        __syncthreads();
        sums[t] += v;
        __syncthreads();
    }
    int run = (t == 0) ? 0 : sums[t - 1];
    for (int i = begin; i < end; i++) {
        g_off[r * (NN + 1) + i] = run;
        g_cnt2[r * NN + i] = run;
        run += g_cnt[r * NN + i];
    }
    if (t == blockDim.x - 1) g_off[r * (NN + 1) + N] = run;
}

__global__ void csr_scatter_kernel(const int* __restrict__ e0, const int* __restrict__ e1,
                                   const int* __restrict__ e2, int E) {
    int idx = blockIdx.x * blockDim.x + threadIdx.x;
    if (idx >= NREL * E) return;
    int r = idx / E, e = idx - r * E;
    const int* ep = (r == 0) ? e0 : (r == 1) ? e1 : e2;
    int d = ep[E + e];
    int pos = atomicAdd(&g_cnt2[r * NN + d], 1);
    g_csr[(size_t)r * EE + pos] = ep[e];
}

// ---------------------------------------------------------------------------
// SINGLE-PASS fused softmax + aggregation, layer 1 (concat), ALL relations.
// One warp per dst; loops over 3 relations; register accumulation; one store.
// out[d] = Sum_b + sum_r (Σ_i e_i h_i) / (Σ_i e_i). No atomics, no RMW.
// Shift-free softmax (logits O(1); alpha invariant to reference max-shift).
// ---------------------------------------------------------------------------
__global__ void agg1_all_kernel(const float* __restrict__ b, int N) {
    int w = (blockIdx.x * blockDim.x + threadIdx.x) >> 5;
    int lane = threadIdx.x & 31;
    if (w >= N) return;
    const int d = w;
    const int head = lane >> 3;

    float4 a0, a1;
    {
        int c = lane * 8;
        a0.x = b[c + 0] + b[HC + c + 0] + b[2 * HC + c + 0];
        a0.y = b[c + 1] + b[HC + c + 1] + b[2 * HC + c + 1];
        a0.z = b[c + 2] + b[HC + c + 2] + b[2 * HC + c + 2];
        a0.w = b[c + 3] + b[HC + c + 3] + b[2 * HC + c + 3];
        a1.x = b[c + 4] + b[HC + c + 4] + b[2 * HC + c + 4];
        a1.y = b[c + 5] + b[HC + c + 5] + b[2 * HC + c + 5];
        a1.z = b[c + 6] + b[HC + c + 6] + b[2 * HC + c + 6];
        a1.w = b[c + 7] + b[HC + c + 7] + b[2 * HC + c + 7];
    }

#pragma unroll
    for (int rel = 0; rel < NREL; rel++) {
        const int* off = g_off + rel * (NN + 1);
        const int* csr = g_csr + (size_t)rel * EE;
        const float* als = g_als + (size_t)rel * NN * HEADS;
        const int base = off[d];
        const int deg = off[d + 1] - base;
        const float adh = g_ald[((size_t)rel * NN + d) * 4 + head];

        float D = 0.f;
        float4 n0 = make_float4(0.f, 0.f, 0.f, 0.f);
        float4 n1 = make_float4(0.f, 0.f, 0.f, 0.f);

        for (int i = 0; i < deg; i++) {
            int s = csr[base + i];
            float e = __expf(lrelu(als[(size_t)s * 4 + head] + adh));
            D += e;
            uint4 hv = *((const uint4*)(g_h + (size_t)s * WIDE + rel * HC) + lane);
            float2 f0 = __half22float2(*(__half2*)&hv.x);
            float2 f1 = __half22float2(*(__half2*)&hv.y);
            float2 f2 = __half22float2(*(__half2*)&hv.z);
            float2 f3 = __half22float2(*(__half2*)&hv.w);
            n0.x += e * f0.x; n0.y += e * f0.y;
            n0.z += e * f1.x; n0.w += e * f1.y;
            n1.x += e * f2.x; n1.y += e * f2.y;
            n1.z += e * f3.x; n1.w += e * f3.y;
        }
        if (rel > 0) {   // self-loop for 'spatial' and 'similar'
            float e = __expf(lrelu(als[(size_t)d * 4 + head] + adh));
            D += e;
            uint4 hv = *((const uint4*)(g_h + (size_t)d * WIDE + rel * HC) + lane);
            float2 f0 = __half22float2(*(__half2*)&hv.x);
            float2 f1 = __half22float2(*(__half2*)&hv.y);
            float2 f2 = __half22float2(*(__half2*)&hv.z);
            float2 f3 = __half22float2(*(__half2*)&hv.w);
            n0.x += e * f0.x; n0.y += e * f0.y;
            n0.z += e * f1.x; n0.w += e * f1.y;
            n1.x += e * f2.x; n1.y += e * f2.y;
            n1.z += e * f3.x; n1.w += e * f3.y;
        }
        float inv = 1.f / (D + 1e-16f);
        a0.x += inv * n0.x; a0.y += inv * n0.y;
        a0.z += inv * n0.z; a0.w += inv * n0.w;
        a1.x += inv * n1.x; a1.y += inv * n1.y;
        a1.z += inv * n1.z; a1.w += inv * n1.w;
    }

    float* op = g_out1 + (size_t)d * HC + lane * 8;
    *(float4*)op = a0;
    *(float4*)(op + 4) = a1;
}

// ---------------------------------------------------------------------------
// SINGLE-PASS fused softmax + aggregation, layer 2 (mean), ALL relations.
// One warp per dst; lane covers 2 of 64 channels; per-head numerators.
// ---------------------------------------------------------------------------
__global__ void agg2_all_kernel(const float* __restrict__ b, int N) {
    int w = (blockIdx.x * blockDim.x + threadIdx.x) >> 5;
    int lane = threadIdx.x & 31;
    if (w >= N) return;
    const int d = w;

    float2 acc;
    {
        int c = lane * 2;
        acc.x = b[c] + b[HID + c] + b[2 * HID + c];
        acc.y = b[c + 1] + b[HID + c + 1] + b[2 * HID + c + 1];
    }

#pragma unroll
    for (int rel = 0; rel < NREL; rel++) {
        const int* off = g_off + rel * (NN + 1);
        const int* csr = g_csr + (size_t)rel * EE;
        const float* als = g_als + (size_t)rel * NN * HEADS;
        const int base = off[d];
        const int deg = off[d + 1] - base;
        float4 ad4 = *(const float4*)(g_ald + ((size_t)rel * NN + d) * 4);

        float Dx = 0.f, Dy = 0.f, Dz = 0.f, Dw = 0.f;
        float2 m0 = make_float2(0.f, 0.f), m1 = make_float2(0.f, 0.f);
        float2 m2 = make_float2(0.f, 0.f), m3 = make_float2(0.f, 0.f);

        for (int i = 0; i < deg; i++) {
            int s = csr[base + i];
            float4 as4 = *(const float4*)(als + (size_t)s * 4);
            float e0 = __expf(lrelu(as4.x + ad4.x));
            float e1 = __expf(lrelu(as4.y + ad4.y));
            float e2 = __expf(lrelu(as4.z + ad4.z));
            float e3 = __expf(lrelu(as4.w + ad4.w));
            Dx += e0; Dy += e1; Dz += e2; Dw += e3;
            const __half* hrow = g_h + (size_t)s * WIDE + rel * HC;
            float2 f0 = __half22float2(*(const __half2*)(hrow + 0 * HID + lane * 2));
            float2 f1 = __half22float2(*(const __half2*)(hrow + 1 * HID + lane * 2));
            float2 f2 = __half22float2(*(const __half2*)(hrow + 2 * HID + lane * 2));
            float2 f3 = __half22float2(*(const __half2*)(hrow + 3 * HID + lane * 2));
            m0.x += e0 * f0.x; m0.y += e0 * f0.y;
            m1.x += e1 * f1.x; m1.y += e1 * f1.y;
            m2.x += e2 * f2.x; m2.y += e2 * f2.y;
            m3.x += e3 * f3.x; m3.y += e3 * f3.y;
        }
        if (rel > 0) {
            float4 as4 = *(const float4*)(als + (size_t)d * 4);
            float e0 = __expf(lrelu(as4.x + ad4.x));
            float e1 = __expf(lrelu(as4.y + ad4.y));
            float e2 = __expf(lrelu(as4.z + ad4.z));
            float e3 = __expf(lrelu(as4.w + ad4.w));
            Dx += e0; Dy += e1; Dz += e2; Dw += e3;
            const __half* hrow = g_h + (size_t)d * WIDE + rel * HC;
            float2 f0 = __half22float2(*(const __half2*)(hrow + 0 * HID + lane * 2));
            float2 f1 = __half22float2(*(const __half2*)(hrow + 1 * HID + lane * 2));
            float2 f2 = __half22float2(*(const __half2*)(hrow + 2 * HID + lane * 2));
            float2 f3 = __half22float2(*(const __half2*)(hrow + 3 * HID + lane * 2));
            m0.x += e0 * f0.x; m0.y += e0 * f0.y;
            m1.x += e1 * f1.x; m1.y += e1 * f1.y;
            m2.x += e2 * f2.x; m2.y += e2 * f2.y;
            m3.x += e3 * f3.x; m3.y += e3 * f3.y;
        }
        float i0 = 0.25f / (Dx + 1e-16f), i1 = 0.25f / (Dy + 1e-16f);
        float i2 = 0.25f / (Dz + 1e-16f), i3 = 0.25f / (Dw + 1e-16f);
        acc.x += i0 * m0.x + i1 * m1.x + i2 * m2.x + i3 * m3.x;
        acc.y += i0 * m0.y + i1 * m1.y + i2 * m2.y + i3 * m3.y;
    }

    *(float2*)(g_out2 + (size_t)d * HID + lane * 2) = acc;
}

// ---------------------------------------------------------------------------
// SIMT SGEMM (final linear layer): out = relu(g_out2) @ Wl + bl
// ---------------------------------------------------------------------------
template<int BM, int BN, int BK, int TM, int TN>
__global__ void __launch_bounds__((BM / TM) * (BN / TN))
final_gemm_kernel(const float* __restrict__ B, float* __restrict__ C,
                  const float* __restrict__ bias, int M, int N, int K) {
    constexpr int NT = (BM / TM) * (BN / TN);
    __shared__ float As[BK][BM + 4];
    __shared__ float Bs[BK][BN];
    const float* A = (const float*)g_out2;
    const int tid = threadIdx.x;
    const int block_row = blockIdx.y * BM;
    const int block_col = blockIdx.x * BN;
    const int tcol = tid % (BN / TN);
    const int trow = tid / (BN / TN);

    float acc[TM][TN];
#pragma unroll
    for (int i = 0; i < TM; i++)
#pragma unroll
        for (int j = 0; j < TN; j++) acc[i][j] = 0.f;

    for (int k0 = 0; k0 < K; k0 += BK) {
#pragma unroll
        for (int i = tid; i < BM * BK / 4; i += NT) {
            int r = i / (BK / 4), c4 = i % (BK / 4);
            int gr = block_row + r;
            float4 v = make_float4(0.f, 0.f, 0.f, 0.f);
            if (gr < M) v = *(const float4*)(A + (size_t)gr * K + k0 + c4 * 4);
            v.x = fmaxf(v.x, 0.f); v.y = fmaxf(v.y, 0.f);
            v.z = fmaxf(v.z, 0.f); v.w = fmaxf(v.w, 0.f);
            As[c4 * 4 + 0][r] = v.x; As[c4 * 4 + 1][r] = v.y;
            As[c4 * 4 + 2][r] = v.z; As[c4 * 4 + 3][r] = v.w;
        }
#pragma unroll
        for (int i = tid; i < BK * BN / 4; i += NT) {
            int r = i / (BN / 4), c4 = i % (BN / 4);
            *(float4*)&Bs[r][c4 * 4] =
                *(const float4*)(B + (size_t)(k0 + r) * N + block_col + c4 * 4);
        }
        __syncthreads();
#pragma unroll
        for (int kk = 0; kk < BK; kk++) {
            float ar[TM], br[TN];
#pragma unroll
            for (int i = 0; i < TM; i++) ar[i] = As[kk][trow * TM + i];
#pragma unroll
            for (int j = 0; j < TN; j++) br[j] = Bs[kk][tcol * TN + j];
#pragma unroll
            for (int i = 0; i < TM; i++)
#pragma unroll
                for (int j = 0; j < TN; j++) acc[i][j] += ar[i] * br[j];
        }
        __syncthreads();
    }
#pragma unroll
    for (int i = 0; i < TM; i++) {
        int gr = block_row + trow * TM + i;
        if (gr >= M) continue;
#pragma unroll
        for (int j = 0; j < TN; j += 4) {
            int gc = block_col + tcol * TN + j;
            float4 v = make_float4(acc[i][j] + bias[gc], acc[i][j + 1] + bias[gc + 1],
                                   acc[i][j + 2] + bias[gc + 2], acc[i][j + 3] + bias[gc + 3]);
            *(float4*)(C + (size_t)gr * N + gc) = v;
        }
    }
}

// ---------------------------------------------------------------------------
// Launcher: kernel launches ONLY (graph-capture safe)
// ---------------------------------------------------------------------------
extern "C" void kernel_launch(void* const* d_in, const int* in_sizes, int n_in,
                              void* d_out, int out_size) {
    const float* x   = (const float*)d_in[0];
    const int*   e0  = (const int*)d_in[1];
    const int*   e1  = (const int*)d_in[2];
    const int*   e2  = (const int*)d_in[3];
    const float* W1  = (const float*)d_in[4];
    const float* a1s = (const float*)d_in[5];
    const float* a1d = (const float*)d_in[6];
    const float* b1  = (const float*)d_in[7];
    const float* W2  = (const float*)d_in[8];
    const float* a2s = (const float*)d_in[9];
    const float* a2d = (const float*)d_in[10];
    const float* b2  = (const float*)d_in[11];
    const float* Wl  = (const float*)d_in[12];
    const float* bl  = (const float*)d_in[13];
    float* out = (float*)d_out;

    const int N = in_sizes[0] / IN_CH;
    const int E = in_sizes[1] / 2;

    // ---------------- CSR-by-dst build ----------------
    csr_zero_kernel<<<(NREL * NN + 255) / 256, 256>>>();
    csr_hist_kernel<<<(NREL * E + 255) / 256, 256>>>(e0, e1, e2, E);
    csr_scan_kernel<<<NREL, 1024>>>(N);
    csr_scatter_kernel<<<(NREL * E + 255) / 256, 256>>>(e0, e1, e2, E);

    const dim3 ggrid(WIDE / 128, (N + 127) / 128);   // 6 x 391
    const int agg_blocks = (N * 32 + 255) / 256;
    const int zero_blocks = (NREL * N * HEADS + 255) / 256;

    // ---------------- Layer 1 (concat) ----------------
    zero_attn_kernel<<<zero_blocks, 256>>>(NREL * N * HEADS);
    mma_gemm_wide_kernel<false, true, IN_CH><<<ggrid, 256>>>(x, W1, a1s, a1d, N);
    agg1_all_kernel<<<agg_blocks, 256>>>(b1, N);

    // ---------------- Layer 2 (mean over heads) ----------------
    zero_attn_kernel<<<zero_blocks, 256>>>(NREL * N * HEADS);
    mma_gemm_wide_kernel<true, false, HC><<<ggrid, 256>>>(nullptr, W2, a2s, a2d, N);
    agg2_all_kernel<<<agg_blocks, 256>>>(b2, N);

    // ---------------- Final linear ----------------
    {
        dim3 grid(1, (N + 127) / 128);
        final_gemm_kernel<128, 64, 16, 4, 8><<<grid, 256>>>(
            Wl, out, bl, N, OUT_CH, OUT_CH);
    }
}

// round 16
// speedup vs baseline: 2.5886x; 1.0106x over previous
#include <cuda_runtime.h>
#include <cuda_bf16.h>
#include <cuda_fp16.h>
#include <cstdint>

#define NN 50000
#define EE 800000
#define IN_CH 128
#define HID 64
#define HEADS 4
#define HC (HEADS * HID)   // 256
#define WIDE (3 * HC)      // 768
#define OUT_CH 64
#define NREL 3

// ---------------------------------------------------------------------------
// Scratch (device globals; no allocation allowed anywhere)
// g_h holds ALL 3 relation planes in fp16: 77 MB -> fits L2.
// ---------------------------------------------------------------------------
__device__ __align__(16) __half g_h[(size_t)NN * WIDE];
__device__ __align__(16) float g_out1[(size_t)NN * HC];
__device__ __align__(16) float g_out2[(size_t)NN * HID];
__device__ __align__(16) float g_als[(size_t)NREL * NN * HEADS];
__device__ __align__(16) float g_ald[(size_t)NREL * NN * HEADS];
__device__ int g_cnt[NREL * NN];
__device__ int g_cnt2[NREL * NN];   // scatter cursors (seeded by scan)
__device__ int g_off[NREL * (NN + 1)];
__device__ int g_csr[(size_t)NREL * EE];

__device__ __forceinline__ float lrelu(float x) { return fmaxf(x, 0.2f * x); }

__device__ __forceinline__ void bf16_split(float v, unsigned short& h, unsigned short& l) {
    __nv_bfloat16 hb = __float2bfloat16_rn(v);
    float r = v - __bfloat162float(hb);
    __nv_bfloat16 lb = __float2bfloat16_rn(r);
    h = __bfloat16_as_ushort(hb);
    l = __bfloat16_as_ushort(lb);
}
__device__ __forceinline__ unsigned pk2(unsigned short a, unsigned short b) {
    return (unsigned)a | ((unsigned)b << 16);
}

#define MMA_BF16(d, a0, a1, a2, a3, b0, b1)                                    \
    asm volatile(                                                              \
        "mma.sync.aligned.m16n8k16.row.col.f32.bf16.bf16.f32 "                 \
        "{%0,%1,%2,%3}, {%4,%5,%6,%7}, {%8,%9}, {%0,%1,%2,%3};"                \
        : "+f"(d[0]), "+f"(d[1]), "+f"(d[2]), "+f"(d[3])                       \
        : "r"(a0), "r"(a1), "r"(a2), "r"(a3), "r"(b0), "r"(b1))

// ---------------------------------------------------------------------------
// WIDE bf16x3 split-precision tensor-core GEMM, all 3 relations at once
// (BYTE-IDENTICAL to the round-10 passing build — do not perturb: it sits at
// the 128-reg launch_bounds cap and any change tips it into local memory).
//   g_h[M, 768] = fp16( op(A)[M, K] @ W[rel][K, 256] ),  rel = block_col/256
// Fused attention-coefficient epilogue.
// ---------------------------------------------------------------------------
template<bool RELU_A, bool A_FROM_PARAM, int K>
__global__ void __launch_bounds__(256, 2)
mma_gemm_wide_kernel(const float* __restrict__ Ap, const float* __restrict__ W,
                     const float* __restrict__ as_all, const float* __restrict__ ad_all,
                     int M) {
    constexpr int BKP = 40;
    __shared__ unsigned short sAhi[128][BKP], sAlo[128][BKP];
    __shared__ unsigned short sBhi[128][BKP], sBlo[128][BKP];

    const float* A = A_FROM_PARAM ? Ap : (const float*)g_out1;

    const int tid = threadIdx.x;
    const int br = blockIdx.y * 128;
    const int bc = blockIdx.x * 128;          // 0..640, step 128
    const int rel = bc >> 8;                  // 0..2
    const int cb = bc & 255;                  // 0 or 128 within the relation
    const float* B = W + (size_t)rel * K * HC + cb;
    const int lane = tid & 31, wid = tid >> 5;
    const int g = lane >> 2, tig = lane & 3;
    const int wm = (wid >> 2) * 64;
    const int wn = (wid & 3) * 32;

    float acc[4][4][4];
#pragma unroll
    for (int i = 0; i < 4; i++)
#pragma unroll
        for (int j = 0; j < 4; j++)
#pragma unroll
            for (int q = 0; q < 4; q++) acc[i][j][q] = 0.f;

    const int nB = tid & 127;
    const int kbB = (tid >> 7) * 4;

    for (int kt = 0; kt < K / 32; kt++) {
        const int k0 = kt * 32;
        if (kt) __syncthreads();

#pragma unroll
        for (int it = 0; it < 4; it++) {
            int idx = tid + it * 256;
            int r = idx >> 3;
            int c4 = (idx & 7) * 4;
            float4 v = make_float4(0.f, 0.f, 0.f, 0.f);
            if (br + r < M) v = *(const float4*)(A + (size_t)(br + r) * K + k0 + c4);
            if (RELU_A) {
                v.x = fmaxf(v.x, 0.f); v.y = fmaxf(v.y, 0.f);
                v.z = fmaxf(v.z, 0.f); v.w = fmaxf(v.w, 0.f);
            }
            unsigned short h0, h1, h2, h3, l0, l1, l2, l3;
            bf16_split(v.x, h0, l0); bf16_split(v.y, h1, l1);
            bf16_split(v.z, h2, l2); bf16_split(v.w, h3, l3);
            *(uint2*)&sAhi[r][c4] = make_uint2(pk2(h0, h1), pk2(h2, h3));
            *(uint2*)&sAlo[r][c4] = make_uint2(pk2(l0, l1), pk2(l2, l3));
        }
#pragma unroll
        for (int it = 0; it < 4; it++) {
            int ks = kbB + it * 8;
            float v0 = B[(size_t)(k0 + ks + 0) * HC + nB];
            float v1 = B[(size_t)(k0 + ks + 1) * HC + nB];
            float v2 = B[(size_t)(k0 + ks + 2) * HC + nB];
            float v3 = B[(size_t)(k0 + ks + 3) * HC + nB];
            unsigned short h0, h1, h2, h3, l0, l1, l2, l3;
            bf16_split(v0, h0, l0); bf16_split(v1, h1, l1);
            bf16_split(v2, h2, l2); bf16_split(v3, h3, l3);
            *(uint2*)&sBhi[nB][ks] = make_uint2(pk2(h0, h1), pk2(h2, h3));
            *(uint2*)&sBlo[nB][ks] = make_uint2(pk2(l0, l1), pk2(l2, l3));
        }
        __syncthreads();

#pragma unroll
        for (int ks = 0; ks < 2; ks++) {
            const int ko = ks * 16;
            unsigned a[4][4], bh[4][2], bx[4][2];
#pragma unroll
            for (int mt = 0; mt < 4; mt++) {
                int row = wm + mt * 16 + g;
                a[mt][0] = *(const unsigned*)&sAhi[row][ko + 2 * tig];
                a[mt][1] = *(const unsigned*)&sAhi[row + 8][ko + 2 * tig];
                a[mt][2] = *(const unsigned*)&sAhi[row][ko + 2 * tig + 8];
                a[mt][3] = *(const unsigned*)&sAhi[row + 8][ko + 2 * tig + 8];
            }
#pragma unroll
            for (int nt = 0; nt < 4; nt++) {
                int col = wn + nt * 8 + g;
                bh[nt][0] = *(const unsigned*)&sBhi[col][ko + 2 * tig];
                bh[nt][1] = *(const unsigned*)&sBhi[col][ko + 2 * tig + 8];
            }
#pragma unroll
            for (int mt = 0; mt < 4; mt++)
#pragma unroll
                for (int nt = 0; nt < 4; nt++)
                    MMA_BF16(acc[mt][nt], a[mt][0], a[mt][1], a[mt][2], a[mt][3],
                             bh[nt][0], bh[nt][1]);
#pragma unroll
            for (int nt = 0; nt < 4; nt++) {
                int col = wn + nt * 8 + g;
                bx[nt][0] = *(const unsigned*)&sBlo[col][ko + 2 * tig];
                bx[nt][1] = *(const unsigned*)&sBlo[col][ko + 2 * tig + 8];
            }
#pragma unroll
            for (int mt = 0; mt < 4; mt++)
#pragma unroll
                for (int nt = 0; nt < 4; nt++)
                    MMA_BF16(acc[mt][nt], a[mt][0], a[mt][1], a[mt][2], a[mt][3],
                             bx[nt][0], bx[nt][1]);
#pragma unroll
            for (int mt = 0; mt < 4; mt++) {
                int row = wm + mt * 16 + g;
                a[mt][0] = *(const unsigned*)&sAlo[row][ko + 2 * tig];
                a[mt][1] = *(const unsigned*)&sAlo[row + 8][ko + 2 * tig];
                a[mt][2] = *(const unsigned*)&sAlo[row][ko + 2 * tig + 8];
                a[mt][3] = *(const unsigned*)&sAlo[row + 8][ko + 2 * tig + 8];
            }
#pragma unroll
            for (int mt = 0; mt < 4; mt++)
#pragma unroll
                for (int nt = 0; nt < 4; nt++)
                    MMA_BF16(acc[mt][nt], a[mt][0], a[mt][1], a[mt][2], a[mt][3],
                             bh[nt][0], bh[nt][1]);
        }
    }

    // ---- epilogue 1: fp32 acc -> fp16 g_h (wide layout) ----
#pragma unroll
    for (int mt = 0; mt < 4; mt++) {
#pragma unroll
        for (int nt = 0; nt < 4; nt++) {
            int row = br + wm + mt * 16 + g;
            int col = bc + wn + nt * 8 + 2 * tig;
            if (row < M)
                *(__half2*)(g_h + (size_t)row * WIDE + col) =
                    __floats2half2_rn(acc[mt][nt][0], acc[mt][nt][1]);
            if (row + 8 < M)
                *(__half2*)(g_h + (size_t)(row + 8) * WIDE + col) =
                    __floats2half2_rn(acc[mt][nt][2], acc[mt][nt][3]);
        }
    }

    // ---- epilogue 2: fused attention-coefficient partial dots ----
    const int head = (cb + wn) >> 6;                        // uniform per warp
    const float* a_s = as_all + rel * HC;
    const float* a_d = ad_all + rel * HC;
    float* als = g_als + (size_t)rel * NN * HEADS;
    float* ald = g_ald + (size_t)rel * NN * HEADS;
#pragma unroll
    for (int mt = 0; mt < 4; mt++) {
        float ps0 = 0.f, pd0 = 0.f, ps1 = 0.f, pd1 = 0.f;
#pragma unroll
        for (int nt = 0; nt < 4; nt++) {
            int col = cb + wn + nt * 8 + 2 * tig;
            float w0s = a_s[col], w1s = a_s[col + 1];
            float w0d = a_d[col], w1d = a_d[col + 1];
            ps0 += acc[mt][nt][0] * w0s + acc[mt][nt][1] * w1s;
            pd0 += acc[mt][nt][0] * w0d + acc[mt][nt][1] * w1d;
            ps1 += acc[mt][nt][2] * w0s + acc[mt][nt][3] * w1s;
            pd1 += acc[mt][nt][2] * w0d + acc[mt][nt][3] * w1d;
        }
        ps0 += __shfl_down_sync(0xffffffffu, ps0, 2);
        ps0 += __shfl_down_sync(0xffffffffu, ps0, 1);
        pd0 += __shfl_down_sync(0xffffffffu, pd0, 2);
        pd0 += __shfl_down_sync(0xffffffffu, pd0, 1);
        ps1 += __shfl_down_sync(0xffffffffu, ps1, 2);
        ps1 += __shfl_down_sync(0xffffffffu, ps1, 1);
        pd1 += __shfl_down_sync(0xffffffffu, pd1, 2);
        pd1 += __shfl_down_sync(0xffffffffu, pd1, 1);
        if (tig == 0) {
            int row = br + wm + mt * 16 + g;
            if (row < M) {
                atomicAdd(&als[row * 4 + head], ps0);
                atomicAdd(&ald[row * 4 + head], pd0);
            }
            if (row + 8 < M) {
                atomicAdd(&als[(row + 8) * 4 + head], ps1);
                atomicAdd(&ald[(row + 8) * 4 + head], pd1);
            }
        }
    }
}

// ---------------------------------------------------------------------------
// Zero attn-coefficient buffers (used before the layer-2 GEMM)
// ---------------------------------------------------------------------------
__global__ void zero_attn_kernel(int total) {
    int i = blockIdx.x * blockDim.x + threadIdx.x;
    if (i < total) { g_als[i] = 0.f; g_ald[i] = 0.f; }
}

// ---------------------------------------------------------------------------
// CSR-by-dst construction (rebuilt every call; stateless).
// csr_zero also zeroes als/ald for layer 1 (one launch saved).
// ---------------------------------------------------------------------------
__global__ void csr_zero_kernel() {
    int i = blockIdx.x * blockDim.x + threadIdx.x;
    if (i < NREL * NN) g_cnt[i] = 0;
    if (i < NREL * NN * HEADS) { g_als[i] = 0.f; g_ald[i] = 0.f; }
}

__global__ void csr_hist_kernel(const int* __restrict__ e0, const int* __restrict__ e1,
                                const int* __restrict__ e2, int E) {
    int idx = blockIdx.x * blockDim.x + threadIdx.x;
    if (idx >= NREL * E) return;
    int r = idx / E, e = idx - r * E;
    const int* ep = (r == 0) ? e0 : (r == 1) ? e1 : e2;
    atomicAdd(&g_cnt[r * NN + ep[E + e]], 1);
}

__global__ void csr_scan_kernel(int N) {
    int r = blockIdx.x;
    int t = threadIdx.x;
    __shared__ int sums[1024];
    int chunk = (N + blockDim.x - 1) / blockDim.x;
    int begin = t * chunk;
    int end = min(begin + chunk, N);
    int s = 0;
    for (int i = begin; i < end; i++) s += g_cnt[r * NN + i];
    sums[t] = s;
    __syncthreads();
    for (int d = 1; d < 1024; d <<= 1) {
        int v = (t >= d) ? sums[t - d] : 0;
        __syncthreads();
        sums[t] += v;
        __syncthreads();
    }
    int run = (t == 0) ? 0 : sums[t - 1];
    for (int i = begin; i < end; i++) {
        g_off[r * (NN + 1) + i] = run;
        g_cnt2[r * NN + i] = run;
        run += g_cnt[r * NN + i];
    }
    if (t == blockDim.x - 1) g_off[r * (NN + 1) + N] = run;
}

__global__ void csr_scatter_kernel(const int* __restrict__ e0, const int* __restrict__ e1,
                                   const int* __restrict__ e2, int E) {
    int idx = blockIdx.x * blockDim.x + threadIdx.x;
    if (idx >= NREL * E) return;
    int r = idx / E, e = idx - r * E;
    const int* ep = (r == 0) ? e0 : (r == 1) ? e1 : e2;
    int d = ep[E + e];
    int pos = atomicAdd(&g_cnt2[r * NN + d], 1);
    g_csr[(size_t)r * EE + pos] = ep[e];
}

// ---------------------------------------------------------------------------
// SINGLE-PASS fused softmax + aggregation, layer 1 (concat), ALL relations.
// One warp per dst; SOFTWARE-PIPELINED: (src, als, h-row) for edge i+1 are
// fetched while edge i's FMAs run -> 2 independent gathers in flight/warp.
// Register-only double buffer (scalars + uint4); arithmetic order unchanged.
// Shift-free softmax (logits O(1); alpha invariant to reference max-shift).
// ---------------------------------------------------------------------------
__global__ void agg1_all_kernel(const float* __restrict__ b, int N) {
    int w = (blockIdx.x * blockDim.x + threadIdx.x) >> 5;
    int lane = threadIdx.x & 31;
    if (w >= N) return;
    const int d = w;
    const int head = lane >> 3;

    float4 a0, a1;
    {
        int c = lane * 8;
        a0.x = b[c + 0] + b[HC + c + 0] + b[2 * HC + c + 0];
        a0.y = b[c + 1] + b[HC + c + 1] + b[2 * HC + c + 1];
        a0.z = b[c + 2] + b[HC + c + 2] + b[2 * HC + c + 2];
        a0.w = b[c + 3] + b[HC + c + 3] + b[2 * HC + c + 3];
        a1.x = b[c + 4] + b[HC + c + 4] + b[2 * HC + c + 4];
        a1.y = b[c + 5] + b[HC + c + 5] + b[2 * HC + c + 5];
        a1.z = b[c + 6] + b[HC + c + 6] + b[2 * HC + c + 6];
        a1.w = b[c + 7] + b[HC + c + 7] + b[2 * HC + c + 7];
    }

#pragma unroll
    for (int rel = 0; rel < NREL; rel++) {
        const int* off = g_off + rel * (NN + 1);
        const int* csr = g_csr + (size_t)rel * EE;
        const float* als = g_als + (size_t)rel * NN * HEADS;
        const int base = off[d];
        const int deg = off[d + 1] - base;
        const float adh = g_ald[((size_t)rel * NN + d) * 4 + head];

        float D = 0.f;
        float4 n0 = make_float4(0.f, 0.f, 0.f, 0.f);
        float4 n1 = make_float4(0.f, 0.f, 0.f, 0.f);

        // pipeline prologue: fetch edge 0
        float a_cur = 0.f;
        uint4 hv_cur = make_uint4(0u, 0u, 0u, 0u);
        if (deg > 0) {
            int s0 = csr[base];
            a_cur = als[(size_t)s0 * 4 + head];
            hv_cur = *((const uint4*)(g_h + (size_t)s0 * WIDE + rel * HC) + lane);
        }
        for (int i = 0; i < deg; i++) {
            // prefetch edge i+1 (overlaps the FMAs below)
            float a_nxt = 0.f;
            uint4 hv_nxt = make_uint4(0u, 0u, 0u, 0u);
            if (i + 1 < deg) {
                int sn = csr[base + i + 1];
                a_nxt = als[(size_t)sn * 4 + head];
                hv_nxt = *((const uint4*)(g_h + (size_t)sn * WIDE + rel * HC) + lane);
            }
            float e = __expf(lrelu(a_cur + adh));
            D += e;
            float2 f0 = __half22float2(*(__half2*)&hv_cur.x);
            float2 f1 = __half22float2(*(__half2*)&hv_cur.y);
            float2 f2 = __half22float2(*(__half2*)&hv_cur.z);
            float2 f3 = __half22float2(*(__half2*)&hv_cur.w);
            n0.x += e * f0.x; n0.y += e * f0.y;
            n0.z += e * f1.x; n0.w += e * f1.y;
            n1.x += e * f2.x; n1.y += e * f2.y;
            n1.z += e * f3.x; n1.w += e * f3.y;
            a_cur = a_nxt;
            hv_cur = hv_nxt;
        }
        if (rel > 0) {   // self-loop for 'spatial' and 'similar'
            float e = __expf(lrelu(als[(size_t)d * 4 + head] + adh));
            D += e;
            uint4 hv = *((const uint4*)(g_h + (size_t)d * WIDE + rel * HC) + lane);
            float2 f0 = __half22float2(*(__half2*)&hv.x);
            float2 f1 = __half22float2(*(__half2*)&hv.y);
            float2 f2 = __half22float2(*(__half2*)&hv.z);
            float2 f3 = __half22float2(*(__half2*)&hv.w);
            n0.x += e * f0.x; n0.y += e * f0.y;
            n0.z += e * f1.x; n0.w += e * f1.y;
            n1.x += e * f2.x; n1.y += e * f2.y;
            n1.z += e * f3.x; n1.w += e * f3.y;
        }
        float inv = 1.f / (D + 1e-16f);
        a0.x += inv * n0.x; a0.y += inv * n0.y;
        a0.z += inv * n0.z; a0.w += inv * n0.w;
        a1.x += inv * n1.x; a1.y += inv * n1.y;
        a1.z += inv * n1.z; a1.w += inv * n1.w;
    }

    float* op = g_out1 + (size_t)d * HC + lane * 8;
    *(float4*)op = a0;
    *(float4*)(op + 4) = a1;
}

// ---------------------------------------------------------------------------
// SINGLE-PASS fused softmax + aggregation, layer 2 (mean), ALL relations.
// Software-pipelined like agg1 (als float4 + 4 half2 words double-buffered).
// ---------------------------------------------------------------------------
__global__ void agg2_all_kernel(const float* __restrict__ b, int N) {
    int w = (blockIdx.x * blockDim.x + threadIdx.x) >> 5;
    int lane = threadIdx.x & 31;
    if (w >= N) return;
    const int d = w;

    float2 acc;
    {
        int c = lane * 2;
        acc.x = b[c] + b[HID + c] + b[2 * HID + c];
        acc.y = b[c + 1] + b[HID + c + 1] + b[2 * HID + c + 1];
    }

#pragma unroll
    for (int rel = 0; rel < NREL; rel++) {
        const int* off = g_off + rel * (NN + 1);
        const int* csr = g_csr + (size_t)rel * EE;
        const float* als = g_als + (size_t)rel * NN * HEADS;
        const int base = off[d];
        const int deg = off[d + 1] - base;
        float4 ad4 = *(const float4*)(g_ald + ((size_t)rel * NN + d) * 4);

        float Dx = 0.f, Dy = 0.f, Dz = 0.f, Dw = 0.f;
        float2 m0 = make_float2(0.f, 0.f), m1 = make_float2(0.f, 0.f);
        float2 m2 = make_float2(0.f, 0.f), m3 = make_float2(0.f, 0.f);

        // pipeline prologue
        float4 as_cur = make_float4(0.f, 0.f, 0.f, 0.f);
        unsigned h0c = 0u, h1c = 0u, h2c = 0u, h3c = 0u;
        if (deg > 0) {
            int s0 = csr[base];
            as_cur = *(const float4*)(als + (size_t)s0 * 4);
            const __half* hrow = g_h + (size_t)s0 * WIDE + rel * HC;
            h0c = *(const unsigned*)(hrow + 0 * HID + lane * 2);
            h1c = *(const unsigned*)(hrow + 1 * HID + lane * 2);
            h2c = *(const unsigned*)(hrow + 2 * HID + lane * 2);
            h3c = *(const unsigned*)(hrow + 3 * HID + lane * 2);
        }
        for (int i = 0; i < deg; i++) {
            float4 as_nxt = make_float4(0.f, 0.f, 0.f, 0.f);
            unsigned h0n = 0u, h1n = 0u, h2n = 0u, h3n = 0u;
            if (i + 1 < deg) {
                int sn = csr[base + i + 1];
                as_nxt = *(const float4*)(als + (size_t)sn * 4);
                const __half* hrow = g_h + (size_t)sn * WIDE + rel * HC;
                h0n = *(const unsigned*)(hrow + 0 * HID + lane * 2);
                h1n = *(const unsigned*)(hrow + 1 * HID + lane * 2);
                h2n = *(const unsigned*)(hrow + 2 * HID + lane * 2);
                h3n = *(const unsigned*)(hrow + 3 * HID + lane * 2);
            }
            float e0 = __expf(lrelu(as_cur.x + ad4.x));
            float e1 = __expf(lrelu(as_cur.y + ad4.y));
            float e2 = __expf(lrelu(as_cur.z + ad4.z));
            float e3 = __expf(lrelu(as_cur.w + ad4.w));
            Dx += e0; Dy += e1; Dz += e2; Dw += e3;
            float2 f0 = __half22float2(*(__half2*)&h0c);
            float2 f1 = __half22float2(*(__half2*)&h1c);
            float2 f2 = __half22float2(*(__half2*)&h2c);
            float2 f3 = __half22float2(*(__half2*)&h3c);
            m0.x += e0 * f0.x; m0.y += e0 * f0.y;
            m1.x += e1 * f1.x; m1.y += e1 * f1.y;
            m2.x += e2 * f2.x; m2.y += e2 * f2.y;
            m3.x += e3 * f3.x; m3.y += e3 * f3.y;
            as_cur = as_nxt;
            h0c = h0n; h1c = h1n; h2c = h2n; h3c = h3n;
        }
        if (rel > 0) {
            float4 as4 = *(const float4*)(als + (size_t)d * 4);
            float e0 = __expf(lrelu(as4.x + ad4.x));
            float e1 = __expf(lrelu(as4.y + ad4.y));
            float e2 = __expf(lrelu(as4.z + ad4.z));
            float e3 = __expf(lrelu(as4.w + ad4.w));
            Dx += e0; Dy += e1; Dz += e2; Dw += e3;
            const __half* hrow = g_h + (size_t)d * WIDE + rel * HC;
            float2 f0 = __half22float2(*(const __half2*)(hrow + 0 * HID + lane * 2));
            float2 f1 = __half22float2(*(const __half2*)(hrow + 1 * HID + lane * 2));
            float2 f2 = __half22float2(*(const __half2*)(hrow + 2 * HID + lane * 2));
            float2 f3 = __half22float2(*(const __half2*)(hrow + 3 * HID + lane * 2));
            m0.x += e0 * f0.x; m0.y += e0 * f0.y;
            m1.x += e1 * f1.x; m1.y += e1 * f1.y;
            m2.x += e2 * f2.x; m2.y += e2 * f2.y;
            m3.x += e3 * f3.x; m3.y += e3 * f3.y;
        }
        float i0 = 0.25f / (Dx + 1e-16f), i1 = 0.25f / (Dy + 1e-16f);
        float i2 = 0.25f / (Dz + 1e-16f), i3 = 0.25f / (Dw + 1e-16f);
        acc.x += i0 * m0.x + i1 * m1.x + i2 * m2.x + i3 * m3.x;
        acc.y += i0 * m0.y + i1 * m1.y + i2 * m2.y + i3 * m3.y;
    }

    *(float2*)(g_out2 + (size_t)d * HID + lane * 2) = acc;
}

// ---------------------------------------------------------------------------
// SIMT SGEMM (final linear layer): out = relu(g_out2) @ Wl + bl
// ---------------------------------------------------------------------------
template<int BM, int BN, int BK, int TM, int TN>
__global__ void __launch_bounds__((BM / TM) * (BN / TN))
final_gemm_kernel(const float* __restrict__ B, float* __restrict__ C,
                  const float* __restrict__ bias, int M, int N, int K) {
    constexpr int NT = (BM / TM) * (BN / TN);
    __shared__ float As[BK][BM + 4];
    __shared__ float Bs[BK][BN];
    const float* A = (const float*)g_out2;
    const int tid = threadIdx.x;
    const int block_row = blockIdx.y * BM;
    const int block_col = blockIdx.x * BN;
    const int tcol = tid % (BN / TN);
    const int trow = tid / (BN / TN);

    float acc[TM][TN];
#pragma unroll
    for (int i = 0; i < TM; i++)
#pragma unroll
        for (int j = 0; j < TN; j++) acc[i][j] = 0.f;

    for (int k0 = 0; k0 < K; k0 += BK) {
#pragma unroll
        for (int i = tid; i < BM * BK / 4; i += NT) {
            int r = i / (BK / 4), c4 = i % (BK / 4);
            int gr = block_row + r;
            float4 v = make_float4(0.f, 0.f, 0.f, 0.f);
            if (gr < M) v = *(const float4*)(A + (size_t)gr * K + k0 + c4 * 4);
            v.x = fmaxf(v.x, 0.f); v.y = fmaxf(v.y, 0.f);
            v.z = fmaxf(v.z, 0.f); v.w = fmaxf(v.w, 0.f);
            As[c4 * 4 + 0][r] = v.x; As[c4 * 4 + 1][r] = v.y;
            As[c4 * 4 + 2][r] = v.z; As[c4 * 4 + 3][r] = v.w;
        }
#pragma unroll
        for (int i = tid; i < BK * BN / 4; i += NT) {
            int r = i / (BN / 4), c4 = i % (BN / 4);
            *(float4*)&Bs[r][c4 * 4] =
                *(const float4*)(B + (size_t)(k0 + r) * N + block_col + c4 * 4);
        }
        __syncthreads();
#pragma unroll
        for (int kk = 0; kk < BK; kk++) {
            float ar[TM], br[TN];
#pragma unroll
            for (int i = 0; i < TM; i++) ar[i] = As[kk][trow * TM + i];
#pragma unroll
            for (int j = 0; j < TN; j++) br[j] = Bs[kk][tcol * TN + j];
#pragma unroll
            for (int i = 0; i < TM; i++)
#pragma unroll
                for (int j = 0; j < TN; j++) acc[i][j] += ar[i] * br[j];
        }
        __syncthreads();
    }
#pragma unroll
    for (int i = 0; i < TM; i++) {
        int gr = block_row + trow * TM + i;
        if (gr >= M) continue;
#pragma unroll
        for (int j = 0; j < TN; j += 4) {
            int gc = block_col + tcol * TN + j;
            float4 v = make_float4(acc[i][j] + bias[gc], acc[i][j + 1] + bias[gc + 1],
                                   acc[i][j + 2] + bias[gc + 2], acc[i][j + 3] + bias[gc + 3]);
            *(float4*)(C + (size_t)gr * N + gc) = v;
        }
    }
}

// ---------------------------------------------------------------------------
// Launcher: kernel launches ONLY (graph-capture safe)
// ---------------------------------------------------------------------------
extern "C" void kernel_launch(void* const* d_in, const int* in_sizes, int n_in,
                              void* d_out, int out_size) {
    const float* x   = (const float*)d_in[0];
    const int*   e0  = (const int*)d_in[1];
    const int*   e1  = (const int*)d_in[2];
    const int*   e2  = (const int*)d_in[3];
    const float* W1  = (const float*)d_in[4];
    const float* a1s = (const float*)d_in[5];
    const float* a1d = (const float*)d_in[6];
    const float* b1  = (const float*)d_in[7];
    const float* W2  = (const float*)d_in[8];
    const float* a2s = (const float*)d_in[9];
    const float* a2d = (const float*)d_in[10];
    const float* b2  = (const float*)d_in[11];
    const float* Wl  = (const float*)d_in[12];
    const float* bl  = (const float*)d_in[13];
    float* out = (float*)d_out;

    const int N = in_sizes[0] / IN_CH;
    const int E = in_sizes[1] / 2;

    // ---------------- CSR-by-dst build (also zeroes layer-1 als/ald) -------
    csr_zero_kernel<<<(NREL * NN * HEADS + 255) / 256, 256>>>();
    csr_hist_kernel<<<(NREL * E + 255) / 256, 256>>>(e0, e1, e2, E);
    csr_scan_kernel<<<NREL, 1024>>>(N);
    csr_scatter_kernel<<<(NREL * E + 255) / 256, 256>>>(e0, e1, e2, E);

    const dim3 ggrid(WIDE / 128, (N + 127) / 128);   // 6 x 391
    const int agg_blocks = (N * 32 + 255) / 256;
    const int zero_blocks = (NREL * N * HEADS + 255) / 256;

    // ---------------- Layer 1 (concat) ----------------
    mma_gemm_wide_kernel<false, true, IN_CH><<<ggrid, 256>>>(x, W1, a1s, a1d, N);
    agg1_all_kernel<<<agg_blocks, 256>>>(b1, N);

    // ---------------- Layer 2 (mean over heads) ----------------
    zero_attn_kernel<<<zero_blocks, 256>>>(NREL * N * HEADS);
    mma_gemm_wide_kernel<true, false, HC><<<ggrid, 256>>>(nullptr, W2, a2s, a2d, N);
    agg2_all_kernel<<<agg_blocks, 256>>>(b2, N);

    // ---------------- Final linear ----------------
    {
        dim3 grid(1, (N + 127) / 128);
        final_gemm_kernel<128, 64, 16, 4, 8><<<grid, 256>>>(
            Wl, out, bl, N, OUT_CH, OUT_CH);
    }
}

// round 17
// speedup vs baseline: 3.0122x; 1.1636x over previous
#include <cuda_runtime.h>
#include <cuda_bf16.h>
#include <cuda_fp16.h>
#include <cstdint>

#define NN 50000
#define EE 800000
#define IN_CH 128
#define HID 64
#define HEADS 4
#define HC (HEADS * HID)   // 256
#define WIDE (3 * HC)      // 768
#define OUT_CH 64
#define NREL 3

// ---------------------------------------------------------------------------
// Scratch (device globals; no allocation allowed anywhere)
// g_h holds ALL 3 relation planes in fp16: 77 MB -> fits L2.
// ---------------------------------------------------------------------------
__device__ __align__(16) __half g_h[(size_t)NN * WIDE];
__device__ __align__(16) float g_out1[(size_t)NN * HC];
__device__ __align__(16) float g_out2[(size_t)NN * HID];
__device__ __align__(16) float g_als[(size_t)NREL * NN * HEADS];
__device__ __align__(16) float g_ald[(size_t)NREL * NN * HEADS];
__device__ int g_cnt[NREL * NN];
__device__ int g_cnt2[NREL * NN];   // scatter cursors (seeded by scan)
__device__ int g_off[NREL * (NN + 1)];
__device__ int g_csr[(size_t)NREL * EE];

__device__ __forceinline__ float lrelu(float x) { return fmaxf(x, 0.2f * x); }

__device__ __forceinline__ unsigned pk2(unsigned short a, unsigned short b) {
    return (unsigned)a | ((unsigned)b << 16);
}

// fp16 mma: same fragment layout as bf16 m16n8k16 (a:4x.b32, b:2x.b32, d:4xf32)
#define MMA_F16(d, a0, a1, a2, a3, b0, b1)                                     \
    asm volatile(                                                              \
        "mma.sync.aligned.m16n8k16.row.col.f32.f16.f16.f32 "                   \
        "{%0,%1,%2,%3}, {%4,%5,%6,%7}, {%8,%9}, {%0,%1,%2,%3};"                \
        : "+f"(d[0]), "+f"(d[1]), "+f"(d[2]), "+f"(d[3])                       \
        : "r"(a0), "r"(a1), "r"(a2), "r"(a3), "r"(b0), "r"(b1))

// ---------------------------------------------------------------------------
// WIDE single-pass fp16 tensor-core GEMM, all 3 relations at once:
//   g_h[M, 768] = fp16( op(A)[M, K] @ W[rel][K, 256] ),  rel = block_col/256
// fp16 operands (~4e-4 RMS per element, attenuated ~3x by the downstream
// softmax aggregation -> final rel_err ~2e-4, well under the 1e-3 gate).
// Strictly lighter than the bf16x3 build: 2 smem arrays, 16 MMAs/k16-step,
// scalar register-only conversions (no address-taken locals -> no stack).
// Fused attention-coefficient epilogue (fp32 pre-rounding, atomic partials).
// ---------------------------------------------------------------------------
template<bool RELU_A, bool A_FROM_PARAM, int K>
__global__ void __launch_bounds__(256, 2)
mma_gemm_wide_kernel(const float* __restrict__ Ap, const float* __restrict__ W,
                     const float* __restrict__ as_all, const float* __restrict__ ad_all,
                     int M) {
    constexpr int BKP = 40;
    __shared__ unsigned short sA[128][BKP], sB[128][BKP];   // fp16 bit patterns

    const float* A = A_FROM_PARAM ? Ap : (const float*)g_out1;

    const int tid = threadIdx.x;
    const int br = blockIdx.y * 128;
    const int bc = blockIdx.x * 128;          // 0..640, step 128
    const int rel = bc >> 8;                  // 0..2
    const int cb = bc & 255;                  // 0 or 128 within the relation
    const float* B = W + (size_t)rel * K * HC + cb;
    const int lane = tid & 31, wid = tid >> 5;
    const int g = lane >> 2, tig = lane & 3;
    const int wm = (wid >> 2) * 64;
    const int wn = (wid & 3) * 32;

    float acc[4][4][4];
#pragma unroll
    for (int i = 0; i < 4; i++)
#pragma unroll
        for (int j = 0; j < 4; j++)
#pragma unroll
            for (int q = 0; q < 4; q++) acc[i][j][q] = 0.f;

    const int nB = tid & 127;
    const int kbB = (tid >> 7) * 4;

    for (int kt = 0; kt < K / 32; kt++) {
        const int k0 = kt * 32;
        if (kt) __syncthreads();

        // ---- A fill: fp32 -> fp16 (scalar converts, register-only) ----
#pragma unroll
        for (int it = 0; it < 4; it++) {
            int idx = tid + it * 256;
            int r = idx >> 3;
            int c4 = (idx & 7) * 4;
            float4 v = make_float4(0.f, 0.f, 0.f, 0.f);
            if (br + r < M) v = *(const float4*)(A + (size_t)(br + r) * K + k0 + c4);
            if (RELU_A) {
                v.x = fmaxf(v.x, 0.f); v.y = fmaxf(v.y, 0.f);
                v.z = fmaxf(v.z, 0.f); v.w = fmaxf(v.w, 0.f);
            }
            unsigned short h0 = __half_as_ushort(__float2half_rn(v.x));
            unsigned short h1 = __half_as_ushort(__float2half_rn(v.y));
            unsigned short h2 = __half_as_ushort(__float2half_rn(v.z));
            unsigned short h3 = __half_as_ushort(__float2half_rn(v.w));
            *(uint2*)&sA[r][c4] = make_uint2(pk2(h0, h1), pk2(h2, h3));
        }
        // ---- B fill: transposed gather fp32 -> fp16 ----
#pragma unroll
        for (int it = 0; it < 4; it++) {
            int ks = kbB + it * 8;
            float v0 = B[(size_t)(k0 + ks + 0) * HC + nB];
            float v1 = B[(size_t)(k0 + ks + 1) * HC + nB];
            float v2 = B[(size_t)(k0 + ks + 2) * HC + nB];
            float v3 = B[(size_t)(k0 + ks + 3) * HC + nB];
            unsigned short h0 = __half_as_ushort(__float2half_rn(v0));
            unsigned short h1 = __half_as_ushort(__float2half_rn(v1));
            unsigned short h2 = __half_as_ushort(__float2half_rn(v2));
            unsigned short h3 = __half_as_ushort(__float2half_rn(v3));
            *(uint2*)&sB[nB][ks] = make_uint2(pk2(h0, h1), pk2(h2, h3));
        }
        __syncthreads();

#pragma unroll
        for (int ks = 0; ks < 2; ks++) {
            const int ko = ks * 16;
            unsigned a[4][4], b[4][2];
#pragma unroll
            for (int mt = 0; mt < 4; mt++) {
                int row = wm + mt * 16 + g;
                a[mt][0] = *(const unsigned*)&sA[row][ko + 2 * tig];
                a[mt][1] = *(const unsigned*)&sA[row + 8][ko + 2 * tig];
                a[mt][2] = *(const unsigned*)&sA[row][ko + 2 * tig + 8];
                a[mt][3] = *(const unsigned*)&sA[row + 8][ko + 2 * tig + 8];
            }
#pragma unroll
            for (int nt = 0; nt < 4; nt++) {
                int col = wn + nt * 8 + g;
                b[nt][0] = *(const unsigned*)&sB[col][ko + 2 * tig];
                b[nt][1] = *(const unsigned*)&sB[col][ko + 2 * tig + 8];
            }
#pragma unroll
            for (int mt = 0; mt < 4; mt++)
#pragma unroll
                for (int nt = 0; nt < 4; nt++)
                    MMA_F16(acc[mt][nt], a[mt][0], a[mt][1], a[mt][2], a[mt][3],
                            b[nt][0], b[nt][1]);
        }
    }

    // ---- epilogue 1: fp32 acc -> fp16 g_h (wide layout) ----
#pragma unroll
    for (int mt = 0; mt < 4; mt++) {
#pragma unroll
        for (int nt = 0; nt < 4; nt++) {
            int row = br + wm + mt * 16 + g;
            int col = bc + wn + nt * 8 + 2 * tig;
            if (row < M)
                *(__half2*)(g_h + (size_t)row * WIDE + col) =
                    __floats2half2_rn(acc[mt][nt][0], acc[mt][nt][1]);
            if (row + 8 < M)
                *(__half2*)(g_h + (size_t)(row + 8) * WIDE + col) =
                    __floats2half2_rn(acc[mt][nt][2], acc[mt][nt][3]);
        }
    }

    // ---- epilogue 2: fused attention-coefficient partial dots ----
    const int head = (cb + wn) >> 6;                        // uniform per warp
    const float* a_s = as_all + rel * HC;
    const float* a_d = ad_all + rel * HC;
    float* als = g_als + (size_t)rel * NN * HEADS;
    float* ald = g_ald + (size_t)rel * NN * HEADS;
#pragma unroll
    for (int mt = 0; mt < 4; mt++) {
        float ps0 = 0.f, pd0 = 0.f, ps1 = 0.f, pd1 = 0.f;
#pragma unroll
        for (int nt = 0; nt < 4; nt++) {
            int col = cb + wn + nt * 8 + 2 * tig;
            float w0s = a_s[col], w1s = a_s[col + 1];
            float w0d = a_d[col], w1d = a_d[col + 1];
            ps0 += acc[mt][nt][0] * w0s + acc[mt][nt][1] * w1s;
            pd0 += acc[mt][nt][0] * w0d + acc[mt][nt][1] * w1d;
            ps1 += acc[mt][nt][2] * w0s + acc[mt][nt][3] * w1s;
            pd1 += acc[mt][nt][2] * w0d + acc[mt][nt][3] * w1d;
        }
        ps0 += __shfl_down_sync(0xffffffffu, ps0, 2);
        ps0 += __shfl_down_sync(0xffffffffu, ps0, 1);
        pd0 += __shfl_down_sync(0xffffffffu, pd0, 2);
        pd0 += __shfl_down_sync(0xffffffffu, pd0, 1);
        ps1 += __shfl_down_sync(0xffffffffu, ps1, 2);
        ps1 += __shfl_down_sync(0xffffffffu, ps1, 1);
        pd1 += __shfl_down_sync(0xffffffffu, pd1, 2);
        pd1 += __shfl_down_sync(0xffffffffu, pd1, 1);
        if (tig == 0) {
            int row = br + wm + mt * 16 + g;
            if (row < M) {
                atomicAdd(&als[row * 4 + head], ps0);
                atomicAdd(&ald[row * 4 + head], pd0);
            }
            if (row + 8 < M) {
                atomicAdd(&als[(row + 8) * 4 + head], ps1);
                atomicAdd(&ald[(row + 8) * 4 + head], pd1);
            }
        }
    }
}

// ---------------------------------------------------------------------------
// Zero attn-coefficient buffers (used before the layer-2 GEMM)
// ---------------------------------------------------------------------------
__global__ void zero_attn_kernel(int total) {
    int i = blockIdx.x * blockDim.x + threadIdx.x;
    if (i < total) { g_als[i] = 0.f; g_ald[i] = 0.f; }
}

// ---------------------------------------------------------------------------
// CSR-by-dst construction (rebuilt every call; stateless).
// csr_zero also zeroes als/ald for layer 1 (one launch saved).
// ---------------------------------------------------------------------------
__global__ void csr_zero_kernel() {
    int i = blockIdx.x * blockDim.x + threadIdx.x;
    if (i < NREL * NN) g_cnt[i] = 0;
    if (i < NREL * NN * HEADS) { g_als[i] = 0.f; g_ald[i] = 0.f; }
}

__global__ void csr_hist_kernel(const int* __restrict__ e0, const int* __restrict__ e1,
                                const int* __restrict__ e2, int E) {
    int idx = blockIdx.x * blockDim.x + threadIdx.x;
    if (idx >= NREL * E) return;
    int r = idx / E, e = idx - r * E;
    const int* ep = (r == 0) ? e0 : (r == 1) ? e1 : e2;
    atomicAdd(&g_cnt[r * NN + ep[E + e]], 1);
}

__global__ void csr_scan_kernel(int N) {
    int r = blockIdx.x;
    int t = threadIdx.x;
    __shared__ int sums[1024];
    int chunk = (N + blockDim.x - 1) / blockDim.x;
    int begin = t * chunk;
    int end = min(begin + chunk, N);
    int s = 0;
    for (int i = begin; i < end; i++) s += g_cnt[r * NN + i];
    sums[t] = s;
    __syncthreads();
    for (int d = 1; d < 1024; d <<= 1) {
        int v = (t >= d) ? sums[t - d] : 0;
        __syncthreads();
        sums[t] += v;
        __syncthreads();
    }
    int run = (t == 0) ? 0 : sums[t - 1];
    for (int i = begin; i < end; i++) {
        g_off[r * (NN + 1) + i] = run;
        g_cnt2[r * NN + i] = run;
        run += g_cnt[r * NN + i];
    }
    if (t == blockDim.x - 1) g_off[r * (NN + 1) + N] = run;
}

__global__ void csr_scatter_kernel(const int* __restrict__ e0, const int* __restrict__ e1,
                                   const int* __restrict__ e2, int E) {
    int idx = blockIdx.x * blockDim.x + threadIdx.x;
    if (idx >= NREL * E) return;
    int r = idx / E, e = idx - r * E;
    const int* ep = (r == 0) ? e0 : (r == 1) ? e1 : e2;
    int d = ep[E + e];
    int pos = atomicAdd(&g_cnt2[r * NN + d], 1);
    g_csr[(size_t)r * EE + pos] = ep[e];
}

// ---------------------------------------------------------------------------
// SINGLE-PASS fused softmax + aggregation, layer 1 (concat), ALL relations.
// One warp per dst; software-pipelined gathers (validated round 16).
// Shift-free softmax (logits O(1); alpha invariant to reference max-shift).
// ---------------------------------------------------------------------------
__global__ void agg1_all_kernel(const float* __restrict__ b, int N) {
    int w = (blockIdx.x * blockDim.x + threadIdx.x) >> 5;
    int lane = threadIdx.x & 31;
    if (w >= N) return;
    const int d = w;
    const int head = lane >> 3;

    float4 a0, a1;
    {
        int c = lane * 8;
        a0.x = b[c + 0] + b[HC + c + 0] + b[2 * HC + c + 0];
        a0.y = b[c + 1] + b[HC + c + 1] + b[2 * HC + c + 1];
        a0.z = b[c + 2] + b[HC + c + 2] + b[2 * HC + c + 2];
        a0.w = b[c + 3] + b[HC + c + 3] + b[2 * HC + c + 3];
        a1.x = b[c + 4] + b[HC + c + 4] + b[2 * HC + c + 4];
        a1.y = b[c + 5] + b[HC + c + 5] + b[2 * HC + c + 5];
        a1.z = b[c + 6] + b[HC + c + 6] + b[2 * HC + c + 6];
        a1.w = b[c + 7] + b[HC + c + 7] + b[2 * HC + c + 7];
    }

#pragma unroll
    for (int rel = 0; rel < NREL; rel++) {
        const int* off = g_off + rel * (NN + 1);
        const int* csr = g_csr + (size_t)rel * EE;
        const float* als = g_als + (size_t)rel * NN * HEADS;
        const int base = off[d];
        const int deg = off[d + 1] - base;
        const float adh = g_ald[((size_t)rel * NN + d) * 4 + head];

        float D = 0.f;
        float4 n0 = make_float4(0.f, 0.f, 0.f, 0.f);
        float4 n1 = make_float4(0.f, 0.f, 0.f, 0.f);

        float a_cur = 0.f;
        uint4 hv_cur = make_uint4(0u, 0u, 0u, 0u);
        if (deg > 0) {
            int s0 = csr[base];
            a_cur = als[(size_t)s0 * 4 + head];
            hv_cur = *((const uint4*)(g_h + (size_t)s0 * WIDE + rel * HC) + lane);
        }
        for (int i = 0; i < deg; i++) {
            float a_nxt = 0.f;
            uint4 hv_nxt = make_uint4(0u, 0u, 0u, 0u);
            if (i + 1 < deg) {
                int sn = csr[base + i + 1];
                a_nxt = als[(size_t)sn * 4 + head];
                hv_nxt = *((const uint4*)(g_h + (size_t)sn * WIDE + rel * HC) + lane);
            }
            float e = __expf(lrelu(a_cur + adh));
            D += e;
            float2 f0 = __half22float2(*(__half2*)&hv_cur.x);
            float2 f1 = __half22float2(*(__half2*)&hv_cur.y);
            float2 f2 = __half22float2(*(__half2*)&hv_cur.z);
            float2 f3 = __half22float2(*(__half2*)&hv_cur.w);
            n0.x += e * f0.x; n0.y += e * f0.y;
            n0.z += e * f1.x; n0.w += e * f1.y;
            n1.x += e * f2.x; n1.y += e * f2.y;
            n1.z += e * f3.x; n1.w += e * f3.y;
            a_cur = a_nxt;
            hv_cur = hv_nxt;
        }
        if (rel > 0) {   // self-loop for 'spatial' and 'similar'
            float e = __expf(lrelu(als[(size_t)d * 4 + head] + adh));
            D += e;
            uint4 hv = *((const uint4*)(g_h + (size_t)d * WIDE + rel * HC) + lane);
            float2 f0 = __half22float2(*(__half2*)&hv.x);
            float2 f1 = __half22float2(*(__half2*)&hv.y);
            float2 f2 = __half22float2(*(__half2*)&hv.z);
            float2 f3 = __half22float2(*(__half2*)&hv.w);
            n0.x += e * f0.x; n0.y += e * f0.y;
            n0.z += e * f1.x; n0.w += e * f1.y;
            n1.x += e * f2.x; n1.y += e * f2.y;
            n1.z += e * f3.x; n1.w += e * f3.y;
        }
        float inv = 1.f / (D + 1e-16f);
        a0.x += inv * n0.x; a0.y += inv * n0.y;
        a0.z += inv * n0.z; a0.w += inv * n0.w;
        a1.x += inv * n1.x; a1.y += inv * n1.y;
        a1.z += inv * n1.z; a1.w += inv * n1.w;
    }

    float* op = g_out1 + (size_t)d * HC + lane * 8;
    *(float4*)op = a0;
    *(float4*)(op + 4) = a1;
}

// ---------------------------------------------------------------------------
// SINGLE-PASS fused softmax + aggregation, layer 2 (mean), ALL relations.
// Software-pipelined like agg1 (validated round 16).
// ---------------------------------------------------------------------------
__global__ void agg2_all_kernel(const float* __restrict__ b, int N) {
    int w = (blockIdx.x * blockDim.x + threadIdx.x) >> 5;
    int lane = threadIdx.x & 31;
    if (w >= N) return;
    const int d = w;

    float2 acc;
    {
        int c = lane * 2;
        acc.x = b[c] + b[HID + c] + b[2 * HID + c];
        acc.y = b[c + 1] + b[HID + c + 1] + b[2 * HID + c + 1];
    }

#pragma unroll
    for (int rel = 0; rel < NREL; rel++) {
        const int* off = g_off + rel * (NN + 1);
        const int* csr = g_csr + (size_t)rel * EE;
        const float* als = g_als + (size_t)rel * NN * HEADS;
        const int base = off[d];
        const int deg = off[d + 1] - base;
        float4 ad4 = *(const float4*)(g_ald + ((size_t)rel * NN + d) * 4);

        float Dx = 0.f, Dy = 0.f, Dz = 0.f, Dw = 0.f;
        float2 m0 = make_float2(0.f, 0.f), m1 = make_float2(0.f, 0.f);
        float2 m2 = make_float2(0.f, 0.f), m3 = make_float2(0.f, 0.f);

        float4 as_cur = make_float4(0.f, 0.f, 0.f, 0.f);
        unsigned h0c = 0u, h1c = 0u, h2c = 0u, h3c = 0u;
        if (deg > 0) {
            int s0 = csr[base];
            as_cur = *(const float4*)(als + (size_t)s0 * 4);
            const __half* hrow = g_h + (size_t)s0 * WIDE + rel * HC;
            h0c = *(const unsigned*)(hrow + 0 * HID + lane * 2);
            h1c = *(const unsigned*)(hrow + 1 * HID + lane * 2);
            h2c = *(const unsigned*)(hrow + 2 * HID + lane * 2);
            h3c = *(const unsigned*)(hrow + 3 * HID + lane * 2);
        }
        for (int i = 0; i < deg; i++) {
            float4 as_nxt = make_float4(0.f, 0.f, 0.f, 0.f);
            unsigned h0n = 0u, h1n = 0u, h2n = 0u, h3n = 0u;
            if (i + 1 < deg) {
                int sn = csr[base + i + 1];
                as_nxt = *(const float4*)(als + (size_t)sn * 4);
                const __half* hrow = g_h + (size_t)sn * WIDE + rel * HC;
                h0n = *(const unsigned*)(hrow + 0 * HID + lane * 2);
                h1n = *(const unsigned*)(hrow + 1 * HID + lane * 2);
                h2n = *(const unsigned*)(hrow + 2 * HID + lane * 2);
                h3n = *(const unsigned*)(hrow + 3 * HID + lane * 2);
            }
            float e0 = __expf(lrelu(as_cur.x + ad4.x));
            float e1 = __expf(lrelu(as_cur.y + ad4.y));
            float e2 = __expf(lrelu(as_cur.z + ad4.z));
            float e3 = __expf(lrelu(as_cur.w + ad4.w));
            Dx += e0; Dy += e1; Dz += e2; Dw += e3;
            float2 f0 = __half22float2(*(__half2*)&h0c);
            float2 f1 = __half22float2(*(__half2*)&h1c);
            float2 f2 = __half22float2(*(__half2*)&h2c);
            float2 f3 = __half22float2(*(__half2*)&h3c);
            m0.x += e0 * f0.x; m0.y += e0 * f0.y;
            m1.x += e1 * f1.x; m1.y += e1 * f1.y;
            m2.x += e2 * f2.x; m2.y += e2 * f2.y;
            m3.x += e3 * f3.x; m3.y += e3 * f3.y;
            as_cur = as_nxt;
            h0c = h0n; h1c = h1n; h2c = h2n; h3c = h3n;
        }
        if (rel > 0) {
            float4 as4 = *(const float4*)(als + (size_t)d * 4);
            float e0 = __expf(lrelu(as4.x + ad4.x));
            float e1 = __expf(lrelu(as4.y + ad4.y));
            float e2 = __expf(lrelu(as4.z + ad4.z));
            float e3 = __expf(lrelu(as4.w + ad4.w));
            Dx += e0; Dy += e1; Dz += e2; Dw += e3;
            const __half* hrow = g_h + (size_t)d * WIDE + rel * HC;
            float2 f0 = __half22float2(*(const __half2*)(hrow + 0 * HID + lane * 2));
            float2 f1 = __half22float2(*(const __half2*)(hrow + 1 * HID + lane * 2));
            float2 f2 = __half22float2(*(const __half2*)(hrow + 2 * HID + lane * 2));
            float2 f3 = __half22float2(*(const __half2*)(hrow + 3 * HID + lane * 2));
            m0.x += e0 * f0.x; m0.y += e0 * f0.y;
            m1.x += e1 * f1.x; m1.y += e1 * f1.y;
            m2.x += e2 * f2.x; m2.y += e2 * f2.y;
            m3.x += e3 * f3.x; m3.y += e3 * f3.y;
        }
        float i0 = 0.25f / (Dx + 1e-16f), i1 = 0.25f / (Dy + 1e-16f);
        float i2 = 0.25f / (Dz + 1e-16f), i3 = 0.25f / (Dw + 1e-16f);
        acc.x += i0 * m0.x + i1 * m1.x + i2 * m2.x + i3 * m3.x;
        acc.y += i0 * m0.y + i1 * m1.y + i2 * m2.y + i3 * m3.y;
    }

    *(float2*)(g_out2 + (size_t)d * HID + lane * 2) = acc;
}

// ---------------------------------------------------------------------------
// SIMT SGEMM (final linear layer): out = relu(g_out2) @ Wl + bl
// ---------------------------------------------------------------------------
template<int BM, int BN, int BK, int TM, int TN>
__global__ void __launch_bounds__((BM / TM) * (BN / TN))
final_gemm_kernel(const float* __restrict__ B, float* __restrict__ C,
                  const float* __restrict__ bias, int M, int N, int K) {
    constexpr int NT = (BM / TM) * (BN / TN);
    __shared__ float As[BK][BM + 4];
    __shared__ float Bs[BK][BN];
    const float* A = (const float*)g_out2;
    const int tid = threadIdx.x;
    const int block_row = blockIdx.y * BM;
    const int block_col = blockIdx.x * BN;
    const int tcol = tid % (BN / TN);
    const int trow = tid / (BN / TN);

    float acc[TM][TN];
#pragma unroll
    for (int i = 0; i < TM; i++)
#pragma unroll
        for (int j = 0; j < TN; j++) acc[i][j] = 0.f;

    for (int k0 = 0; k0 < K; k0 += BK) {
#pragma unroll
        for (int i = tid; i < BM * BK / 4; i += NT) {
            int r = i / (BK / 4), c4 = i % (BK / 4);
            int gr = block_row + r;
            float4 v = make_float4(0.f, 0.f, 0.f, 0.f);
            if (gr < M) v = *(const float4*)(A + (size_t)gr * K + k0 + c4 * 4);
            v.x = fmaxf(v.x, 0.f); v.y = fmaxf(v.y, 0.f);
            v.z = fmaxf(v.z, 0.f); v.w = fmaxf(v.w, 0.f);
            As[c4 * 4 + 0][r] = v.x; As[c4 * 4 + 1][r] = v.y;
            As[c4 * 4 + 2][r] = v.z; As[c4 * 4 + 3][r] = v.w;
        }
#pragma unroll
        for (int i = tid; i < BK * BN / 4; i += NT) {
            int r = i / (BN / 4), c4 = i % (BN / 4);
            *(float4*)&Bs[r][c4 * 4] =
                *(const float4*)(B + (size_t)(k0 + r) * N + block_col + c4 * 4);
        }
        __syncthreads();
#pragma unroll
        for (int kk = 0; kk < BK; kk++) {
            float ar[TM], br[TN];
#pragma unroll
            for (int i = 0; i < TM; i++) ar[i] = As[kk][trow * TM + i];
#pragma unroll
            for (int j = 0; j < TN; j++) br[j] = Bs[kk][tcol * TN + j];
#pragma unroll
            for (int i = 0; i < TM; i++)
#pragma unroll
                for (int j = 0; j < TN; j++) acc[i][j] += ar[i] * br[j];
        }
        __syncthreads();
    }
#pragma unroll
    for (int i = 0; i < TM; i++) {
        int gr = block_row + trow * TM + i;
        if (gr >= M) continue;
#pragma unroll
        for (int j = 0; j < TN; j += 4) {
            int gc = block_col + tcol * TN + j;
            float4 v = make_float4(acc[i][j] + bias[gc], acc[i][j + 1] + bias[gc + 1],
                                   acc[i][j + 2] + bias[gc + 2], acc[i][j + 3] + bias[gc + 3]);
            *(float4*)(C + (size_t)gr * N + gc) = v;
        }
    }
}

// ---------------------------------------------------------------------------
// Launcher: kernel launches ONLY (graph-capture safe)
// ---------------------------------------------------------------------------
extern "C" void kernel_launch(void* const* d_in, const int* in_sizes, int n_in,
                              void* d_out, int out_size) {
    const float* x   = (const float*)d_in[0];
    const int*   e0  = (const int*)d_in[1];
    const int*   e1  = (const int*)d_in[2];
    const int*   e2  = (const int*)d_in[3];
    const float* W1  = (const float*)d_in[4];
    const float* a1s = (const float*)d_in[5];
    const float* a1d = (const float*)d_in[6];
    const float* b1  = (const float*)d_in[7];
    const float* W2  = (const float*)d_in[8];
    const float* a2s = (const float*)d_in[9];
    const float* a2d = (const float*)d_in[10];
    const float* b2  = (const float*)d_in[11];
    const float* Wl  = (const float*)d_in[12];
    const float* bl  = (const float*)d_in[13];
    float* out = (float*)d_out;

    const int N = in_sizes[0] / IN_CH;
    const int E = in_sizes[1] / 2;

    // ---------------- CSR-by-dst build (also zeroes layer-1 als/ald) -------
    csr_zero_kernel<<<(NREL * NN * HEADS + 255) / 256, 256>>>();
    csr_hist_kernel<<<(NREL * E + 255) / 256, 256>>>(e0, e1, e2, E);
    csr_scan_kernel<<<NREL, 1024>>>(N);
    csr_scatter_kernel<<<(NREL * E + 255) / 256, 256>>>(e0, e1, e2, E);

    const dim3 ggrid(WIDE / 128, (N + 127) / 128);   // 6 x 391
    const int agg_blocks = (N * 32 + 255) / 256;
    const int zero_blocks = (NREL * N * HEADS + 255) / 256;

    // ---------------- Layer 1 (concat) ----------------
    mma_gemm_wide_kernel<false, true, IN_CH><<<ggrid, 256>>>(x, W1, a1s, a1d, N);
    agg1_all_kernel<<<agg_blocks, 256>>>(b1, N);

    // ---------------- Layer 2 (mean over heads) ----------------
    zero_attn_kernel<<<zero_blocks, 256>>>(NREL * N * HEADS);
    mma_gemm_wide_kernel<true, false, HC><<<ggrid, 256>>>(nullptr, W2, a2s, a2d, N);
    agg2_all_kernel<<<agg_blocks, 256>>>(b2, N);

    // ---------------- Final linear ----------------
    {
        dim3 grid(1, (N + 127) / 128);
        final_gemm_kernel<128, 64, 16, 4, 8><<<grid, 256>>>(
            Wl, out, bl, N, OUT_CH, OUT_CH);
    }
}